// round 5
// baseline (speedup 1.0000x reference)
#include <cuda_runtime.h>
#include <cuda_bf16.h>
#include <cstdint>
#include <math.h>

// Problem constants
#define DIM 1024
#define NH  16
#define HD  64
#define B_  2
#define T_  2048
#define M_TOT (B_ * T_)          // 4096

// ---------------------------------------------------------------------------
// Device scratch (no allocation allowed)
// ---------------------------------------------------------------------------
__device__ __nv_bfloat16 g_ahi[M_TOT * DIM];   // x-split, later ctx-split
__device__ __nv_bfloat16 g_alo[M_TOT * DIM];
__device__ __nv_bfloat16 g_whi[4 * DIM * DIM]; // Wq,Wk,Wv,Wo hi
__device__ __nv_bfloat16 g_wlo[4 * DIM * DIM];
__device__ __nv_bfloat16 g_qhi[M_TOT * DIM];   // [B,H,T,Hd], pre-scaled 1/8
__device__ __nv_bfloat16 g_qlo[M_TOT * DIM];
__device__ __nv_bfloat16 g_khi[M_TOT * DIM];
__device__ __nv_bfloat16 g_klo[M_TOT * DIM];
__device__ __nv_bfloat16 g_vhi[M_TOT * DIM];
__device__ __nv_bfloat16 g_vlo[M_TOT * DIM];

// ===========================================================================
// Helpers (plain sm_103-compatible: ldmatrix, mma.sync, cp.async)
// ===========================================================================
__device__ __forceinline__ uint32_t smem_to_u32(const void* p) {
    uint32_t a;
    asm("{ .reg .u64 t; cvta.to.shared.u64 t, %1; cvt.u32.u64 %0, t; }"
        : "=r"(a) : "l"(p));
    return a;
}

#define LDSM_X4(r, addr) \
    asm volatile("ldmatrix.sync.aligned.m8n8.x4.shared.b16 {%0,%1,%2,%3}, [%4];" \
        : "=r"((r)[0]), "=r"((r)[1]), "=r"((r)[2]), "=r"((r)[3]) : "r"(addr))

#define LDSM_X4_T(r, addr) \
    asm volatile("ldmatrix.sync.aligned.m8n8.x4.trans.shared.b16 {%0,%1,%2,%3}, [%4];" \
        : "=r"((r)[0]), "=r"((r)[1]), "=r"((r)[2]), "=r"((r)[3]) : "r"(addr))

#define MMA_BF16(d, a, b) \
    asm volatile("mma.sync.aligned.m16n8k16.row.col.f32.bf16.bf16.f32 " \
        "{%0,%1,%2,%3}, {%4,%5,%6,%7}, {%8,%9}, {%0,%1,%2,%3};" \
        : "+f"((d)[0]), "+f"((d)[1]), "+f"((d)[2]), "+f"((d)[3]) \
        : "r"((a)[0]), "r"((a)[1]), "r"((a)[2]), "r"((a)[3]), \
          "r"((b)[0]), "r"((b)[1]))

#define CP_A16(dst, src) \
    asm volatile("cp.async.cg.shared.global [%0], [%1], 16;" \
        :: "r"(dst), "l"(src) : "memory")
#define CP_COMMIT() asm volatile("cp.async.commit_group;" ::: "memory")
#define CP_WAIT(N)  asm volatile("cp.async.wait_group %0;" :: "n"(N) : "memory")

__device__ __forceinline__ void split4(float4 v, uint2& hi, uint2& lo) {
    __nv_bfloat162 h01 = __floats2bfloat162_rn(v.x, v.y);
    __nv_bfloat162 h23 = __floats2bfloat162_rn(v.z, v.w);
    __nv_bfloat162 l01 = __floats2bfloat162_rn(v.x - __bfloat162float(h01.x),
                                               v.y - __bfloat162float(h01.y));
    __nv_bfloat162 l23 = __floats2bfloat162_rn(v.z - __bfloat162float(h23.x),
                                               v.w - __bfloat162float(h23.y));
    hi = make_uint2(*reinterpret_cast<uint32_t*>(&h01),
                    *reinterpret_cast<uint32_t*>(&h23));
    lo = make_uint2(*reinterpret_cast<uint32_t*>(&l01),
                    *reinterpret_cast<uint32_t*>(&l23));
}

__device__ __forceinline__ void store_pair(
    __nv_bfloat16* hi, __nv_bfloat16* lo, size_t o, float v0, float v1)
{
    __nv_bfloat162 h = __floats2bfloat162_rn(v0, v1);
    __nv_bfloat162 l = __floats2bfloat162_rn(v0 - __bfloat162float(h.x),
                                             v1 - __bfloat162float(h.y));
    *reinterpret_cast<__nv_bfloat162*>(hi + o) = h;
    *reinterpret_cast<__nv_bfloat162*>(lo + o) = l;
}

// ===========================================================================
// Pre-split: fp32 array -> bf16 hi/lo
// ===========================================================================
__global__ void __launch_bounds__(256) split_kernel(
    const float* __restrict__ in, __nv_bfloat16* __restrict__ hi,
    __nv_bfloat16* __restrict__ lo, int n4)
{
    const int i = blockIdx.x * 256 + threadIdx.x;
    if (i < n4) {
        float4 v = reinterpret_cast<const float4*>(in)[i];
        uint2 h, l;
        split4(v, h, l);
        reinterpret_cast<uint2*>(hi)[i] = h;
        reinterpret_cast<uint2*>(lo)[i] = l;
    }
}

// ===========================================================================
// Split-bf16 GEMM, cp.async pipelined.
// C = A @ W^T + bias, A/W given as bf16 hi/lo pairs.
// mode 0: fp32 [M,1024]; mode 1: fp32 scatter [B,H,T,Hd] + bf16 hi/lo scatter;
// mode 2: bf16 hi/lo scatter only, scaled by 0.125 (Q).
// ===========================================================================
#define BK 64
#define ROW_B 144
#define TILE_BYTES (128 * ROW_B)         // 18432
#define STAGE_BYTES (4 * TILE_BYTES)     // 73728
#define GEMM_SMEM (2 * STAGE_BYTES)      // 147456
#define N_CHUNKS 16

__global__ void __launch_bounds__(256, 1) gemm_tc_kernel(
    const __nv_bfloat16* __restrict__ Ahi, const __nv_bfloat16* __restrict__ Alo,
    const __nv_bfloat16* __restrict__ Whi, const __nv_bfloat16* __restrict__ Wlo,
    const float* __restrict__ bias, float* __restrict__ Cf,
    __nv_bfloat16* __restrict__ Chi, __nv_bfloat16* __restrict__ Clo, int mode)
{
    extern __shared__ char smem[];
    const uint32_t sb = smem_to_u32(smem);
    const int tid    = threadIdx.x;
    const int lane   = tid & 31;
    const int wid    = tid >> 5;
    const int warp_m = wid & 1;
    const int warp_n = wid >> 1;
    const int m0 = blockIdx.y * 128;
    const int n0 = blockIdx.x * 128;

    float acc[4][4][4];
    #pragma unroll
    for (int mi = 0; mi < 4; mi++)
        #pragma unroll
        for (int ni = 0; ni < 4; ni++)
            #pragma unroll
            for (int j = 0; j < 4; j++) acc[mi][ni][j] = 0.0f;

    const int r    = lane & 7;
    const int quad = lane >> 3;
    const uint32_t a_lane_off =
        (uint32_t)(warp_m * 64 + (quad & 1) * 8 + r) * ROW_B + (quad >> 1) * 16;
    const uint32_t b_lane_off =
        (uint32_t)(warp_n * 32 + (quad >> 1) * 8 + r) * ROW_B + (quad & 1) * 16;

    auto ISSUE = [&](int c, int p) {
        const int k0 = c * BK;
        const uint32_t stage = sb + p * STAGE_BYTES;
        #pragma unroll
        for (int i = 0; i < 4; i++) {
            const int f   = i * 256 + tid;
            const int row = f >> 3;        // 8 x 16B chunks per 64-col row
            const int cc  = f & 7;
            const uint32_t off = (uint32_t)row * ROW_B + cc * 16;
            const size_t ga = (size_t)(m0 + row) * DIM + k0 + cc * 8;
            const size_t gw = (size_t)(n0 + row) * DIM + k0 + cc * 8;
            CP_A16(stage + off,                  Ahi + ga);
            CP_A16(stage + TILE_BYTES + off,     Alo + ga);
            CP_A16(stage + 2 * TILE_BYTES + off, Whi + gw);
            CP_A16(stage + 3 * TILE_BYTES + off, Wlo + gw);
        }
        CP_COMMIT();
    };

    ISSUE(0, 0);
    ISSUE(1, 1);

    for (int c = 0; c < N_CHUNKS; ++c) {
        const int p = c & 1;
        if (c < N_CHUNKS - 1) { CP_WAIT(1); } else { CP_WAIT(0); }
        __syncthreads();

        const uint32_t stage = sb + p * STAGE_BYTES;
        #pragma unroll
        for (int ks = 0; ks < 4; ++ks) {
            uint32_t ah[4][4], al[4][4];
            #pragma unroll
            for (int mi = 0; mi < 4; mi++) {
                const uint32_t addr =
                    stage + a_lane_off + mi * (16 * ROW_B) + ks * 32;
                LDSM_X4(ah[mi], addr);
                LDSM_X4(al[mi], addr + TILE_BYTES);
            }
            uint32_t bh[4][2], bl[4][2];
            #pragma unroll
            for (int pr = 0; pr < 2; pr++) {
                const uint32_t addr =
                    stage + 2 * TILE_BYTES + b_lane_off + pr * (16 * ROW_B) + ks * 32;
                LDSM_X4(&bh[2 * pr][0], addr);
                LDSM_X4(&bl[2 * pr][0], addr + TILE_BYTES);
            }
            #pragma unroll
            for (int mi = 0; mi < 4; mi++)
                #pragma unroll
                for (int ni = 0; ni < 4; ni++) {
                    MMA_BF16(acc[mi][ni], ah[mi], bh[ni]);
                    MMA_BF16(acc[mi][ni], al[mi], bh[ni]);
                    MMA_BF16(acc[mi][ni], ah[mi], bl[ni]);
                }
        }
        __syncthreads();
        if (c + 2 < N_CHUNKS) ISSUE(c + 2, p);
    }

    // ---- epilogue ----
    const int gid  = lane >> 2;
    const int tid4 = lane & 3;
    #pragma unroll
    for (int mi = 0; mi < 4; mi++) {
        #pragma unroll
        for (int ni = 0; ni < 4; ni++) {
            const int n = n0 + warp_n * 32 + ni * 8 + tid4 * 2;
            const float2 bb = *reinterpret_cast<const float2*>(&bias[n]);
            #pragma unroll
            for (int hrow = 0; hrow < 2; hrow++) {
                const int m = m0 + warp_m * 64 + mi * 16 + gid + hrow * 8;
                float v0 = acc[mi][ni][hrow * 2 + 0] + bb.x;
                float v1 = acc[mi][ni][hrow * 2 + 1] + bb.y;
                if (mode == 0) {
                    float2 o; o.x = v0; o.y = v1;
                    *reinterpret_cast<float2*>(&Cf[(size_t)m * DIM + n]) = o;
                } else {
                    const int b  = m >> 11;
                    const int t  = m & (T_ - 1);
                    const int h  = n >> 6;
                    const int hd = n & (HD - 1);
                    const size_t o = ((((size_t)b * NH + h) * T_) + t) * HD + hd;
                    if (mode == 1) {
                        float2 of; of.x = v0; of.y = v1;
                        *reinterpret_cast<float2*>(&Cf[o]) = of;
                    } else {             // mode 2: Q, pre-scale by 1/8
                        v0 *= 0.125f; v1 *= 0.125f;
                    }
                    store_pair(Chi, Clo, o, v0, v1);
                }
            }
        }
    }
}

// ===========================================================================
// Tensor-core causal flash attention, bf16 hi/lo inputs, cp.async pipelined.
// 256 threads / 8 warps; q-tile 128 (16 rows/warp); kv-tile 64, double-buffered.
// Writes ctx as bf16 hi/lo into [B,T,DIM] (feeds output GEMM).
// ===========================================================================
#define AROWB 144
#define KV_TILE (64 * AROWB)             // 9216
#define KV_STG  (4 * KV_TILE)            // 36864: KHI,KLO,VHI,VLO
#define OFF_P   (2 * KV_STG)             // 73728
#define P_TILE  (128 * AROWB)            // 18432
#define ATTN_SMEM (OFF_P + 2 * P_TILE)   // 110592

__global__ void __launch_bounds__(256, 1) attn_tc_kernel(
    const __nv_bfloat16* __restrict__ qhi, const __nv_bfloat16* __restrict__ qlo,
    const __nv_bfloat16* __restrict__ khi, const __nv_bfloat16* __restrict__ klo,
    const __nv_bfloat16* __restrict__ vhi, const __nv_bfloat16* __restrict__ vlo,
    __nv_bfloat16* __restrict__ ahi, __nv_bfloat16* __restrict__ alo)
{
    extern __shared__ char smem[];
    const uint32_t sb = smem_to_u32(smem);
    const int tid  = threadIdx.x;
    const int lane = tid & 31;
    const int w    = tid >> 5;
    const int qt = gridDim.x - 1 - blockIdx.x;    // heavy tiles first
    const int h  = blockIdx.y;
    const int b  = blockIdx.z;
    const int q0 = qt * 128;
    const int nkv = 2 * (qt + 1);

    const size_t head = ((size_t)b * NH + h) * T_ * HD;

    const int r    = lane & 7;
    const int quad = lane >> 3;
    const int gid  = lane >> 2;
    const int tid4 = lane & 3;
    const uint32_t a_off =
        (uint32_t)((quad & 1) * 8 + r) * AROWB + (quad >> 1) * 16;
    const uint32_t b_off =
        (uint32_t)((quad >> 1) * 8 + r) * AROWB + (quad & 1) * 16;

    // ---- prologue: Q (group 0), KV0 (group 1), KV1 (group 2) ----
    {   // Q tile: 128 rows x 64 bf16 (hi+lo) into P region
        #pragma unroll
        for (int i = 0; i < 4; i++) {
            const int f   = i * 256 + tid;
            const int row = f >> 3;
            const int cc  = f & 7;
            const size_t g = head + (size_t)(q0 + row) * HD + cc * 8;
            const uint32_t d = sb + OFF_P + (uint32_t)row * AROWB + cc * 16;
            CP_A16(d,          qhi + g);
            CP_A16(d + P_TILE, qlo + g);
        }
        CP_COMMIT();
    }
    auto ISSUE_KV = [&](int it, int p) {
        const int j0 = it * 64;
        const uint32_t stage = sb + p * KV_STG;
        #pragma unroll
        for (int i = 0; i < 2; i++) {
            const int f   = i * 256 + tid;
            const int row = f >> 3;
            const int cc  = f & 7;
            const size_t g = head + (size_t)(j0 + row) * HD + cc * 8;
            const uint32_t d = stage + (uint32_t)row * AROWB + cc * 16;
            CP_A16(d,               khi + g);
            CP_A16(d + KV_TILE,     klo + g);
            CP_A16(d + 2 * KV_TILE, vhi + g);
            CP_A16(d + 3 * KV_TILE, vlo + g);
        }
        CP_COMMIT();
    };
    ISSUE_KV(0, 0);
    if (nkv > 1) ISSUE_KV(1, 1);

    uint32_t qh[4][4], ql[4][4];
    float c_acc[8][4];
    #pragma unroll
    for (int nt = 0; nt < 8; nt++)
        #pragma unroll
        for (int j = 0; j < 4; j++) c_acc[nt][j] = 0.0f;
    float m0r = -INFINITY, m1r = -INFINITY;
    float l0r = 0.0f, l1r = 0.0f;

    const int row0 = w * 16 + gid;   // local q rows of this thread
    const int row1 = row0 + 8;

    for (int it = 0; it < nkv; ++it) {
        const int p  = it & 1;
        const int j0 = it * 64;
        if (it < nkv - 1) { CP_WAIT(1); } else { CP_WAIT(0); }
        __syncthreads();

        if (it == 0) {
            // Q fragments (warp-private rows; P region safe until S-write below)
            #pragma unroll
            for (int ks = 0; ks < 4; ks++) {
                const uint32_t addr =
                    sb + OFF_P + (uint32_t)(w * 16) * AROWB + a_off + ks * 32;
                LDSM_X4(qh[ks], addr);
                LDSM_X4(ql[ks], addr + P_TILE);
            }
        }

        const uint32_t kst = sb + p * KV_STG;

        // ---- S = Q @ K^T (3-term) ----
        float s[8][4];
        #pragma unroll
        for (int nt = 0; nt < 8; nt++)
            #pragma unroll
            for (int j = 0; j < 4; j++) s[nt][j] = 0.0f;

        #pragma unroll
        for (int ks = 0; ks < 4; ++ks) {
            uint32_t kb[4][4];
            #pragma unroll
            for (int p2 = 0; p2 < 4; p2++)
                LDSM_X4(kb[p2], kst + (uint32_t)(p2 * 16) * AROWB + b_off + ks * 32);
            #pragma unroll
            for (int p2 = 0; p2 < 4; p2++) {
                MMA_BF16(s[2 * p2 + 0], qh[ks], &kb[p2][0]);
                MMA_BF16(s[2 * p2 + 1], qh[ks], &kb[p2][2]);
                MMA_BF16(s[2 * p2 + 0], ql[ks], &kb[p2][0]);
                MMA_BF16(s[2 * p2 + 1], ql[ks], &kb[p2][2]);
            }
            #pragma unroll
            for (int p2 = 0; p2 < 4; p2++)
                LDSM_X4(kb[p2], kst + KV_TILE + (uint32_t)(p2 * 16) * AROWB
                                + b_off + ks * 32);
            #pragma unroll
            for (int p2 = 0; p2 < 4; p2++) {
                MMA_BF16(s[2 * p2 + 0], qh[ks], &kb[p2][0]);
                MMA_BF16(s[2 * p2 + 1], qh[ks], &kb[p2][2]);
            }
        }

        // ---- causal mask ----
        if (j0 + 63 > q0 + w * 16) {
            const int qg0 = q0 + row0;
            const int qg1 = qg0 + 8;
            #pragma unroll
            for (int nt = 0; nt < 8; nt++) {
                const int cg = j0 + nt * 8 + tid4 * 2;
                if (cg     > qg0) s[nt][0] = -INFINITY;
                if (cg + 1 > qg0) s[nt][1] = -INFINITY;
                if (cg     > qg1) s[nt][2] = -INFINITY;
                if (cg + 1 > qg1) s[nt][3] = -INFINITY;
            }
        }

        // ---- online softmax ----
        float mt0 = -INFINITY, mt1 = -INFINITY;
        #pragma unroll
        for (int nt = 0; nt < 8; nt++) {
            mt0 = fmaxf(mt0, fmaxf(s[nt][0], s[nt][1]));
            mt1 = fmaxf(mt1, fmaxf(s[nt][2], s[nt][3]));
        }
        mt0 = fmaxf(mt0, __shfl_xor_sync(0xffffffffu, mt0, 1));
        mt0 = fmaxf(mt0, __shfl_xor_sync(0xffffffffu, mt0, 2));
        mt1 = fmaxf(mt1, __shfl_xor_sync(0xffffffffu, mt1, 1));
        mt1 = fmaxf(mt1, __shfl_xor_sync(0xffffffffu, mt1, 2));

        const float mn0 = fmaxf(m0r, mt0);
        const float mn1 = fmaxf(m1r, mt1);
        const float sc0 = __expf(m0r - mn0);
        const float sc1 = __expf(m1r - mn1);
        m0r = mn0; m1r = mn1;

        float ls0 = 0.0f, ls1 = 0.0f;
        #pragma unroll
        for (int nt = 0; nt < 8; nt++) {
            s[nt][0] = __expf(s[nt][0] - mn0);
            s[nt][1] = __expf(s[nt][1] - mn0);
            s[nt][2] = __expf(s[nt][2] - mn1);
            s[nt][3] = __expf(s[nt][3] - mn1);
            ls0 += s[nt][0] + s[nt][1];
            ls1 += s[nt][2] + s[nt][3];
        }
        ls0 += __shfl_xor_sync(0xffffffffu, ls0, 1);
        ls0 += __shfl_xor_sync(0xffffffffu, ls0, 2);
        ls1 += __shfl_xor_sync(0xffffffffu, ls1, 1);
        ls1 += __shfl_xor_sync(0xffffffffu, ls1, 2);
        l0r = l0r * sc0 + ls0;
        l1r = l1r * sc1 + ls1;

        #pragma unroll
        for (int nt = 0; nt < 8; nt++) {
            c_acc[nt][0] *= sc0; c_acc[nt][1] *= sc0;
            c_acc[nt][2] *= sc1; c_acc[nt][3] *= sc1;
        }

        // ---- write P (split bf16) to per-warp P region ----
        #pragma unroll
        for (int nt = 0; nt < 8; nt++) {
            __nv_bfloat162 h01 = __floats2bfloat162_rn(s[nt][0], s[nt][1]);
            __nv_bfloat162 l01 = __floats2bfloat162_rn(
                s[nt][0] - __bfloat162float(h01.x),
                s[nt][1] - __bfloat162float(h01.y));
            __nv_bfloat162 h23 = __floats2bfloat162_rn(s[nt][2], s[nt][3]);
            __nv_bfloat162 l23 = __floats2bfloat162_rn(
                s[nt][2] - __bfloat162float(h23.x),
                s[nt][3] - __bfloat162float(h23.y));
            const uint32_t c0 = (uint32_t)(nt * 16 + tid4 * 4);
            const uint32_t o0 = sb + OFF_P + (uint32_t)row0 * AROWB + c0;
            const uint32_t o1 = sb + OFF_P + (uint32_t)row1 * AROWB + c0;
            *reinterpret_cast<uint32_t*>((char*)0 + o0) = 0; // placeholder removed
        }
        // (actual P stores below — compiler-friendly direct smem pointers)
        #pragma unroll
        for (int nt = 0; nt < 8; nt++) {
            __nv_bfloat162 h01 = __floats2bfloat162_rn(s[nt][0], s[nt][1]);
            __nv_bfloat162 l01 = __floats2bfloat162_rn(
                s[nt][0] - __bfloat162float(h01.x),
                s[nt][1] - __bfloat162float(h01.y));
            __nv_bfloat162 h23 = __floats2bfloat162_rn(s[nt][2], s[nt][3]);
            __nv_bfloat162 l23 = __floats2bfloat162_rn(
                s[nt][2] - __bfloat162float(h23.x),
                s[nt][3] - __bfloat162float(h23.y));
            const uint32_t c0 = (uint32_t)(nt * 16 + tid4 * 4);
            char* p0 = smem + OFF_P + (uint32_t)row0 * AROWB + c0;
            char* p1 = smem + OFF_P + (uint32_t)row1 * AROWB + c0;
            *reinterpret_cast<uint32_t*>(p0)          = *reinterpret_cast<uint32_t*>(&h01);
            *reinterpret_cast<uint32_t*>(p0 + P_TILE) = *reinterpret_cast<uint32_t*>(&l01);
            *reinterpret_cast<uint32_t*>(p1)          = *reinterpret_cast<uint32_t*>(&h23);
            *reinterpret_cast<uint32_t*>(p1 + P_TILE) = *reinterpret_cast<uint32_t*>(&l23);
        }
        __syncwarp();

        // ---- ctx += P @ V (3-term) ----
        #pragma unroll
        for (int kk = 0; kk < 4; ++kk) {
            uint32_t ph[4], pl[4];
            const uint32_t paddr =
                sb + OFF_P + (uint32_t)(w * 16) * AROWB + a_off + kk * 32;
            LDSM_X4(ph, paddr);
            LDSM_X4(pl, paddr + P_TILE);

            uint32_t vb[4][4];
            #pragma unroll
            for (int nt2 = 0; nt2 < 4; nt2++)
                LDSM_X4_T(vb[nt2], kst + 2 * KV_TILE
                          + (uint32_t)(kk * 16) * AROWB + a_off + nt2 * 32);
            #pragma unroll
            for (int nt2 = 0; nt2 < 4; nt2++) {
                MMA_BF16(c_acc[2 * nt2 + 0], ph, &vb[nt2][0]);
                MMA_BF16(c_acc[2 * nt2 + 1], ph, &vb[nt2][2]);
                MMA_BF16(c_acc[2 * nt2 + 0], pl, &vb[nt2][0]);
                MMA_BF16(c_acc[2 * nt2 + 1], pl, &vb[nt2][2]);
            }
            #pragma unroll
            for (int nt2 = 0; nt2 < 4; nt2++)
                LDSM_X4_T(vb[nt2], kst + 3 * KV_TILE
                          + (uint32_t)(kk * 16) * AROWB + a_off + nt2 * 32);
            #pragma unroll
            for (int nt2 = 0; nt2 < 4; nt2++) {
                MMA_BF16(c_acc[2 * nt2 + 0], ph, &vb[nt2][0]);
                MMA_BF16(c_acc[2 * nt2 + 1], ph, &vb[nt2][2]);
            }
        }
        __syncthreads();
        if (it + 2 < nkv) ISSUE_KV(it + 2, p);
    }

    // ---- epilogue: ctx/l -> bf16 hi/lo into [B,T,DIM] ----
    const float inv0 = 1.0f / l0r;
    const float inv1 = 1.0f / l1r;
    const int qr0 = q0 + row0;
    const int qr1 = q0 + row1;
    #pragma unroll
    for (int nt = 0; nt < 8; nt++) {
        const int hd = nt * 8 + tid4 * 2;
        const size_t o0 = ((size_t)b * T_ + qr0) * DIM + h * HD + hd;
        const size_t o1 = ((size_t)b * T_ + qr1) * DIM + h * HD + hd;
        store_pair(ahi, alo, o0, c_acc[nt][0] * inv0, c_acc[nt][1] * inv0);
        store_pair(ahi, alo, o1, c_acc[nt][2] * inv1, c_acc[nt][3] * inv1);
    }
}

// ---------------------------------------------------------------------------
// kernel_launch
// ---------------------------------------------------------------------------
extern "C" void kernel_launch(void* const* d_in, const int* in_sizes, int n_in,
                              void* d_out, int out_size)
{
    const float* x  = (const float*)d_in[0];
    const float* Wq = (const float*)d_in[1];
    const float* bq = (const float*)d_in[2];
    const float* Wk = (const float*)d_in[3];
    const float* bk = (const float*)d_in[4];
    const float* Wv = (const float*)d_in[5];
    const float* bv = (const float*)d_in[6];
    const float* Wo = (const float*)d_in[7];
    const float* bo = (const float*)d_in[8];

    float* out   = (float*)d_out;
    float* k_out = out + (size_t)M_TOT * DIM;
    float* v_out = out + (size_t)2 * M_TOT * DIM;

    __nv_bfloat16 *ahi, *alo, *whi, *wlo, *qhi, *qlo, *khi, *klo, *vhi, *vlo;
    cudaGetSymbolAddress((void**)&ahi, g_ahi);
    cudaGetSymbolAddress((void**)&alo, g_alo);
    cudaGetSymbolAddress((void**)&whi, g_whi);
    cudaGetSymbolAddress((void**)&wlo, g_wlo);
    cudaGetSymbolAddress((void**)&qhi, g_qhi);
    cudaGetSymbolAddress((void**)&qlo, g_qlo);
    cudaGetSymbolAddress((void**)&khi, g_khi);
    cudaGetSymbolAddress((void**)&klo, g_klo);
    cudaGetSymbolAddress((void**)&vhi, g_vhi);
    cudaGetSymbolAddress((void**)&vlo, g_vlo);

    cudaFuncSetAttribute(gemm_tc_kernel,
                         cudaFuncAttributeMaxDynamicSharedMemorySize, GEMM_SMEM);
    cudaFuncSetAttribute(attn_tc_kernel,
                         cudaFuncAttributeMaxDynamicSharedMemorySize, ATTN_SMEM);

    const size_t DD = (size_t)DIM * DIM;

    // Pre-split x and weights
    split_kernel<<<(M_TOT * DIM / 4 + 255) / 256, 256>>>(x, ahi, alo, M_TOT * DIM / 4);
    split_kernel<<<(DD / 4 + 255) / 256, 256>>>(Wq, whi,          wlo,          DD / 4);
    split_kernel<<<(DD / 4 + 255) / 256, 256>>>(Wk, whi + DD,     wlo + DD,     DD / 4);
    split_kernel<<<(DD / 4 + 255) / 256, 256>>>(Wv, whi + 2 * DD, wlo + 2 * DD, DD / 4);
    split_kernel<<<(DD / 4 + 255) / 256, 256>>>(Wo, whi + 3 * DD, wlo + 3 * DD, DD / 4);

    dim3 ggrid(DIM / 128, M_TOT / 128);   // (8, 32)

    // Projections
    gemm_tc_kernel<<<ggrid, 256, GEMM_SMEM>>>(ahi, alo, whi,          wlo,          bq,
                                              nullptr, qhi, qlo, 2);
    gemm_tc_kernel<<<ggrid, 256, GEMM_SMEM>>>(ahi, alo, whi + DD,     wlo + DD,     bk,
                                              k_out, khi, klo, 1);
    gemm_tc_kernel<<<ggrid, 256, GEMM_SMEM>>>(ahi, alo, whi + 2 * DD, wlo + 2 * DD, bv,
                                              v_out, vhi, vlo, 1);

    // Attention -> ctx split into ahi/alo
    dim3 agrid(T_ / 128, NH, B_);         // (16, 16, 2)
    attn_tc_kernel<<<agrid, 256, ATTN_SMEM>>>(qhi, qlo, khi, klo, vhi, vlo, ahi, alo);

    // Output projection
    gemm_tc_kernel<<<ggrid, 256, GEMM_SMEM>>>(ahi, alo, whi + 3 * DD, wlo + 3 * DD, bo,
                                              out, nullptr, nullptr, 0);
}

// round 6
// speedup vs baseline: 1.0574x; 1.0574x over previous
#include <cuda_runtime.h>
#include <cuda_bf16.h>
#include <cstdint>
#include <math.h>

// Problem constants
#define DIM 1024
#define NH  16
#define HD  64
#define B_  2
#define T_  2048
#define M_TOT (B_ * T_)          // 4096
#define DD   ((size_t)DIM * DIM)

// ---------------------------------------------------------------------------
// Device scratch (no allocation allowed)
// ---------------------------------------------------------------------------
__device__ __nv_bfloat16 g_ahi[M_TOT * DIM];   // x-split, later ctx-split
__device__ __nv_bfloat16 g_alo[M_TOT * DIM];
__device__ __nv_bfloat16 g_whi[4 * DIM * DIM]; // Wq,Wk,Wv,Wo hi
__device__ __nv_bfloat16 g_wlo[4 * DIM * DIM];
__device__ __nv_bfloat16 g_qhi[M_TOT * DIM];   // [B,H,T,Hd], pre-scaled 1/8
__device__ __nv_bfloat16 g_qlo[M_TOT * DIM];
__device__ __nv_bfloat16 g_khi[M_TOT * DIM];
__device__ __nv_bfloat16 g_klo[M_TOT * DIM];
__device__ __nv_bfloat16 g_vhi[M_TOT * DIM];
__device__ __nv_bfloat16 g_vlo[M_TOT * DIM];
__device__ float         g_bias[3 * DIM];      // bq|bk|bv

// ===========================================================================
// Helpers (plain sm_103-compatible: ldmatrix, mma.sync, cp.async)
// ===========================================================================
__device__ __forceinline__ uint32_t smem_to_u32(const void* p) {
    uint32_t a;
    asm("{ .reg .u64 t; cvta.to.shared.u64 t, %1; cvt.u32.u64 %0, t; }"
        : "=r"(a) : "l"(p));
    return a;
}

#define LDSM_X4(r, addr) \
    asm volatile("ldmatrix.sync.aligned.m8n8.x4.shared.b16 {%0,%1,%2,%3}, [%4];" \
        : "=r"((r)[0]), "=r"((r)[1]), "=r"((r)[2]), "=r"((r)[3]) : "r"(addr))

#define LDSM_X4_T(r, addr) \
    asm volatile("ldmatrix.sync.aligned.m8n8.x4.trans.shared.b16 {%0,%1,%2,%3}, [%4];" \
        : "=r"((r)[0]), "=r"((r)[1]), "=r"((r)[2]), "=r"((r)[3]) : "r"(addr))

#define MMA_BF16(d, a, b) \
    asm volatile("mma.sync.aligned.m16n8k16.row.col.f32.bf16.bf16.f32 " \
        "{%0,%1,%2,%3}, {%4,%5,%6,%7}, {%8,%9}, {%0,%1,%2,%3};" \
        : "+f"((d)[0]), "+f"((d)[1]), "+f"((d)[2]), "+f"((d)[3]) \
        : "r"((a)[0]), "r"((a)[1]), "r"((a)[2]), "r"((a)[3]), \
          "r"((b)[0]), "r"((b)[1]))

#define CP_A16(dst, src) \
    asm volatile("cp.async.cg.shared.global [%0], [%1], 16;" \
        :: "r"(dst), "l"(src) : "memory")
#define CP_COMMIT() asm volatile("cp.async.commit_group;" ::: "memory")
#define CP_WAIT(N)  asm volatile("cp.async.wait_group %0;" :: "n"(N) : "memory")

__device__ __forceinline__ void split4(float4 v, uint2& hi, uint2& lo) {
    __nv_bfloat162 h01 = __floats2bfloat162_rn(v.x, v.y);
    __nv_bfloat162 h23 = __floats2bfloat162_rn(v.z, v.w);
    __nv_bfloat162 l01 = __floats2bfloat162_rn(v.x - __bfloat162float(h01.x),
                                               v.y - __bfloat162float(h01.y));
    __nv_bfloat162 l23 = __floats2bfloat162_rn(v.z - __bfloat162float(h23.x),
                                               v.w - __bfloat162float(h23.y));
    hi = make_uint2(*reinterpret_cast<uint32_t*>(&h01),
                    *reinterpret_cast<uint32_t*>(&h23));
    lo = make_uint2(*reinterpret_cast<uint32_t*>(&l01),
                    *reinterpret_cast<uint32_t*>(&l23));
}

__device__ __forceinline__ void store_pair(
    __nv_bfloat16* hi, __nv_bfloat16* lo, size_t o, float v0, float v1)
{
    __nv_bfloat162 h = __floats2bfloat162_rn(v0, v1);
    __nv_bfloat162 l = __floats2bfloat162_rn(v0 - __bfloat162float(h.x),
                                             v1 - __bfloat162float(h.y));
    *reinterpret_cast<__nv_bfloat162*>(hi + o) = h;
    *reinterpret_cast<__nv_bfloat162*>(lo + o) = l;
}

// ===========================================================================
// Pre-split kernels
// ===========================================================================
__global__ void __launch_bounds__(256) split_x_kernel(const float* __restrict__ x)
{
    const int i = blockIdx.x * 256 + threadIdx.x;   // < M_TOT*DIM/4
    float4 v = reinterpret_cast<const float4*>(x)[i];
    uint2 h, l;
    split4(v, h, l);
    reinterpret_cast<uint2*>(g_ahi)[i] = h;
    reinterpret_cast<uint2*>(g_alo)[i] = l;
}

__global__ void __launch_bounds__(256) split_w_kernel(
    const float* __restrict__ w0, const float* __restrict__ w1,
    const float* __restrict__ w2, const float* __restrict__ w3)
{
    const int y = blockIdx.y;
    const float* src = (y == 0) ? w0 : (y == 1) ? w1 : (y == 2) ? w2 : w3;
    const int i = blockIdx.x * 256 + threadIdx.x;   // < DD/4
    float4 v = reinterpret_cast<const float4*>(src)[i];
    uint2 h, l;
    split4(v, h, l);
    reinterpret_cast<uint2*>(g_whi + (size_t)y * DD)[i] = h;
    reinterpret_cast<uint2*>(g_wlo + (size_t)y * DD)[i] = l;
}

__global__ void __launch_bounds__(256) copy_bias_kernel(
    const float* __restrict__ b0, const float* __restrict__ b1,
    const float* __restrict__ b2)
{
    const int i = blockIdx.x * 256 + threadIdx.x;   // < 3*DIM
    float v;
    if (i < DIM)            v = b0[i];
    else if (i < 2 * DIM)   v = b1[i - DIM];
    else                    v = b2[i - 2 * DIM];
    g_bias[i] = v;
}

// ===========================================================================
// GEMM mainloop: tile 128(M) x 64(N), BK=64, 2-stage cp.async, 256 thr/8 warps
// warp tile 32x32 (warp_m = wid&3, warp_n = wid>>2). 3-term split-bf16.
// Stage: Ahi[128x144] Alo Whi[64x144] Wlo = 55296 B; 2 stages = 110592 B.
// ===========================================================================
#define GROW   144
#define A_T    18432                 // 128*144
#define W_T    9216                  // 64*144
#define OFF_AL (A_T)
#define OFF_WH (2 * A_T)
#define OFF_WL (2 * A_T + W_T)
#define STAGE  55296
#define GEMM_SMEM (2 * STAGE)        // 110592
#define NCH 16

__device__ __forceinline__ void gemm_mainloop(
    const __nv_bfloat16* __restrict__ Ahi, const __nv_bfloat16* __restrict__ Alo,
    const __nv_bfloat16* __restrict__ Whi, const __nv_bfloat16* __restrict__ Wlo,
    int m0, int n0, uint32_t sb, float acc[2][4][4])
{
    const int tid  = threadIdx.x;
    const int lane = tid & 31;
    const int wid  = tid >> 5;
    const int warp_m = wid & 3;
    const int warp_n = wid >> 2;
    const int r    = lane & 7;
    const int quad = lane >> 3;
    const uint32_t a_off =
        (uint32_t)(warp_m * 32 + (quad & 1) * 8 + r) * GROW + (quad >> 1) * 16;
    const uint32_t b_off =
        (uint32_t)(warp_n * 32 + (quad >> 1) * 8 + r) * GROW + (quad & 1) * 16;

    auto ISSUE = [&](int c, int p) {
        const int k0 = c * 64;
        const uint32_t st = sb + p * STAGE;
        #pragma unroll
        for (int i = 0; i < 4; i++) {              // A: 1024 16B-chunks (hi+lo)
            const int f   = i * 256 + tid;
            const int row = f >> 3, cc = f & 7;
            const size_t g = (size_t)(m0 + row) * DIM + k0 + cc * 8;
            const uint32_t d = st + (uint32_t)row * GROW + cc * 16;
            CP_A16(d,          Ahi + g);
            CP_A16(d + OFF_AL, Alo + g);
        }
        #pragma unroll
        for (int i = 0; i < 2; i++) {              // W: 512 chunks (hi+lo)
            const int f   = i * 256 + tid;
            const int row = f >> 3, cc = f & 7;
            const size_t g = (size_t)(n0 + row) * DIM + k0 + cc * 8;
            const uint32_t d = st + (uint32_t)row * GROW + cc * 16;
            CP_A16(d + OFF_WH, Whi + g);
            CP_A16(d + OFF_WL, Wlo + g);
        }
        CP_COMMIT();
    };

    ISSUE(0, 0);
    ISSUE(1, 1);

    for (int c = 0; c < NCH; ++c) {
        const int p = c & 1;
        if (c < NCH - 1) { CP_WAIT(1); } else { CP_WAIT(0); }
        __syncthreads();

        const uint32_t st = sb + p * STAGE;
        #pragma unroll
        for (int ks = 0; ks < 4; ++ks) {
            uint32_t ah[2][4], al[2][4];
            #pragma unroll
            for (int mi = 0; mi < 2; mi++) {
                const uint32_t addr = st + a_off + mi * (16 * GROW) + ks * 32;
                LDSM_X4(ah[mi], addr);
                LDSM_X4(al[mi], addr + OFF_AL);
            }
            uint32_t bh[4][2], bl[4][2];
            #pragma unroll
            for (int pr = 0; pr < 2; pr++) {
                const uint32_t addr = st + b_off + pr * (16 * GROW) + ks * 32;
                LDSM_X4(&bh[2 * pr][0], addr + OFF_WH);
                LDSM_X4(&bl[2 * pr][0], addr + OFF_WL);
            }
            #pragma unroll
            for (int mi = 0; mi < 2; mi++)
                #pragma unroll
                for (int ni = 0; ni < 4; ni++) {
                    MMA_BF16(acc[mi][ni], ah[mi], bh[ni]);
                    MMA_BF16(acc[mi][ni], al[mi], bh[ni]);
                    MMA_BF16(acc[mi][ni], ah[mi], bl[ni]);
                }
        }
        __syncthreads();
        if (c + 2 < NCH) ISSUE(c + 2, p);
    }
}

// Fused QKV projection: grid (48, 32). id = blockIdx.x>>4 selects Q/K/V.
__global__ void __launch_bounds__(256, 1) qkv_gemm_kernel(
    float* __restrict__ k_out, float* __restrict__ v_out)
{
    extern __shared__ char smem[];
    const uint32_t sb = smem_to_u32(smem);
    const int nb = blockIdx.x;
    const int id = nb >> 4;
    const int n0 = (nb & 15) * 64;
    const int m0 = blockIdx.y * 128;

    float acc[2][4][4];
    #pragma unroll
    for (int mi = 0; mi < 2; mi++)
        #pragma unroll
        for (int ni = 0; ni < 4; ni++)
            #pragma unroll
            for (int j = 0; j < 4; j++) acc[mi][ni][j] = 0.0f;

    gemm_mainloop(g_ahi, g_alo, g_whi + (size_t)id * DD, g_wlo + (size_t)id * DD,
                  m0, n0, sb, acc);

    const int lane = threadIdx.x & 31;
    const int wid  = threadIdx.x >> 5;
    const int warp_m = wid & 3;
    const int warp_n = wid >> 2;
    const int gid  = lane >> 2;
    const int tid4 = lane & 3;

    #pragma unroll
    for (int mi = 0; mi < 2; mi++) {
        #pragma unroll
        for (int ni = 0; ni < 4; ni++) {
            const int n = n0 + warp_n * 32 + ni * 8 + tid4 * 2;
            const float2 bb =
                *reinterpret_cast<const float2*>(&g_bias[id * DIM + n]);
            #pragma unroll
            for (int hrow = 0; hrow < 2; hrow++) {
                const int m = m0 + warp_m * 32 + mi * 16 + gid + hrow * 8;
                float v0 = acc[mi][ni][hrow * 2 + 0] + bb.x;
                float v1 = acc[mi][ni][hrow * 2 + 1] + bb.y;
                const int b  = m >> 11;
                const int t  = m & (T_ - 1);
                const int h  = n >> 6;
                const int hd = n & (HD - 1);
                const size_t o = ((((size_t)b * NH + h) * T_) + t) * HD + hd;
                if (id == 0) {                     // Q: bf16 only, x 1/8
                    store_pair(g_qhi, g_qlo, o, v0 * 0.125f, v1 * 0.125f);
                } else if (id == 1) {              // K: fp32 out + bf16
                    float2 of; of.x = v0; of.y = v1;
                    *reinterpret_cast<float2*>(&k_out[o]) = of;
                    store_pair(g_khi, g_klo, o, v0, v1);
                } else {                           // V
                    float2 of; of.x = v0; of.y = v1;
                    *reinterpret_cast<float2*>(&v_out[o]) = of;
                    store_pair(g_vhi, g_vlo, o, v0, v1);
                }
            }
        }
    }
}

// Output projection: ctx(bf16 split in g_ahi/g_alo) @ Wo^T + bo -> fp32 out
__global__ void __launch_bounds__(256, 1) oproj_gemm_kernel(
    const float* __restrict__ bo, float* __restrict__ out)
{
    extern __shared__ char smem[];
    const uint32_t sb = smem_to_u32(smem);
    const int n0 = blockIdx.x * 64;
    const int m0 = blockIdx.y * 128;

    float acc[2][4][4];
    #pragma unroll
    for (int mi = 0; mi < 2; mi++)
        #pragma unroll
        for (int ni = 0; ni < 4; ni++)
            #pragma unroll
            for (int j = 0; j < 4; j++) acc[mi][ni][j] = 0.0f;

    gemm_mainloop(g_ahi, g_alo, g_whi + 3 * DD, g_wlo + 3 * DD, m0, n0, sb, acc);

    const int lane = threadIdx.x & 31;
    const int wid  = threadIdx.x >> 5;
    const int warp_m = wid & 3;
    const int warp_n = wid >> 2;
    const int gid  = lane >> 2;
    const int tid4 = lane & 3;

    #pragma unroll
    for (int mi = 0; mi < 2; mi++) {
        #pragma unroll
        for (int ni = 0; ni < 4; ni++) {
            const int n = n0 + warp_n * 32 + ni * 8 + tid4 * 2;
            const float2 bb = *reinterpret_cast<const float2*>(&bo[n]);
            #pragma unroll
            for (int hrow = 0; hrow < 2; hrow++) {
                const int m = m0 + warp_m * 32 + mi * 16 + gid + hrow * 8;
                float2 o;
                o.x = acc[mi][ni][hrow * 2 + 0] + bb.x;
                o.y = acc[mi][ni][hrow * 2 + 1] + bb.y;
                *reinterpret_cast<float2*>(&out[(size_t)m * DIM + n]) = o;
            }
        }
    }
}

// ===========================================================================
// Tensor-core causal flash attention, bf16 hi/lo inputs, cp.async KV pipeline.
// 128 threads / 4 warps; q-tile 64 (16 rows/warp); kv-tile 64 double-buffered.
// Smem: KV stages 2x36864 | Q 18432 | P 18432 = 110592 -> 2 CTAs/SM.
// Writes ctx as bf16 hi/lo into g_ahi/g_alo [B,T,DIM].
// ===========================================================================
#define KV_T   9216                    // one 64x144 tile
#define KV_STG (4 * KV_T)              // Khi,Klo,Vhi,Vlo = 36864
#define OFF_Q  (2 * KV_STG)            // 73728
#define OFF_P  (OFF_Q + 2 * KV_T)      // 92160 (Q hi+lo = 18432)
#define ATTN_SMEM (OFF_P + 2 * KV_T)   // 110592

__global__ void __launch_bounds__(128, 2) attn_tc_kernel(
    float* __restrict__ dummy)
{
    extern __shared__ char smem[];
    const uint32_t sb = smem_to_u32(smem);
    const int tid  = threadIdx.x;
    const int lane = tid & 31;
    const int w    = tid >> 5;
    const int qt = gridDim.x - 1 - blockIdx.x;    // heavy tiles first
    const int h  = blockIdx.y;
    const int b  = blockIdx.z;
    const int q0 = qt * 64;
    const int nkv = qt + 1;

    const size_t head = ((size_t)b * NH + h) * T_ * HD;

    const int r    = lane & 7;
    const int quad = lane >> 3;
    const int gid  = lane >> 2;
    const int tid4 = lane & 3;
    const uint32_t a_off =
        (uint32_t)((quad & 1) * 8 + r) * GROW + (quad >> 1) * 16;
    const uint32_t b_off =
        (uint32_t)((quad >> 1) * 8 + r) * GROW + (quad & 1) * 16;

    // ---- prologue: Q (group 0), KV0, KV1 ----
    {   // Q: 64 rows x 8 chunks x (hi+lo) = 1024 chunks / 128 thr = 8 each
        #pragma unroll
        for (int i = 0; i < 4; i++) {
            const int f   = i * 128 + tid;
            const int row = f >> 3, cc = f & 7;
            const size_t g = head + (size_t)(q0 + row) * HD + cc * 8;
            const uint32_t d = sb + OFF_Q + (uint32_t)row * GROW + cc * 16;
            CP_A16(d,        g_qhi + g);
            CP_A16(d + KV_T, g_qlo + g);
        }
        CP_COMMIT();
    }
    auto ISSUE_KV = [&](int it, int p) {
        const int j0 = it * 64;
        const uint32_t st = sb + p * KV_STG;
        #pragma unroll
        for (int i = 0; i < 4; i++) {
            const int f   = i * 128 + tid;
            const int row = f >> 3, cc = f & 7;
            const size_t g = head + (size_t)(j0 + row) * HD + cc * 8;
            const uint32_t d = st + (uint32_t)row * GROW + cc * 16;
            CP_A16(d,            g_khi + g);
            CP_A16(d + KV_T,     g_klo + g);
            CP_A16(d + 2 * KV_T, g_vhi + g);
            CP_A16(d + 3 * KV_T, g_vlo + g);
        }
        CP_COMMIT();
    };
    ISSUE_KV(0, 0);
    if (nkv > 1) ISSUE_KV(1, 1);

    uint32_t qh[4][4], ql[4][4];
    float c_acc[8][4];
    #pragma unroll
    for (int nt = 0; nt < 8; nt++)
        #pragma unroll
        for (int j = 0; j < 4; j++) c_acc[nt][j] = 0.0f;
    float m0r = -INFINITY, m1r = -INFINITY;
    float l0r = 0.0f, l1r = 0.0f;

    const int row0 = w * 16 + gid;
    const int row1 = row0 + 8;

    for (int it = 0; it < nkv; ++it) {
        const int p = it & 1;
        if (it < nkv - 1) { CP_WAIT(1); } else { CP_WAIT(0); }
        __syncthreads();

        if (it == 0) {
            #pragma unroll
            for (int ks = 0; ks < 4; ks++) {
                const uint32_t addr =
                    sb + OFF_Q + (uint32_t)(w * 16) * GROW + a_off + ks * 32;
                LDSM_X4(qh[ks], addr);
                LDSM_X4(ql[ks], addr + KV_T);
            }
        }

        const uint32_t kst = sb + p * KV_STG;

        // ---- S = Q @ K^T (3-term) ----
        float s[8][4];
        #pragma unroll
        for (int nt = 0; nt < 8; nt++)
            #pragma unroll
            for (int j = 0; j < 4; j++) s[nt][j] = 0.0f;

        #pragma unroll
        for (int ks = 0; ks < 4; ++ks) {
            uint32_t kb[4][4];
            #pragma unroll
            for (int p2 = 0; p2 < 4; p2++)
                LDSM_X4(kb[p2], kst + (uint32_t)(p2 * 16) * GROW + b_off + ks * 32);
            #pragma unroll
            for (int p2 = 0; p2 < 4; p2++) {
                MMA_BF16(s[2 * p2 + 0], qh[ks], &kb[p2][0]);
                MMA_BF16(s[2 * p2 + 1], qh[ks], &kb[p2][2]);
                MMA_BF16(s[2 * p2 + 0], ql[ks], &kb[p2][0]);
                MMA_BF16(s[2 * p2 + 1], ql[ks], &kb[p2][2]);
            }
            #pragma unroll
            for (int p2 = 0; p2 < 4; p2++)
                LDSM_X4(kb[p2], kst + KV_T + (uint32_t)(p2 * 16) * GROW
                                + b_off + ks * 32);
            #pragma unroll
            for (int p2 = 0; p2 < 4; p2++) {
                MMA_BF16(s[2 * p2 + 0], qh[ks], &kb[p2][0]);
                MMA_BF16(s[2 * p2 + 1], qh[ks], &kb[p2][2]);
            }
        }

        // ---- causal mask (diagonal tile only) ----
        if (it == qt) {
            #pragma unroll
            for (int nt = 0; nt < 8; nt++) {
                const int c0 = nt * 8 + tid4 * 2;
                if (c0     > row0) s[nt][0] = -INFINITY;
                if (c0 + 1 > row0) s[nt][1] = -INFINITY;
                if (c0     > row1) s[nt][2] = -INFINITY;
                if (c0 + 1 > row1) s[nt][3] = -INFINITY;
            }
        }

        // ---- online softmax ----
        float mt0 = -INFINITY, mt1 = -INFINITY;
        #pragma unroll
        for (int nt = 0; nt < 8; nt++) {
            mt0 = fmaxf(mt0, fmaxf(s[nt][0], s[nt][1]));
            mt1 = fmaxf(mt1, fmaxf(s[nt][2], s[nt][3]));
        }
        mt0 = fmaxf(mt0, __shfl_xor_sync(0xffffffffu, mt0, 1));
        mt0 = fmaxf(mt0, __shfl_xor_sync(0xffffffffu, mt0, 2));
        mt1 = fmaxf(mt1, __shfl_xor_sync(0xffffffffu, mt1, 1));
        mt1 = fmaxf(mt1, __shfl_xor_sync(0xffffffffu, mt1, 2));

        const float mn0 = fmaxf(m0r, mt0);
        const float mn1 = fmaxf(m1r, mt1);
        const float sc0 = __expf(m0r - mn0);
        const float sc1 = __expf(m1r - mn1);
        m0r = mn0; m1r = mn1;

        float ls0 = 0.0f, ls1 = 0.0f;
        #pragma unroll
        for (int nt = 0; nt < 8; nt++) {
            s[nt][0] = __expf(s[nt][0] - mn0);
            s[nt][1] = __expf(s[nt][1] - mn0);
            s[nt][2] = __expf(s[nt][2] - mn1);
            s[nt][3] = __expf(s[nt][3] - mn1);
            ls0 += s[nt][0] + s[nt][1];
            ls1 += s[nt][2] + s[nt][3];
        }
        ls0 += __shfl_xor_sync(0xffffffffu, ls0, 1);
        ls0 += __shfl_xor_sync(0xffffffffu, ls0, 2);
        ls1 += __shfl_xor_sync(0xffffffffu, ls1, 1);
        ls1 += __shfl_xor_sync(0xffffffffu, ls1, 2);
        l0r = l0r * sc0 + ls0;
        l1r = l1r * sc1 + ls1;

        #pragma unroll
        for (int nt = 0; nt < 8; nt++) {
            c_acc[nt][0] *= sc0; c_acc[nt][1] *= sc0;
            c_acc[nt][2] *= sc1; c_acc[nt][3] *= sc1;
        }

        // ---- write P (split bf16) to per-warp rows of P region ----
        #pragma unroll
        for (int nt = 0; nt < 8; nt++) {
            __nv_bfloat162 h01 = __floats2bfloat162_rn(s[nt][0], s[nt][1]);
            __nv_bfloat162 l01 = __floats2bfloat162_rn(
                s[nt][0] - __bfloat162float(h01.x),
                s[nt][1] - __bfloat162float(h01.y));
            __nv_bfloat162 h23 = __floats2bfloat162_rn(s[nt][2], s[nt][3]);
            __nv_bfloat162 l23 = __floats2bfloat162_rn(
                s[nt][2] - __bfloat162float(h23.x),
                s[nt][3] - __bfloat162float(h23.y));
            const uint32_t c0 = (uint32_t)(nt * 16 + tid4 * 4);
            char* p0 = smem + OFF_P + (uint32_t)row0 * GROW + c0;
            char* p1 = smem + OFF_P + (uint32_t)row1 * GROW + c0;
            *reinterpret_cast<uint32_t*>(p0)        = *reinterpret_cast<uint32_t*>(&h01);
            *reinterpret_cast<uint32_t*>(p0 + KV_T) = *reinterpret_cast<uint32_t*>(&l01);
            *reinterpret_cast<uint32_t*>(p1)        = *reinterpret_cast<uint32_t*>(&h23);
            *reinterpret_cast<uint32_t*>(p1 + KV_T) = *reinterpret_cast<uint32_t*>(&l23);
        }
        __syncwarp();

        // ---- ctx += P @ V (3-term) ----
        #pragma unroll
        for (int kk = 0; kk < 4; ++kk) {
            uint32_t ph[4], pl[4];
            const uint32_t paddr =
                sb + OFF_P + (uint32_t)(w * 16) * GROW + a_off + kk * 32;
            LDSM_X4(ph, paddr);
            LDSM_X4(pl, paddr + KV_T);

            uint32_t vb[4][4];
            #pragma unroll
            for (int nt2 = 0; nt2 < 4; nt2++)
                LDSM_X4_T(vb[nt2], kst + 2 * KV_T
                          + (uint32_t)(kk * 16) * GROW + a_off + nt2 * 32);
            #pragma unroll
            for (int nt2 = 0; nt2 < 4; nt2++) {
                MMA_BF16(c_acc[2 * nt2 + 0], ph, &vb[nt2][0]);
                MMA_BF16(c_acc[2 * nt2 + 1], ph, &vb[nt2][2]);
                MMA_BF16(c_acc[2 * nt2 + 0], pl, &vb[nt2][0]);
                MMA_BF16(c_acc[2 * nt2 + 1], pl, &vb[nt2][2]);
            }
            #pragma unroll
            for (int nt2 = 0; nt2 < 4; nt2++)
                LDSM_X4_T(vb[nt2], kst + 3 * KV_T
                          + (uint32_t)(kk * 16) * GROW + a_off + nt2 * 32);
            #pragma unroll
            for (int nt2 = 0; nt2 < 4; nt2++) {
                MMA_BF16(c_acc[2 * nt2 + 0], ph, &vb[nt2][0]);
                MMA_BF16(c_acc[2 * nt2 + 1], ph, &vb[nt2][2]);
            }
        }
        __syncthreads();
        if (it + 2 < nkv) ISSUE_KV(it + 2, p);
    }

    // ---- epilogue: ctx/l -> bf16 hi/lo into g_ahi/g_alo [B,T,DIM] ----
    const float inv0 = 1.0f / l0r;
    const float inv1 = 1.0f / l1r;
    const int qr0 = q0 + row0;
    const int qr1 = q0 + row1;
    #pragma unroll
    for (int nt = 0; nt < 8; nt++) {
        const int hd = nt * 8 + tid4 * 2;
        const size_t o0 = ((size_t)b * T_ + qr0) * DIM + h * HD + hd;
        const size_t o1 = ((size_t)b * T_ + qr1) * DIM + h * HD + hd;
        store_pair(g_ahi, g_alo, o0, c_acc[nt][0] * inv0, c_acc[nt][1] * inv0);
        store_pair(g_ahi, g_alo, o1, c_acc[nt][2] * inv1, c_acc[nt][3] * inv1);
    }
    (void)dummy;
}

// ---------------------------------------------------------------------------
// kernel_launch
// ---------------------------------------------------------------------------
extern "C" void kernel_launch(void* const* d_in, const int* in_sizes, int n_in,
                              void* d_out, int out_size)
{
    const float* x  = (const float*)d_in[0];
    const float* Wq = (const float*)d_in[1];
    const float* bq = (const float*)d_in[2];
    const float* Wk = (const float*)d_in[3];
    const float* bk = (const float*)d_in[4];
    const float* Wv = (const float*)d_in[5];
    const float* bv = (const float*)d_in[6];
    const float* Wo = (const float*)d_in[7];
    const float* bo = (const float*)d_in[8];

    float* out   = (float*)d_out;
    float* k_out = out + (size_t)M_TOT * DIM;
    float* v_out = out + (size_t)2 * M_TOT * DIM;

    cudaFuncSetAttribute(qkv_gemm_kernel,
                         cudaFuncAttributeMaxDynamicSharedMemorySize, GEMM_SMEM);
    cudaFuncSetAttribute(oproj_gemm_kernel,
                         cudaFuncAttributeMaxDynamicSharedMemorySize, GEMM_SMEM);
    cudaFuncSetAttribute(attn_tc_kernel,
                         cudaFuncAttributeMaxDynamicSharedMemorySize, ATTN_SMEM);

    // Pre-split x, weights; gather biases
    split_x_kernel<<<M_TOT * DIM / 4 / 256, 256>>>(x);
    {
        dim3 wg(DD / 4 / 256, 4);
        split_w_kernel<<<wg, 256>>>(Wq, Wk, Wv, Wo);
    }
    copy_bias_kernel<<<3 * DIM / 256, 256>>>(bq, bk, bv);

    // Fused QKV projection
    dim3 qkvg(48, M_TOT / 128);           // (48, 32)
    qkv_gemm_kernel<<<qkvg, 256, GEMM_SMEM>>>(k_out, v_out);

    // Causal flash attention
    dim3 agrid(T_ / 64, NH, B_);          // (32, 16, 2)
    attn_tc_kernel<<<agrid, 128, ATTN_SMEM>>>(nullptr);

    // Output projection
    dim3 og(DIM / 64, M_TOT / 128);       // (16, 32)
    oproj_gemm_kernel<<<og, 256, GEMM_SMEM>>>(bo, out);
}

// round 7
// speedup vs baseline: 1.0702x; 1.0121x over previous
#include <cuda_runtime.h>
#include <cuda_bf16.h>
#include <cstdint>
#include <math.h>

// Problem constants
#define DIM 1024
#define NH  16
#define HD  64
#define B_  2
#define T_  2048
#define M_TOT (B_ * T_)          // 4096
#define DD   ((size_t)DIM * DIM)

// ---------------------------------------------------------------------------
// Device scratch (no allocation allowed)
// ---------------------------------------------------------------------------
__device__ __nv_bfloat16 g_ahi[M_TOT * DIM];   // x-split, later ctx-split
__device__ __nv_bfloat16 g_alo[M_TOT * DIM];
__device__ __nv_bfloat16 g_whi[4 * DIM * DIM]; // Wq,Wk,Wv,Wo hi
__device__ __nv_bfloat16 g_wlo[4 * DIM * DIM];
__device__ __nv_bfloat16 g_qhi[M_TOT * DIM];   // [B,H,T,Hd], pre-scaled 1/8
__device__ __nv_bfloat16 g_qlo[M_TOT * DIM];
__device__ __nv_bfloat16 g_khi[M_TOT * DIM];
__device__ __nv_bfloat16 g_klo[M_TOT * DIM];
__device__ __nv_bfloat16 g_vhi[M_TOT * DIM];
__device__ __nv_bfloat16 g_vlo[M_TOT * DIM];
__device__ float         g_bias[3 * DIM];      // bq|bk|bv

// ===========================================================================
// Helpers (plain sm_103-compatible: ldmatrix, mma.sync, cp.async)
// ===========================================================================
__device__ __forceinline__ uint32_t smem_to_u32(const void* p) {
    uint32_t a;
    asm("{ .reg .u64 t; cvta.to.shared.u64 t, %1; cvt.u32.u64 %0, t; }"
        : "=r"(a) : "l"(p));
    return a;
}

#define LDSM_X4(r, addr) \
    asm volatile("ldmatrix.sync.aligned.m8n8.x4.shared.b16 {%0,%1,%2,%3}, [%4];" \
        : "=r"((r)[0]), "=r"((r)[1]), "=r"((r)[2]), "=r"((r)[3]) : "r"(addr))

#define LDSM_X4_T(r, addr) \
    asm volatile("ldmatrix.sync.aligned.m8n8.x4.trans.shared.b16 {%0,%1,%2,%3}, [%4];" \
        : "=r"((r)[0]), "=r"((r)[1]), "=r"((r)[2]), "=r"((r)[3]) : "r"(addr))

#define MMA_BF16(d, a, b) \
    asm volatile("mma.sync.aligned.m16n8k16.row.col.f32.bf16.bf16.f32 " \
        "{%0,%1,%2,%3}, {%4,%5,%6,%7}, {%8,%9}, {%0,%1,%2,%3};" \
        : "+f"((d)[0]), "+f"((d)[1]), "+f"((d)[2]), "+f"((d)[3]) \
        : "r"((a)[0]), "r"((a)[1]), "r"((a)[2]), "r"((a)[3]), \
          "r"((b)[0]), "r"((b)[1]))

#define CP_A16(dst, src) \
    asm volatile("cp.async.cg.shared.global [%0], [%1], 16;" \
        :: "r"(dst), "l"(src) : "memory")
#define CP_COMMIT() asm volatile("cp.async.commit_group;" ::: "memory")
#define CP_WAIT(N)  asm volatile("cp.async.wait_group %0;" :: "n"(N) : "memory")

__device__ __forceinline__ void split4(float4 v, uint2& hi, uint2& lo) {
    __nv_bfloat162 h01 = __floats2bfloat162_rn(v.x, v.y);
    __nv_bfloat162 h23 = __floats2bfloat162_rn(v.z, v.w);
    __nv_bfloat162 l01 = __floats2bfloat162_rn(v.x - __bfloat162float(h01.x),
                                               v.y - __bfloat162float(h01.y));
    __nv_bfloat162 l23 = __floats2bfloat162_rn(v.z - __bfloat162float(h23.x),
                                               v.w - __bfloat162float(h23.y));
    hi = make_uint2(*reinterpret_cast<uint32_t*>(&h01),
                    *reinterpret_cast<uint32_t*>(&h23));
    lo = make_uint2(*reinterpret_cast<uint32_t*>(&l01),
                    *reinterpret_cast<uint32_t*>(&l23));
}

__device__ __forceinline__ void store_pair(
    __nv_bfloat16* hi, __nv_bfloat16* lo, size_t o, float v0, float v1)
{
    __nv_bfloat162 h = __floats2bfloat162_rn(v0, v1);
    __nv_bfloat162 l = __floats2bfloat162_rn(v0 - __bfloat162float(h.x),
                                             v1 - __bfloat162float(h.y));
    *reinterpret_cast<__nv_bfloat162*>(hi + o) = h;
    *reinterpret_cast<__nv_bfloat162*>(lo + o) = l;
}

// ===========================================================================
// Pre-split kernels
// ===========================================================================
__global__ void __launch_bounds__(256) split_x_kernel(const float* __restrict__ x)
{
    const int i = blockIdx.x * 256 + threadIdx.x;
    float4 v = reinterpret_cast<const float4*>(x)[i];
    uint2 h, l;
    split4(v, h, l);
    reinterpret_cast<uint2*>(g_ahi)[i] = h;
    reinterpret_cast<uint2*>(g_alo)[i] = l;
}

__global__ void __launch_bounds__(256) split_w_kernel(
    const float* __restrict__ w0, const float* __restrict__ w1,
    const float* __restrict__ w2, const float* __restrict__ w3)
{
    const int y = blockIdx.y;
    const float* src = (y == 0) ? w0 : (y == 1) ? w1 : (y == 2) ? w2 : w3;
    const int i = blockIdx.x * 256 + threadIdx.x;
    float4 v = reinterpret_cast<const float4*>(src)[i];
    uint2 h, l;
    split4(v, h, l);
    reinterpret_cast<uint2*>(g_whi + (size_t)y * DD)[i] = h;
    reinterpret_cast<uint2*>(g_wlo + (size_t)y * DD)[i] = l;
}

__global__ void __launch_bounds__(256) copy_bias_kernel(
    const float* __restrict__ b0, const float* __restrict__ b1,
    const float* __restrict__ b2)
{
    const int i = blockIdx.x * 256 + threadIdx.x;
    float v;
    if (i < DIM)            v = b0[i];
    else if (i < 2 * DIM)   v = b1[i - DIM];
    else                    v = b2[i - 2 * DIM];
    g_bias[i] = v;
}

// ===========================================================================
// GEMM mainloop: block 128(M) x 128(N), BK=64, 3-stage cp.async, 1 sync/chunk.
// 256 thr / 8 warps (2x4); warp tile 64x32. 3-term split-bf16.
// Stage: Ahi,Alo [128x144] + Whi,Wlo [128x144] = 73728 B; 3 stages = 221184 B.
// ===========================================================================
#define GROW   144
#define G_T    18432                 // 128*144
#define OFF_AL (G_T)
#define OFF_WH (2 * G_T)
#define OFF_WL (3 * G_T)
#define STAGE  (4 * G_T)             // 73728
#define GEMM_SMEM (3 * STAGE)        // 221184
#define NCH 16

__device__ __forceinline__ void gemm_mainloop(
    const __nv_bfloat16* __restrict__ Ahi, const __nv_bfloat16* __restrict__ Alo,
    const __nv_bfloat16* __restrict__ Whi, const __nv_bfloat16* __restrict__ Wlo,
    int m0, int n0, uint32_t sb, float acc[4][4][4])
{
    const int tid  = threadIdx.x;
    const int lane = tid & 31;
    const int wid  = tid >> 5;
    const int warp_m = wid & 1;          // 0..1 (64 rows)
    const int warp_n = wid >> 1;         // 0..3 (32 cols)
    const int r    = lane & 7;
    const int quad = lane >> 3;
    const uint32_t a_off =
        (uint32_t)(warp_m * 64 + (quad & 1) * 8 + r) * GROW + (quad >> 1) * 16;
    const uint32_t b_off =
        (uint32_t)(warp_n * 32 + (quad >> 1) * 8 + r) * GROW + (quad & 1) * 16;

    auto ISSUE = [&](int c, int p) {
        const int k0 = c * 64;
        const uint32_t st = sb + p * STAGE;
        #pragma unroll
        for (int i = 0; i < 4; i++) {          // A: 128x64 hi+lo
            const int f   = i * 256 + tid;
            const int row = f >> 3, cc = f & 7;
            const size_t g = (size_t)(m0 + row) * DIM + k0 + cc * 8;
            const uint32_t d = st + (uint32_t)row * GROW + cc * 16;
            CP_A16(d,          Ahi + g);
            CP_A16(d + OFF_AL, Alo + g);
        }
        #pragma unroll
        for (int i = 0; i < 4; i++) {          // W: 128x64 hi+lo
            const int f   = i * 256 + tid;
            const int row = f >> 3, cc = f & 7;
            const size_t g = (size_t)(n0 + row) * DIM + k0 + cc * 8;
            const uint32_t d = st + (uint32_t)row * GROW + cc * 16;
            CP_A16(d + OFF_WH, Whi + g);
            CP_A16(d + OFF_WL, Wlo + g);
        }
        CP_COMMIT();
    };

    ISSUE(0, 0);
    ISSUE(1, 1);

    for (int c = 0; c < NCH; ++c) {
        const int p = c - (c / 3) * 3;         // c % 3
        if (c < NCH - 1) { CP_WAIT(1); } else { CP_WAIT(0); }
        __syncthreads();

        const uint32_t st = sb + p * STAGE;
        #pragma unroll
        for (int ks = 0; ks < 4; ++ks) {
            uint32_t ah[4][4], al[4][4];
            #pragma unroll
            for (int mi = 0; mi < 4; mi++) {
                const uint32_t addr = st + a_off + mi * (16 * GROW) + ks * 32;
                LDSM_X4(ah[mi], addr);
                LDSM_X4(al[mi], addr + OFF_AL);
            }
            uint32_t bh[4][2], bl[4][2];
            #pragma unroll
            for (int pr = 0; pr < 2; pr++) {
                const uint32_t addr = st + b_off + pr * (16 * GROW) + ks * 32;
                LDSM_X4(&bh[2 * pr][0], addr + OFF_WH);
                LDSM_X4(&bl[2 * pr][0], addr + OFF_WL);
            }
            #pragma unroll
            for (int mi = 0; mi < 4; mi++)
                #pragma unroll
                for (int ni = 0; ni < 4; ni++) {
                    MMA_BF16(acc[mi][ni], ah[mi], bh[ni]);
                    MMA_BF16(acc[mi][ni], al[mi], bh[ni]);
                    MMA_BF16(acc[mi][ni], ah[mi], bl[ni]);
                }
        }
        if (c + 2 < NCH) {
            const int p2 = (c + 2) - ((c + 2) / 3) * 3;
            ISSUE(c + 2, p2);
        }
    }
}

// Fused QKV projection: grid (24, 32). id = blockIdx.x>>3 selects Q/K/V.
__global__ void __launch_bounds__(256, 1) qkv_gemm_kernel(
    float* __restrict__ k_out, float* __restrict__ v_out)
{
    extern __shared__ char smem[];
    const uint32_t sb = smem_to_u32(smem);
    const int nb = blockIdx.x;
    const int id = nb >> 3;
    const int n0 = (nb & 7) * 128;
    const int m0 = blockIdx.y * 128;

    float acc[4][4][4];
    #pragma unroll
    for (int mi = 0; mi < 4; mi++)
        #pragma unroll
        for (int ni = 0; ni < 4; ni++)
            #pragma unroll
            for (int j = 0; j < 4; j++) acc[mi][ni][j] = 0.0f;

    gemm_mainloop(g_ahi, g_alo, g_whi + (size_t)id * DD, g_wlo + (size_t)id * DD,
                  m0, n0, sb, acc);

    const int lane = threadIdx.x & 31;
    const int wid  = threadIdx.x >> 5;
    const int warp_m = wid & 1;
    const int warp_n = wid >> 1;
    const int gid  = lane >> 2;
    const int tid4 = lane & 3;

    #pragma unroll
    for (int mi = 0; mi < 4; mi++) {
        #pragma unroll
        for (int ni = 0; ni < 4; ni++) {
            const int n = n0 + warp_n * 32 + ni * 8 + tid4 * 2;
            const float2 bb =
                *reinterpret_cast<const float2*>(&g_bias[id * DIM + n]);
            #pragma unroll
            for (int hrow = 0; hrow < 2; hrow++) {
                const int m = m0 + warp_m * 64 + mi * 16 + gid + hrow * 8;
                float v0 = acc[mi][ni][hrow * 2 + 0] + bb.x;
                float v1 = acc[mi][ni][hrow * 2 + 1] + bb.y;
                const int b  = m >> 11;
                const int t  = m & (T_ - 1);
                const int h  = n >> 6;
                const int hd = n & (HD - 1);
                const size_t o = ((((size_t)b * NH + h) * T_) + t) * HD + hd;
                if (id == 0) {                     // Q: bf16 only, x 1/8
                    store_pair(g_qhi, g_qlo, o, v0 * 0.125f, v1 * 0.125f);
                } else if (id == 1) {              // K: fp32 out + bf16
                    float2 of; of.x = v0; of.y = v1;
                    *reinterpret_cast<float2*>(&k_out[o]) = of;
                    store_pair(g_khi, g_klo, o, v0, v1);
                } else {                           // V
                    float2 of; of.x = v0; of.y = v1;
                    *reinterpret_cast<float2*>(&v_out[o]) = of;
                    store_pair(g_vhi, g_vlo, o, v0, v1);
                }
            }
        }
    }
}

// Output projection: ctx(bf16 split in g_ahi/g_alo) @ Wo^T + bo -> fp32 out
__global__ void __launch_bounds__(256, 1) oproj_gemm_kernel(
    const float* __restrict__ bo, float* __restrict__ out)
{
    extern __shared__ char smem[];
    const uint32_t sb = smem_to_u32(smem);
    const int n0 = blockIdx.x * 128;
    const int m0 = blockIdx.y * 128;

    float acc[4][4][4];
    #pragma unroll
    for (int mi = 0; mi < 4; mi++)
        #pragma unroll
        for (int ni = 0; ni < 4; ni++)
            #pragma unroll
            for (int j = 0; j < 4; j++) acc[mi][ni][j] = 0.0f;

    gemm_mainloop(g_ahi, g_alo, g_whi + 3 * DD, g_wlo + 3 * DD, m0, n0, sb, acc);

    const int lane = threadIdx.x & 31;
    const int wid  = threadIdx.x >> 5;
    const int warp_m = wid & 1;
    const int warp_n = wid >> 1;
    const int gid  = lane >> 2;
    const int tid4 = lane & 3;

    #pragma unroll
    for (int mi = 0; mi < 4; mi++) {
        #pragma unroll
        for (int ni = 0; ni < 4; ni++) {
            const int n = n0 + warp_n * 32 + ni * 8 + tid4 * 2;
            const float2 bb = *reinterpret_cast<const float2*>(&bo[n]);
            #pragma unroll
            for (int hrow = 0; hrow < 2; hrow++) {
                const int m = m0 + warp_m * 64 + mi * 16 + gid + hrow * 8;
                float2 o;
                o.x = acc[mi][ni][hrow * 2 + 0] + bb.x;
                o.y = acc[mi][ni][hrow * 2 + 1] + bb.y;
                *reinterpret_cast<float2*>(&out[(size_t)m * DIM + n]) = o;
            }
        }
    }
}

// ===========================================================================
// Tensor-core causal flash attention (unchanged from R5 pass).
// 128 threads / 4 warps; q-tile 64; kv-tile 64 double-buffered cp.async.
// ===========================================================================
#define KV_T   9216
#define KV_STG (4 * KV_T)
#define OFF_Q  (2 * KV_STG)
#define OFF_P  (OFF_Q + 2 * KV_T)
#define ATTN_SMEM (OFF_P + 2 * KV_T)   // 110592

__global__ void __launch_bounds__(128, 2) attn_tc_kernel(
    float* __restrict__ dummy)
{
    extern __shared__ char smem[];
    const uint32_t sb = smem_to_u32(smem);
    const int tid  = threadIdx.x;
    const int lane = tid & 31;
    const int w    = tid >> 5;
    const int qt = gridDim.x - 1 - blockIdx.x;
    const int h  = blockIdx.y;
    const int b  = blockIdx.z;
    const int q0 = qt * 64;
    const int nkv = qt + 1;

    const size_t head = ((size_t)b * NH + h) * T_ * HD;

    const int r    = lane & 7;
    const int quad = lane >> 3;
    const int gid  = lane >> 2;
    const int tid4 = lane & 3;
    const uint32_t a_off =
        (uint32_t)((quad & 1) * 8 + r) * GROW + (quad >> 1) * 16;
    const uint32_t b_off =
        (uint32_t)((quad >> 1) * 8 + r) * GROW + (quad & 1) * 16;

    {
        #pragma unroll
        for (int i = 0; i < 4; i++) {
            const int f   = i * 128 + tid;
            const int row = f >> 3, cc = f & 7;
            const size_t g = head + (size_t)(q0 + row) * HD + cc * 8;
            const uint32_t d = sb + OFF_Q + (uint32_t)row * GROW + cc * 16;
            CP_A16(d,        g_qhi + g);
            CP_A16(d + KV_T, g_qlo + g);
        }
        CP_COMMIT();
    }
    auto ISSUE_KV = [&](int it, int p) {
        const int j0 = it * 64;
        const uint32_t st = sb + p * KV_STG;
        #pragma unroll
        for (int i = 0; i < 4; i++) {
            const int f   = i * 128 + tid;
            const int row = f >> 3, cc = f & 7;
            const size_t g = head + (size_t)(j0 + row) * HD + cc * 8;
            const uint32_t d = st + (uint32_t)row * GROW + cc * 16;
            CP_A16(d,            g_khi + g);
            CP_A16(d + KV_T,     g_klo + g);
            CP_A16(d + 2 * KV_T, g_vhi + g);
            CP_A16(d + 3 * KV_T, g_vlo + g);
        }
        CP_COMMIT();
    };
    ISSUE_KV(0, 0);
    if (nkv > 1) ISSUE_KV(1, 1);

    uint32_t qh[4][4], ql[4][4];
    float c_acc[8][4];
    #pragma unroll
    for (int nt = 0; nt < 8; nt++)
        #pragma unroll
        for (int j = 0; j < 4; j++) c_acc[nt][j] = 0.0f;
    float m0r = -INFINITY, m1r = -INFINITY;
    float l0r = 0.0f, l1r = 0.0f;

    const int row0 = w * 16 + gid;
    const int row1 = row0 + 8;

    for (int it = 0; it < nkv; ++it) {
        const int p = it & 1;
        if (it < nkv - 1) { CP_WAIT(1); } else { CP_WAIT(0); }
        __syncthreads();

        if (it == 0) {
            #pragma unroll
            for (int ks = 0; ks < 4; ks++) {
                const uint32_t addr =
                    sb + OFF_Q + (uint32_t)(w * 16) * GROW + a_off + ks * 32;
                LDSM_X4(qh[ks], addr);
                LDSM_X4(ql[ks], addr + KV_T);
            }
        }

        const uint32_t kst = sb + p * KV_STG;

        float s[8][4];
        #pragma unroll
        for (int nt = 0; nt < 8; nt++)
            #pragma unroll
            for (int j = 0; j < 4; j++) s[nt][j] = 0.0f;

        #pragma unroll
        for (int ks = 0; ks < 4; ++ks) {
            uint32_t kb[4][4];
            #pragma unroll
            for (int p2 = 0; p2 < 4; p2++)
                LDSM_X4(kb[p2], kst + (uint32_t)(p2 * 16) * GROW + b_off + ks * 32);
            #pragma unroll
            for (int p2 = 0; p2 < 4; p2++) {
                MMA_BF16(s[2 * p2 + 0], qh[ks], &kb[p2][0]);
                MMA_BF16(s[2 * p2 + 1], qh[ks], &kb[p2][2]);
                MMA_BF16(s[2 * p2 + 0], ql[ks], &kb[p2][0]);
                MMA_BF16(s[2 * p2 + 1], ql[ks], &kb[p2][2]);
            }
            #pragma unroll
            for (int p2 = 0; p2 < 4; p2++)
                LDSM_X4(kb[p2], kst + KV_T + (uint32_t)(p2 * 16) * GROW
                                + b_off + ks * 32);
            #pragma unroll
            for (int p2 = 0; p2 < 4; p2++) {
                MMA_BF16(s[2 * p2 + 0], qh[ks], &kb[p2][0]);
                MMA_BF16(s[2 * p2 + 1], qh[ks], &kb[p2][2]);
            }
        }

        if (it == qt) {
            #pragma unroll
            for (int nt = 0; nt < 8; nt++) {
                const int c0 = nt * 8 + tid4 * 2;
                if (c0     > row0) s[nt][0] = -INFINITY;
                if (c0 + 1 > row0) s[nt][1] = -INFINITY;
                if (c0     > row1) s[nt][2] = -INFINITY;
                if (c0 + 1 > row1) s[nt][3] = -INFINITY;
            }
        }

        float mt0 = -INFINITY, mt1 = -INFINITY;
        #pragma unroll
        for (int nt = 0; nt < 8; nt++) {
            mt0 = fmaxf(mt0, fmaxf(s[nt][0], s[nt][1]));
            mt1 = fmaxf(mt1, fmaxf(s[nt][2], s[nt][3]));
        }
        mt0 = fmaxf(mt0, __shfl_xor_sync(0xffffffffu, mt0, 1));
        mt0 = fmaxf(mt0, __shfl_xor_sync(0xffffffffu, mt0, 2));
        mt1 = fmaxf(mt1, __shfl_xor_sync(0xffffffffu, mt1, 1));
        mt1 = fmaxf(mt1, __shfl_xor_sync(0xffffffffu, mt1, 2));

        const float mn0 = fmaxf(m0r, mt0);
        const float mn1 = fmaxf(m1r, mt1);
        const float sc0 = __expf(m0r - mn0);
        const float sc1 = __expf(m1r - mn1);
        m0r = mn0; m1r = mn1;

        float ls0 = 0.0f, ls1 = 0.0f;
        #pragma unroll
        for (int nt = 0; nt < 8; nt++) {
            s[nt][0] = __expf(s[nt][0] - mn0);
            s[nt][1] = __expf(s[nt][1] - mn0);
            s[nt][2] = __expf(s[nt][2] - mn1);
            s[nt][3] = __expf(s[nt][3] - mn1);
            ls0 += s[nt][0] + s[nt][1];
            ls1 += s[nt][2] + s[nt][3];
        }
        ls0 += __shfl_xor_sync(0xffffffffu, ls0, 1);
        ls0 += __shfl_xor_sync(0xffffffffu, ls0, 2);
        ls1 += __shfl_xor_sync(0xffffffffu, ls1, 1);
        ls1 += __shfl_xor_sync(0xffffffffu, ls1, 2);
        l0r = l0r * sc0 + ls0;
        l1r = l1r * sc1 + ls1;

        #pragma unroll
        for (int nt = 0; nt < 8; nt++) {
            c_acc[nt][0] *= sc0; c_acc[nt][1] *= sc0;
            c_acc[nt][2] *= sc1; c_acc[nt][3] *= sc1;
        }

        #pragma unroll
        for (int nt = 0; nt < 8; nt++) {
            __nv_bfloat162 h01 = __floats2bfloat162_rn(s[nt][0], s[nt][1]);
            __nv_bfloat162 l01 = __floats2bfloat162_rn(
                s[nt][0] - __bfloat162float(h01.x),
                s[nt][1] - __bfloat162float(h01.y));
            __nv_bfloat162 h23 = __floats2bfloat162_rn(s[nt][2], s[nt][3]);
            __nv_bfloat162 l23 = __floats2bfloat162_rn(
                s[nt][2] - __bfloat162float(h23.x),
                s[nt][3] - __bfloat162float(h23.y));
            const uint32_t c0 = (uint32_t)(nt * 16 + tid4 * 4);
            char* p0 = smem + OFF_P + (uint32_t)row0 * GROW + c0;
            char* p1 = smem + OFF_P + (uint32_t)row1 * GROW + c0;
            *reinterpret_cast<uint32_t*>(p0)        = *reinterpret_cast<uint32_t*>(&h01);
            *reinterpret_cast<uint32_t*>(p0 + KV_T) = *reinterpret_cast<uint32_t*>(&l01);
            *reinterpret_cast<uint32_t*>(p1)        = *reinterpret_cast<uint32_t*>(&h23);
            *reinterpret_cast<uint32_t*>(p1 + KV_T) = *reinterpret_cast<uint32_t*>(&l23);
        }
        __syncwarp();

        #pragma unroll
        for (int kk = 0; kk < 4; ++kk) {
            uint32_t ph[4], pl[4];
            const uint32_t paddr =
                sb + OFF_P + (uint32_t)(w * 16) * GROW + a_off + kk * 32;
            LDSM_X4(ph, paddr);
            LDSM_X4(pl, paddr + KV_T);

            uint32_t vb[4][4];
            #pragma unroll
            for (int nt2 = 0; nt2 < 4; nt2++)
                LDSM_X4_T(vb[nt2], kst + 2 * KV_T
                          + (uint32_t)(kk * 16) * GROW + a_off + nt2 * 32);
            #pragma unroll
            for (int nt2 = 0; nt2 < 4; nt2++) {
                MMA_BF16(c_acc[2 * nt2 + 0], ph, &vb[nt2][0]);
                MMA_BF16(c_acc[2 * nt2 + 1], ph, &vb[nt2][2]);
                MMA_BF16(c_acc[2 * nt2 + 0], pl, &vb[nt2][0]);
                MMA_BF16(c_acc[2 * nt2 + 1], pl, &vb[nt2][2]);
            }
            #pragma unroll
            for (int nt2 = 0; nt2 < 4; nt2++)
                LDSM_X4_T(vb[nt2], kst + 3 * KV_T
                          + (uint32_t)(kk * 16) * GROW + a_off + nt2 * 32);
            #pragma unroll
            for (int nt2 = 0; nt2 < 4; nt2++) {
                MMA_BF16(c_acc[2 * nt2 + 0], ph, &vb[nt2][0]);
                MMA_BF16(c_acc[2 * nt2 + 1], ph, &vb[nt2][2]);
            }
        }
        __syncthreads();
        if (it + 2 < nkv) ISSUE_KV(it + 2, p);
    }

    const float inv0 = 1.0f / l0r;
    const float inv1 = 1.0f / l1r;
    const int qr0 = q0 + row0;
    const int qr1 = q0 + row1;
    #pragma unroll
    for (int nt = 0; nt < 8; nt++) {
        const int hd = nt * 8 + tid4 * 2;
        const size_t o0 = ((size_t)b * T_ + qr0) * DIM + h * HD + hd;
        const size_t o1 = ((size_t)b * T_ + qr1) * DIM + h * HD + hd;
        store_pair(g_ahi, g_alo, o0, c_acc[nt][0] * inv0, c_acc[nt][1] * inv0);
        store_pair(g_ahi, g_alo, o1, c_acc[nt][2] * inv1, c_acc[nt][3] * inv1);
    }
    (void)dummy;
}

// ---------------------------------------------------------------------------
// kernel_launch
// ---------------------------------------------------------------------------
extern "C" void kernel_launch(void* const* d_in, const int* in_sizes, int n_in,
                              void* d_out, int out_size)
{
    const float* x  = (const float*)d_in[0];
    const float* Wq = (const float*)d_in[1];
    const float* bq = (const float*)d_in[2];
    const float* Wk = (const float*)d_in[3];
    const float* bk = (const float*)d_in[4];
    const float* Wv = (const float*)d_in[5];
    const float* bv = (const float*)d_in[6];
    const float* Wo = (const float*)d_in[7];
    const float* bo = (const float*)d_in[8];

    float* out   = (float*)d_out;
    float* k_out = out + (size_t)M_TOT * DIM;
    float* v_out = out + (size_t)2 * M_TOT * DIM;

    cudaFuncSetAttribute(qkv_gemm_kernel,
                         cudaFuncAttributeMaxDynamicSharedMemorySize, GEMM_SMEM);
    cudaFuncSetAttribute(oproj_gemm_kernel,
                         cudaFuncAttributeMaxDynamicSharedMemorySize, GEMM_SMEM);
    cudaFuncSetAttribute(attn_tc_kernel,
                         cudaFuncAttributeMaxDynamicSharedMemorySize, ATTN_SMEM);

    // Pre-split x, weights; gather biases
    split_x_kernel<<<M_TOT * DIM / 4 / 256, 256>>>(x);
    {
        dim3 wg(DD / 4 / 256, 4);
        split_w_kernel<<<wg, 256>>>(Wq, Wk, Wv, Wo);
    }
    copy_bias_kernel<<<3 * DIM / 256, 256>>>(bq, bk, bv);

    // Fused QKV projection
    dim3 qkvg(24, M_TOT / 128);           // (24, 32)
    qkv_gemm_kernel<<<qkvg, 256, GEMM_SMEM>>>(k_out, v_out);

    // Causal flash attention
    dim3 agrid(T_ / 64, NH, B_);          // (32, 16, 2)
    attn_tc_kernel<<<agrid, 128, ATTN_SMEM>>>(nullptr);

    // Output projection
    dim3 og(DIM / 128, M_TOT / 128);      // (8, 32)
    oproj_gemm_kernel<<<og, 256, GEMM_SMEM>>>(bo, out);
}

// round 8
// speedup vs baseline: 1.2993x; 1.2141x over previous
#include <cuda_runtime.h>
#include <cuda_bf16.h>
#include <cuda_fp16.h>
#include <cstdint>
#include <math.h>

// Problem constants
#define DIM 1024
#define NH  16
#define HD  64
#define B_  2
#define T_  2048
#define M_TOT (B_ * T_)          // 4096
#define DD   ((size_t)DIM * DIM)

// ---------------------------------------------------------------------------
// Device scratch (no allocation allowed)
// ---------------------------------------------------------------------------
__device__ __nv_bfloat16 g_xbh[M_TOT * DIM];   // x bf16 hi (Q,K proj)
__device__ __nv_bfloat16 g_xbl[M_TOT * DIM];   // x bf16 lo
__device__ __half        g_xfh[M_TOT * DIM];   // (16*x) fp16 hi (V proj)
__device__ __half        g_xfl[M_TOT * DIM];   // (16*x) fp16 lo
__device__ __nv_bfloat16 g_wbh[2 * DIM * DIM]; // Wq,Wk bf16 hi
__device__ __nv_bfloat16 g_wbl[2 * DIM * DIM]; // Wq,Wk bf16 lo
__device__ __half        g_wfh[2 * DIM * DIM]; // Wv,Wo fp16 hi (lo dropped)
__device__ __nv_bfloat16 g_qhi[M_TOT * DIM];   // Q [B,H,T,Hd] bf16, x 1/8
__device__ __nv_bfloat16 g_qlo[M_TOT * DIM];
__device__ __nv_bfloat16 g_khi[M_TOT * DIM];   // K bf16 hi/lo
__device__ __nv_bfloat16 g_klo[M_TOT * DIM];
__device__ __half        g_vh16[M_TOT * DIM];  // V fp16 (single plane)
__device__ __half        g_cfh[M_TOT * DIM];   // (16*ctx) fp16 hi [B,T,DIM]
__device__ __half        g_cfl[M_TOT * DIM];   // (16*ctx) fp16 lo
__device__ float         g_bias[3 * DIM];      // bq|bk|bv

// ===========================================================================
// Helpers
// ===========================================================================
__device__ __forceinline__ uint32_t smem_to_u32(const void* p) {
    uint32_t a;
    asm("{ .reg .u64 t; cvta.to.shared.u64 t, %1; cvt.u32.u64 %0, t; }"
        : "=r"(a) : "l"(p));
    return a;
}

#define LDSM_X4(r, addr) \
    asm volatile("ldmatrix.sync.aligned.m8n8.x4.shared.b16 {%0,%1,%2,%3}, [%4];" \
        : "=r"((r)[0]), "=r"((r)[1]), "=r"((r)[2]), "=r"((r)[3]) : "r"(addr))

#define LDSM_X4_T(r, addr) \
    asm volatile("ldmatrix.sync.aligned.m8n8.x4.trans.shared.b16 {%0,%1,%2,%3}, [%4];" \
        : "=r"((r)[0]), "=r"((r)[1]), "=r"((r)[2]), "=r"((r)[3]) : "r"(addr))

#define MMA_BF16(d, a, b) \
    asm volatile("mma.sync.aligned.m16n8k16.row.col.f32.bf16.bf16.f32 " \
        "{%0,%1,%2,%3}, {%4,%5,%6,%7}, {%8,%9}, {%0,%1,%2,%3};" \
        : "+f"((d)[0]), "+f"((d)[1]), "+f"((d)[2]), "+f"((d)[3]) \
        : "r"((a)[0]), "r"((a)[1]), "r"((a)[2]), "r"((a)[3]), \
          "r"((b)[0]), "r"((b)[1]))

#define MMA_FP16(d, a, b) \
    asm volatile("mma.sync.aligned.m16n8k16.row.col.f32.f16.f16.f32 " \
        "{%0,%1,%2,%3}, {%4,%5,%6,%7}, {%8,%9}, {%0,%1,%2,%3};" \
        : "+f"((d)[0]), "+f"((d)[1]), "+f"((d)[2]), "+f"((d)[3]) \
        : "r"((a)[0]), "r"((a)[1]), "r"((a)[2]), "r"((a)[3]), \
          "r"((b)[0]), "r"((b)[1]))

#define CP_A16(dst, src) \
    asm volatile("cp.async.cg.shared.global [%0], [%1], 16;" \
        :: "r"(dst), "l"(src) : "memory")
#define CP_COMMIT() asm volatile("cp.async.commit_group;" ::: "memory")
#define CP_WAIT(N)  asm volatile("cp.async.wait_group %0;" :: "n"(N) : "memory")

__device__ __forceinline__ void split4b(float4 v, uint2& hi, uint2& lo) {
    __nv_bfloat162 h01 = __floats2bfloat162_rn(v.x, v.y);
    __nv_bfloat162 h23 = __floats2bfloat162_rn(v.z, v.w);
    __nv_bfloat162 l01 = __floats2bfloat162_rn(v.x - __bfloat162float(h01.x),
                                               v.y - __bfloat162float(h01.y));
    __nv_bfloat162 l23 = __floats2bfloat162_rn(v.z - __bfloat162float(h23.x),
                                               v.w - __bfloat162float(h23.y));
    hi = make_uint2(*reinterpret_cast<uint32_t*>(&h01),
                    *reinterpret_cast<uint32_t*>(&h23));
    lo = make_uint2(*reinterpret_cast<uint32_t*>(&l01),
                    *reinterpret_cast<uint32_t*>(&l23));
}

__device__ __forceinline__ void split4h(float4 v, uint2& hi, uint2& lo) {
    __half2 h01 = __floats2half2_rn(v.x, v.y);
    __half2 h23 = __floats2half2_rn(v.z, v.w);
    float2 f01 = __half22float2(h01);
    float2 f23 = __half22float2(h23);
    __half2 l01 = __floats2half2_rn(v.x - f01.x, v.y - f01.y);
    __half2 l23 = __floats2half2_rn(v.z - f23.x, v.w - f23.y);
    hi = make_uint2(*reinterpret_cast<uint32_t*>(&h01),
                    *reinterpret_cast<uint32_t*>(&h23));
    lo = make_uint2(*reinterpret_cast<uint32_t*>(&l01),
                    *reinterpret_cast<uint32_t*>(&l23));
}

__device__ __forceinline__ void store_pair_b(
    __nv_bfloat16* hi, __nv_bfloat16* lo, size_t o, float v0, float v1)
{
    __nv_bfloat162 h = __floats2bfloat162_rn(v0, v1);
    __nv_bfloat162 l = __floats2bfloat162_rn(v0 - __bfloat162float(h.x),
                                             v1 - __bfloat162float(h.y));
    *reinterpret_cast<__nv_bfloat162*>(hi + o) = h;
    *reinterpret_cast<__nv_bfloat162*>(lo + o) = l;
}

__device__ __forceinline__ void store_pair_h(
    __half* hi, __half* lo, size_t o, float v0, float v1)
{
    __half2 h = __floats2half2_rn(v0, v1);
    float2 f = __half22float2(h);
    __half2 l = __floats2half2_rn(v0 - f.x, v1 - f.y);
    *reinterpret_cast<__half2*>(hi + o) = h;
    *reinterpret_cast<__half2*>(lo + o) = l;
}

// ===========================================================================
// Pre-split kernels
// ===========================================================================
__global__ void __launch_bounds__(256) split_x_kernel(const float* __restrict__ x)
{
    const int i = blockIdx.x * 256 + threadIdx.x;
    float4 v = reinterpret_cast<const float4*>(x)[i];
    uint2 h, l;
    split4b(v, h, l);
    reinterpret_cast<uint2*>(g_xbh)[i] = h;
    reinterpret_cast<uint2*>(g_xbl)[i] = l;
    float4 v16;
    v16.x = v.x * 16.0f; v16.y = v.y * 16.0f;
    v16.z = v.z * 16.0f; v16.w = v.w * 16.0f;
    split4h(v16, h, l);
    reinterpret_cast<uint2*>(g_xfh)[i] = h;
    reinterpret_cast<uint2*>(g_xfl)[i] = l;
}

__global__ void __launch_bounds__(256) split_w_kernel(
    const float* __restrict__ w0, const float* __restrict__ w1,
    const float* __restrict__ w2, const float* __restrict__ w3)
{
    const int y = blockIdx.y;
    const int i = blockIdx.x * 256 + threadIdx.x;
    if (y < 2) {   // Wq, Wk -> bf16 hi/lo
        const float* src = (y == 0) ? w0 : w1;
        float4 v = reinterpret_cast<const float4*>(src)[i];
        uint2 h, l;
        split4b(v, h, l);
        reinterpret_cast<uint2*>(g_wbh + (size_t)y * DD)[i] = h;
        reinterpret_cast<uint2*>(g_wbl + (size_t)y * DD)[i] = l;
    } else {       // Wv, Wo -> fp16 hi only
        const float* src = (y == 2) ? w2 : w3;
        float4 v = reinterpret_cast<const float4*>(src)[i];
        __half2 h01 = __floats2half2_rn(v.x, v.y);
        __half2 h23 = __floats2half2_rn(v.z, v.w);
        uint2 h = make_uint2(*reinterpret_cast<uint32_t*>(&h01),
                             *reinterpret_cast<uint32_t*>(&h23));
        reinterpret_cast<uint2*>(g_wfh + (size_t)(y - 2) * DD)[i] = h;
    }
}

__global__ void __launch_bounds__(256) copy_bias_kernel(
    const float* __restrict__ b0, const float* __restrict__ b1,
    const float* __restrict__ b2)
{
    const int i = blockIdx.x * 256 + threadIdx.x;
    float v;
    if (i < DIM)            v = b0[i];
    else if (i < 2 * DIM)   v = b1[i - DIM];
    else                    v = b2[i - 2 * DIM];
    g_bias[i] = v;
}

// ===========================================================================
// GEMM mainloops: block 128x128, BK=64, 3-stage cp.async, 256 thr / 8 warps,
// warp tile 64x32.  3t = bf16 3-term; 2t = fp16 2-term (Ahi,Alo,Wh planes).
// ===========================================================================
#define GROW   144
#define G_T    18432                 // 128*144
#define STAGE  (4 * G_T)             // 73728 (3t uses 4 planes; 2t uses 3)
#define GEMM_SMEM (3 * STAGE)        // 221184
#define NCH 16

__device__ __forceinline__ void gemm_mainloop_3t(
    const __nv_bfloat16* __restrict__ Ahi, const __nv_bfloat16* __restrict__ Alo,
    const __nv_bfloat16* __restrict__ Whi, const __nv_bfloat16* __restrict__ Wlo,
    int m0, int n0, uint32_t sb, float acc[4][4][4])
{
    const int tid  = threadIdx.x;
    const int lane = tid & 31;
    const int wid  = tid >> 5;
    const int warp_m = wid & 1;
    const int warp_n = wid >> 1;
    const int r    = lane & 7;
    const int quad = lane >> 3;
    const uint32_t a_off =
        (uint32_t)(warp_m * 64 + (quad & 1) * 8 + r) * GROW + (quad >> 1) * 16;
    const uint32_t b_off =
        (uint32_t)(warp_n * 32 + (quad >> 1) * 8 + r) * GROW + (quad & 1) * 16;

    auto ISSUE = [&](int c, int p) {
        const int k0 = c * 64;
        const uint32_t st = sb + p * STAGE;
        #pragma unroll
        for (int i = 0; i < 4; i++) {
            const int f   = i * 256 + tid;
            const int row = f >> 3, cc = f & 7;
            const size_t g = (size_t)(m0 + row) * DIM + k0 + cc * 8;
            const uint32_t d = st + (uint32_t)row * GROW + cc * 16;
            CP_A16(d,       Ahi + g);
            CP_A16(d + G_T, Alo + g);
        }
        #pragma unroll
        for (int i = 0; i < 4; i++) {
            const int f   = i * 256 + tid;
            const int row = f >> 3, cc = f & 7;
            const size_t g = (size_t)(n0 + row) * DIM + k0 + cc * 8;
            const uint32_t d = st + (uint32_t)row * GROW + cc * 16;
            CP_A16(d + 2 * G_T, Whi + g);
            CP_A16(d + 3 * G_T, Wlo + g);
        }
        CP_COMMIT();
    };

    ISSUE(0, 0);
    ISSUE(1, 1);

    for (int c = 0; c < NCH; ++c) {
        const int p = c - (c / 3) * 3;
        if (c < NCH - 1) { CP_WAIT(1); } else { CP_WAIT(0); }
        __syncthreads();

        const uint32_t st = sb + p * STAGE;
        #pragma unroll
        for (int ks = 0; ks < 4; ++ks) {
            uint32_t ah[4][4], al[4][4];
            #pragma unroll
            for (int mi = 0; mi < 4; mi++) {
                const uint32_t addr = st + a_off + mi * (16 * GROW) + ks * 32;
                LDSM_X4(ah[mi], addr);
                LDSM_X4(al[mi], addr + G_T);
            }
            uint32_t bh[4][2], bl[4][2];
            #pragma unroll
            for (int pr = 0; pr < 2; pr++) {
                const uint32_t addr = st + b_off + pr * (16 * GROW) + ks * 32;
                LDSM_X4(&bh[2 * pr][0], addr + 2 * G_T);
                LDSM_X4(&bl[2 * pr][0], addr + 3 * G_T);
            }
            #pragma unroll
            for (int mi = 0; mi < 4; mi++)
                #pragma unroll
                for (int ni = 0; ni < 4; ni++) {
                    MMA_BF16(acc[mi][ni], ah[mi], bh[ni]);
                    MMA_BF16(acc[mi][ni], al[mi], bh[ni]);
                    MMA_BF16(acc[mi][ni], ah[mi], bl[ni]);
                }
        }
        if (c + 2 < NCH) {
            const int p2 = (c + 2) - ((c + 2) / 3) * 3;
            ISSUE(c + 2, p2);
        }
    }
}

__device__ __forceinline__ void gemm_mainloop_2t(
    const __half* __restrict__ Ahi, const __half* __restrict__ Alo,
    const __half* __restrict__ Wh,
    int m0, int n0, uint32_t sb, float acc[4][4][4])
{
    const int tid  = threadIdx.x;
    const int lane = tid & 31;
    const int wid  = tid >> 5;
    const int warp_m = wid & 1;
    const int warp_n = wid >> 1;
    const int r    = lane & 7;
    const int quad = lane >> 3;
    const uint32_t a_off =
        (uint32_t)(warp_m * 64 + (quad & 1) * 8 + r) * GROW + (quad >> 1) * 16;
    const uint32_t b_off =
        (uint32_t)(warp_n * 32 + (quad >> 1) * 8 + r) * GROW + (quad & 1) * 16;

    auto ISSUE = [&](int c, int p) {
        const int k0 = c * 64;
        const uint32_t st = sb + p * STAGE;
        #pragma unroll
        for (int i = 0; i < 4; i++) {
            const int f   = i * 256 + tid;
            const int row = f >> 3, cc = f & 7;
            const size_t g = (size_t)(m0 + row) * DIM + k0 + cc * 8;
            const uint32_t d = st + (uint32_t)row * GROW + cc * 16;
            CP_A16(d,       Ahi + g);
            CP_A16(d + G_T, Alo + g);
        }
        #pragma unroll
        for (int i = 0; i < 4; i++) {
            const int f   = i * 256 + tid;
            const int row = f >> 3, cc = f & 7;
            const size_t g = (size_t)(n0 + row) * DIM + k0 + cc * 8;
            const uint32_t d = st + (uint32_t)row * GROW + cc * 16;
            CP_A16(d + 2 * G_T, Wh + g);
        }
        CP_COMMIT();
    };

    ISSUE(0, 0);
    ISSUE(1, 1);

    for (int c = 0; c < NCH; ++c) {
        const int p = c - (c / 3) * 3;
        if (c < NCH - 1) { CP_WAIT(1); } else { CP_WAIT(0); }
        __syncthreads();

        const uint32_t st = sb + p * STAGE;
        #pragma unroll
        for (int ks = 0; ks < 4; ++ks) {
            uint32_t ah[4][4], al[4][4];
            #pragma unroll
            for (int mi = 0; mi < 4; mi++) {
                const uint32_t addr = st + a_off + mi * (16 * GROW) + ks * 32;
                LDSM_X4(ah[mi], addr);
                LDSM_X4(al[mi], addr + G_T);
            }
            uint32_t bh[4][2];
            #pragma unroll
            for (int pr = 0; pr < 2; pr++) {
                const uint32_t addr = st + b_off + pr * (16 * GROW) + ks * 32;
                LDSM_X4(&bh[2 * pr][0], addr + 2 * G_T);
            }
            #pragma unroll
            for (int mi = 0; mi < 4; mi++)
                #pragma unroll
                for (int ni = 0; ni < 4; ni++) {
                    MMA_FP16(acc[mi][ni], ah[mi], bh[ni]);
                    MMA_FP16(acc[mi][ni], al[mi], bh[ni]);
                }
        }
        if (c + 2 < NCH) {
            const int p2 = (c + 2) - ((c + 2) / 3) * 3;
            ISSUE(c + 2, p2);
        }
    }
}

// Fused QKV projection: grid (24, 32). id = blockIdx.x>>3 selects Q/K/V.
__global__ void __launch_bounds__(256, 1) qkv_gemm_kernel(
    float* __restrict__ k_out, float* __restrict__ v_out)
{
    extern __shared__ char smem[];
    const uint32_t sb = smem_to_u32(smem);
    const int nb = blockIdx.x;
    const int id = nb >> 3;
    const int n0 = (nb & 7) * 128;
    const int m0 = blockIdx.y * 128;

    float acc[4][4][4];
    #pragma unroll
    for (int mi = 0; mi < 4; mi++)
        #pragma unroll
        for (int ni = 0; ni < 4; ni++)
            #pragma unroll
            for (int j = 0; j < 4; j++) acc[mi][ni][j] = 0.0f;

    if (id < 2) {
        gemm_mainloop_3t(g_xbh, g_xbl, g_wbh + (size_t)id * DD,
                         g_wbl + (size_t)id * DD, m0, n0, sb, acc);
    } else {
        gemm_mainloop_2t(g_xfh, g_xfl, g_wfh, m0, n0, sb, acc);  // V: x*16
    }

    const int lane = threadIdx.x & 31;
    const int wid  = threadIdx.x >> 5;
    const int warp_m = wid & 1;
    const int warp_n = wid >> 1;
    const int gid  = lane >> 2;
    const int tid4 = lane & 3;

    #pragma unroll
    for (int mi = 0; mi < 4; mi++) {
        #pragma unroll
        for (int ni = 0; ni < 4; ni++) {
            const int n = n0 + warp_n * 32 + ni * 8 + tid4 * 2;
            const float2 bb =
                *reinterpret_cast<const float2*>(&g_bias[id * DIM + n]);
            #pragma unroll
            for (int hrow = 0; hrow < 2; hrow++) {
                const int m = m0 + warp_m * 64 + mi * 16 + gid + hrow * 8;
                float v0 = acc[mi][ni][hrow * 2 + 0];
                float v1 = acc[mi][ni][hrow * 2 + 1];
                const int b  = m >> 11;
                const int t  = m & (T_ - 1);
                const int h  = n >> 6;
                const int hd = n & (HD - 1);
                const size_t o = ((((size_t)b * NH + h) * T_) + t) * HD + hd;
                if (id == 0) {                     // Q: bf16, x 1/8
                    v0 = (v0 + bb.x) * 0.125f;
                    v1 = (v1 + bb.y) * 0.125f;
                    store_pair_b(g_qhi, g_qlo, o, v0, v1);
                } else if (id == 1) {              // K: fp32 out + bf16
                    v0 += bb.x; v1 += bb.y;
                    float2 of; of.x = v0; of.y = v1;
                    *reinterpret_cast<float2*>(&k_out[o]) = of;
                    store_pair_b(g_khi, g_klo, o, v0, v1);
                } else {                           // V: acc = 16*x*Wvh
                    v0 = v0 * 0.0625f + bb.x;
                    v1 = v1 * 0.0625f + bb.y;
                    float2 of; of.x = v0; of.y = v1;
                    *reinterpret_cast<float2*>(&v_out[o]) = of;
                    *reinterpret_cast<__half2*>(g_vh16 + o) =
                        __floats2half2_rn(v0, v1);
                }
            }
        }
    }
}

// Output projection: (16*ctx fp16 planes) @ Woh^T / 16 + bo -> fp32 out
__global__ void __launch_bounds__(256, 1) oproj_gemm_kernel(
    const float* __restrict__ bo, float* __restrict__ out)
{
    extern __shared__ char smem[];
    const uint32_t sb = smem_to_u32(smem);
    const int n0 = blockIdx.x * 128;
    const int m0 = blockIdx.y * 128;

    float acc[4][4][4];
    #pragma unroll
    for (int mi = 0; mi < 4; mi++)
        #pragma unroll
        for (int ni = 0; ni < 4; ni++)
            #pragma unroll
            for (int j = 0; j < 4; j++) acc[mi][ni][j] = 0.0f;

    gemm_mainloop_2t(g_cfh, g_cfl, g_wfh + DD, m0, n0, sb, acc);

    const int lane = threadIdx.x & 31;
    const int wid  = threadIdx.x >> 5;
    const int warp_m = wid & 1;
    const int warp_n = wid >> 1;
    const int gid  = lane >> 2;
    const int tid4 = lane & 3;

    #pragma unroll
    for (int mi = 0; mi < 4; mi++) {
        #pragma unroll
        for (int ni = 0; ni < 4; ni++) {
            const int n = n0 + warp_n * 32 + ni * 8 + tid4 * 2;
            const float2 bb = *reinterpret_cast<const float2*>(&bo[n]);
            #pragma unroll
            for (int hrow = 0; hrow < 2; hrow++) {
                const int m = m0 + warp_m * 64 + mi * 16 + gid + hrow * 8;
                float2 o;
                o.x = acc[mi][ni][hrow * 2 + 0] * 0.0625f + bb.x;
                o.y = acc[mi][ni][hrow * 2 + 1] * 0.0625f + bb.y;
                *reinterpret_cast<float2*>(&out[(size_t)m * DIM + n]) = o;
            }
        }
    }
}

// ===========================================================================
// Tensor-core causal flash attention.
// QK^T: bf16 3-term (unchanged).  P@V: fp16 2-term, P scaled x1024.
// Smem: KV stages 2 x (Khi|Klo|Vh) = 55296 | Q 18432 | P 18432 = 92160.
// Writes ctx*16 as fp16 hi/lo into g_cfh/g_cfl [B,T,DIM].
// ===========================================================================
#define KV_T   9216
#define KV_STG (3 * KV_T)              // 27648
#define OFF_Q  (2 * KV_STG)            // 55296
#define OFF_P  (OFF_Q + 2 * KV_T)      // 73728
#define ATTN_SMEM (OFF_P + 2 * KV_T)   // 92160

__global__ void __launch_bounds__(128, 2) attn_tc_kernel(
    float* __restrict__ dummy)
{
    extern __shared__ char smem[];
    const uint32_t sb = smem_to_u32(smem);
    const int tid  = threadIdx.x;
    const int lane = tid & 31;
    const int w    = tid >> 5;
    const int qt = gridDim.x - 1 - blockIdx.x;
    const int h  = blockIdx.y;
    const int b  = blockIdx.z;
    const int q0 = qt * 64;
    const int nkv = qt + 1;

    const size_t head = ((size_t)b * NH + h) * T_ * HD;

    const int r    = lane & 7;
    const int quad = lane >> 3;
    const int gid  = lane >> 2;
    const int tid4 = lane & 3;
    const uint32_t a_off =
        (uint32_t)((quad & 1) * 8 + r) * GROW + (quad >> 1) * 16;
    const uint32_t b_off =
        (uint32_t)((quad >> 1) * 8 + r) * GROW + (quad & 1) * 16;

    {
        #pragma unroll
        for (int i = 0; i < 4; i++) {
            const int f   = i * 128 + tid;
            const int row = f >> 3, cc = f & 7;
            const size_t g = head + (size_t)(q0 + row) * HD + cc * 8;
            const uint32_t d = sb + OFF_Q + (uint32_t)row * GROW + cc * 16;
            CP_A16(d,        g_qhi + g);
            CP_A16(d + KV_T, g_qlo + g);
        }
        CP_COMMIT();
    }
    auto ISSUE_KV = [&](int it, int p) {
        const int j0 = it * 64;
        const uint32_t st = sb + p * KV_STG;
        #pragma unroll
        for (int i = 0; i < 4; i++) {
            const int f   = i * 128 + tid;
            const int row = f >> 3, cc = f & 7;
            const size_t g = head + (size_t)(j0 + row) * HD + cc * 8;
            const uint32_t d = st + (uint32_t)row * GROW + cc * 16;
            CP_A16(d,            g_khi + g);
            CP_A16(d + KV_T,     g_klo + g);
            CP_A16(d + 2 * KV_T, g_vh16 + g);
        }
        CP_COMMIT();
    };
    ISSUE_KV(0, 0);
    if (nkv > 1) ISSUE_KV(1, 1);

    uint32_t qh[4][4], ql[4][4];
    float c_acc[8][4];
    #pragma unroll
    for (int nt = 0; nt < 8; nt++)
        #pragma unroll
        for (int j = 0; j < 4; j++) c_acc[nt][j] = 0.0f;
    float m0r = -INFINITY, m1r = -INFINITY;
    float l0r = 0.0f, l1r = 0.0f;

    const int row0 = w * 16 + gid;
    const int row1 = row0 + 8;

    for (int it = 0; it < nkv; ++it) {
        const int p = it & 1;
        if (it < nkv - 1) { CP_WAIT(1); } else { CP_WAIT(0); }
        __syncthreads();

        if (it == 0) {
            #pragma unroll
            for (int ks = 0; ks < 4; ks++) {
                const uint32_t addr =
                    sb + OFF_Q + (uint32_t)(w * 16) * GROW + a_off + ks * 32;
                LDSM_X4(qh[ks], addr);
                LDSM_X4(ql[ks], addr + KV_T);
            }
        }

        const uint32_t kst = sb + p * KV_STG;

        // ---- S = Q @ K^T (bf16 3-term) ----
        float s[8][4];
        #pragma unroll
        for (int nt = 0; nt < 8; nt++)
            #pragma unroll
            for (int j = 0; j < 4; j++) s[nt][j] = 0.0f;

        #pragma unroll
        for (int ks = 0; ks < 4; ++ks) {
            uint32_t kb[4][4];
            #pragma unroll
            for (int p2 = 0; p2 < 4; p2++)
                LDSM_X4(kb[p2], kst + (uint32_t)(p2 * 16) * GROW + b_off + ks * 32);
            #pragma unroll
            for (int p2 = 0; p2 < 4; p2++) {
                MMA_BF16(s[2 * p2 + 0], qh[ks], &kb[p2][0]);
                MMA_BF16(s[2 * p2 + 1], qh[ks], &kb[p2][2]);
                MMA_BF16(s[2 * p2 + 0], ql[ks], &kb[p2][0]);
                MMA_BF16(s[2 * p2 + 1], ql[ks], &kb[p2][2]);
            }
            #pragma unroll
            for (int p2 = 0; p2 < 4; p2++)
                LDSM_X4(kb[p2], kst + KV_T + (uint32_t)(p2 * 16) * GROW
                                + b_off + ks * 32);
            #pragma unroll
            for (int p2 = 0; p2 < 4; p2++) {
                MMA_BF16(s[2 * p2 + 0], qh[ks], &kb[p2][0]);
                MMA_BF16(s[2 * p2 + 1], qh[ks], &kb[p2][2]);
            }
        }

        if (it == qt) {
            #pragma unroll
            for (int nt = 0; nt < 8; nt++) {
                const int c0 = nt * 8 + tid4 * 2;
                if (c0     > row0) s[nt][0] = -INFINITY;
                if (c0 + 1 > row0) s[nt][1] = -INFINITY;
                if (c0     > row1) s[nt][2] = -INFINITY;
                if (c0 + 1 > row1) s[nt][3] = -INFINITY;
            }
        }

        float mt0 = -INFINITY, mt1 = -INFINITY;
        #pragma unroll
        for (int nt = 0; nt < 8; nt++) {
            mt0 = fmaxf(mt0, fmaxf(s[nt][0], s[nt][1]));
            mt1 = fmaxf(mt1, fmaxf(s[nt][2], s[nt][3]));
        }
        mt0 = fmaxf(mt0, __shfl_xor_sync(0xffffffffu, mt0, 1));
        mt0 = fmaxf(mt0, __shfl_xor_sync(0xffffffffu, mt0, 2));
        mt1 = fmaxf(mt1, __shfl_xor_sync(0xffffffffu, mt1, 1));
        mt1 = fmaxf(mt1, __shfl_xor_sync(0xffffffffu, mt1, 2));

        const float mn0 = fmaxf(m0r, mt0);
        const float mn1 = fmaxf(m1r, mt1);
        const float sc0 = __expf(m0r - mn0);
        const float sc1 = __expf(m1r - mn1);
        m0r = mn0; m1r = mn1;

        float ls0 = 0.0f, ls1 = 0.0f;
        #pragma unroll
        for (int nt = 0; nt < 8; nt++) {
            s[nt][0] = __expf(s[nt][0] - mn0);
            s[nt][1] = __expf(s[nt][1] - mn0);
            s[nt][2] = __expf(s[nt][2] - mn1);
            s[nt][3] = __expf(s[nt][3] - mn1);
            ls0 += s[nt][0] + s[nt][1];
            ls1 += s[nt][2] + s[nt][3];
        }
        ls0 += __shfl_xor_sync(0xffffffffu, ls0, 1);
        ls0 += __shfl_xor_sync(0xffffffffu, ls0, 2);
        ls1 += __shfl_xor_sync(0xffffffffu, ls1, 1);
        ls1 += __shfl_xor_sync(0xffffffffu, ls1, 2);
        l0r = l0r * sc0 + ls0;
        l1r = l1r * sc1 + ls1;

        #pragma unroll
        for (int nt = 0; nt < 8; nt++) {
            c_acc[nt][0] *= sc0; c_acc[nt][1] *= sc0;
            c_acc[nt][2] *= sc1; c_acc[nt][3] *= sc1;
        }

        // ---- write P*1024 (fp16 split) ----
        #pragma unroll
        for (int nt = 0; nt < 8; nt++) {
            const float p0 = s[nt][0] * 1024.0f, p1 = s[nt][1] * 1024.0f;
            const float p2f = s[nt][2] * 1024.0f, p3 = s[nt][3] * 1024.0f;
            __half2 h01 = __floats2half2_rn(p0, p1);
            float2 f01 = __half22float2(h01);
            __half2 l01 = __floats2half2_rn(p0 - f01.x, p1 - f01.y);
            __half2 h23 = __floats2half2_rn(p2f, p3);
            float2 f23 = __half22float2(h23);
            __half2 l23 = __floats2half2_rn(p2f - f23.x, p3 - f23.y);
            const uint32_t c0 = (uint32_t)(nt * 16 + tid4 * 4);
            char* pp0 = smem + OFF_P + (uint32_t)row0 * GROW + c0;
            char* pp1 = smem + OFF_P + (uint32_t)row1 * GROW + c0;
            *reinterpret_cast<uint32_t*>(pp0)        = *reinterpret_cast<uint32_t*>(&h01);
            *reinterpret_cast<uint32_t*>(pp0 + KV_T) = *reinterpret_cast<uint32_t*>(&l01);
            *reinterpret_cast<uint32_t*>(pp1)        = *reinterpret_cast<uint32_t*>(&h23);
            *reinterpret_cast<uint32_t*>(pp1 + KV_T) = *reinterpret_cast<uint32_t*>(&l23);
        }
        __syncwarp();

        // ---- ctx += P' @ Vh (fp16 2-term) ----
        #pragma unroll
        for (int kk = 0; kk < 4; ++kk) {
            uint32_t ph[4], pl[4];
            const uint32_t paddr =
                sb + OFF_P + (uint32_t)(w * 16) * GROW + a_off + kk * 32;
            LDSM_X4(ph, paddr);
            LDSM_X4(pl, paddr + KV_T);

            uint32_t vb[4][4];
            #pragma unroll
            for (int nt2 = 0; nt2 < 4; nt2++)
                LDSM_X4_T(vb[nt2], kst + 2 * KV_T
                          + (uint32_t)(kk * 16) * GROW + a_off + nt2 * 32);
            #pragma unroll
            for (int nt2 = 0; nt2 < 4; nt2++) {
                MMA_FP16(c_acc[2 * nt2 + 0], ph, &vb[nt2][0]);
                MMA_FP16(c_acc[2 * nt2 + 1], ph, &vb[nt2][2]);
                MMA_FP16(c_acc[2 * nt2 + 0], pl, &vb[nt2][0]);
                MMA_FP16(c_acc[2 * nt2 + 1], pl, &vb[nt2][2]);
            }
        }
        __syncthreads();
        if (it + 2 < nkv) ISSUE_KV(it + 2, p);
    }

    // ---- epilogue: ctx*16 -> fp16 hi/lo planes [B,T,DIM] ----
    // c_acc = 1024 * sum(p*vh); ctx*16 = c_acc * 16/(1024*l)
    const float inv0 = 0.015625f / l0r;   // 16/1024
    const float inv1 = 0.015625f / l1r;
    const int qr0 = q0 + row0;
    const int qr1 = q0 + row1;
    #pragma unroll
    for (int nt = 0; nt < 8; nt++) {
        const int hd = nt * 8 + tid4 * 2;
        const size_t o0 = ((size_t)b * T_ + qr0) * DIM + h * HD + hd;
        const size_t o1 = ((size_t)b * T_ + qr1) * DIM + h * HD + hd;
        store_pair_h(g_cfh, g_cfl, o0, c_acc[nt][0] * inv0, c_acc[nt][1] * inv0);
        store_pair_h(g_cfh, g_cfl, o1, c_acc[nt][2] * inv1, c_acc[nt][3] * inv1);
    }
    (void)dummy;
}

// ---------------------------------------------------------------------------
// kernel_launch
// ---------------------------------------------------------------------------
extern "C" void kernel_launch(void* const* d_in, const int* in_sizes, int n_in,
                              void* d_out, int out_size)
{
    const float* x  = (const float*)d_in[0];
    const float* Wq = (const float*)d_in[1];
    const float* bq = (const float*)d_in[2];
    const float* Wk = (const float*)d_in[3];
    const float* bk = (const float*)d_in[4];
    const float* Wv = (const float*)d_in[5];
    const float* bv = (const float*)d_in[6];
    const float* Wo = (const float*)d_in[7];
    const float* bo = (const float*)d_in[8];

    float* out   = (float*)d_out;
    float* k_out = out + (size_t)M_TOT * DIM;
    float* v_out = out + (size_t)2 * M_TOT * DIM;

    cudaFuncSetAttribute(qkv_gemm_kernel,
                         cudaFuncAttributeMaxDynamicSharedMemorySize, GEMM_SMEM);
    cudaFuncSetAttribute(oproj_gemm_kernel,
                         cudaFuncAttributeMaxDynamicSharedMemorySize, GEMM_SMEM);
    cudaFuncSetAttribute(attn_tc_kernel,
                         cudaFuncAttributeMaxDynamicSharedMemorySize, ATTN_SMEM);

    // Pre-split x, weights; gather biases
    split_x_kernel<<<M_TOT * DIM / 4 / 256, 256>>>(x);
    {
        dim3 wg(DD / 4 / 256, 4);
        split_w_kernel<<<wg, 256>>>(Wq, Wk, Wv, Wo);
    }
    copy_bias_kernel<<<3 * DIM / 256, 256>>>(bq, bk, bv);

    // Fused QKV projection
    dim3 qkvg(24, M_TOT / 128);           // (24, 32)
    qkv_gemm_kernel<<<qkvg, 256, GEMM_SMEM>>>(k_out, v_out);

    // Causal flash attention
    dim3 agrid(T_ / 64, NH, B_);          // (32, 16, 2)
    attn_tc_kernel<<<agrid, 128, ATTN_SMEM>>>(nullptr);

    // Output projection
    dim3 og(DIM / 128, M_TOT / 128);      // (8, 32)
    oproj_gemm_kernel<<<og, 256, GEMM_SMEM>>>(bo, out);
}

// round 9
// speedup vs baseline: 1.5396x; 1.1850x over previous
#include <cuda_runtime.h>
#include <cuda_bf16.h>
#include <cuda_fp16.h>
#include <cstdint>
#include <math.h>

// Problem constants
#define DIM 1024
#define NH  16
#define HD  64
#define B_  2
#define T_  2048
#define M_TOT (B_ * T_)          // 4096
#define DD   ((size_t)DIM * DIM)

// ---------------------------------------------------------------------------
// Device scratch (no allocation allowed).  All MMA operands are fp16 planes.
// ---------------------------------------------------------------------------
__device__ __half g_xfh[M_TOT * DIM];   // (16*x) fp16 hi
__device__ __half g_xfl[M_TOT * DIM];   // (16*x) fp16 lo
__device__ __half g_wfh[4 * DIM * DIM]; // Wq,Wk,Wv,Wo fp16 hi
__device__ __half g_qh[M_TOT * DIM];    // (4*q)  [B,H,T,Hd] hi
__device__ __half g_ql[M_TOT * DIM];    // (4*q)  lo
__device__ __half g_kh[M_TOT * DIM];    // (16*k) single plane
__device__ __half g_vh16[M_TOT * DIM];  // V fp16 natural scale
__device__ __half g_cfh[M_TOT * DIM];   // (16*ctx) hi [B,T,DIM]
__device__ __half g_cfl[M_TOT * DIM];   // (16*ctx) lo
__device__ float  g_bias[3 * DIM];      // bq|bk|bv

// ===========================================================================
// Helpers
// ===========================================================================
__device__ __forceinline__ uint32_t smem_to_u32(const void* p) {
    uint32_t a;
    asm("{ .reg .u64 t; cvta.to.shared.u64 t, %1; cvt.u32.u64 %0, t; }"
        : "=r"(a) : "l"(p));
    return a;
}

#define LDSM_X4(r, addr) \
    asm volatile("ldmatrix.sync.aligned.m8n8.x4.shared.b16 {%0,%1,%2,%3}, [%4];" \
        : "=r"((r)[0]), "=r"((r)[1]), "=r"((r)[2]), "=r"((r)[3]) : "r"(addr))

#define LDSM_X4_T(r, addr) \
    asm volatile("ldmatrix.sync.aligned.m8n8.x4.trans.shared.b16 {%0,%1,%2,%3}, [%4];" \
        : "=r"((r)[0]), "=r"((r)[1]), "=r"((r)[2]), "=r"((r)[3]) : "r"(addr))

#define MMA_FP16(d, a, b) \
    asm volatile("mma.sync.aligned.m16n8k16.row.col.f32.f16.f16.f32 " \
        "{%0,%1,%2,%3}, {%4,%5,%6,%7}, {%8,%9}, {%0,%1,%2,%3};" \
        : "+f"((d)[0]), "+f"((d)[1]), "+f"((d)[2]), "+f"((d)[3]) \
        : "r"((a)[0]), "r"((a)[1]), "r"((a)[2]), "r"((a)[3]), \
          "r"((b)[0]), "r"((b)[1]))

#define CP_A16(dst, src) \
    asm volatile("cp.async.cg.shared.global [%0], [%1], 16;" \
        :: "r"(dst), "l"(src) : "memory")
#define CP_COMMIT() asm volatile("cp.async.commit_group;" ::: "memory")
#define CP_WAIT(N)  asm volatile("cp.async.wait_group %0;" :: "n"(N) : "memory")

__device__ __forceinline__ void split4h(float4 v, uint2& hi, uint2& lo) {
    __half2 h01 = __floats2half2_rn(v.x, v.y);
    __half2 h23 = __floats2half2_rn(v.z, v.w);
    float2 f01 = __half22float2(h01);
    float2 f23 = __half22float2(h23);
    __half2 l01 = __floats2half2_rn(v.x - f01.x, v.y - f01.y);
    __half2 l23 = __floats2half2_rn(v.z - f23.x, v.w - f23.y);
    hi = make_uint2(*reinterpret_cast<uint32_t*>(&h01),
                    *reinterpret_cast<uint32_t*>(&h23));
    lo = make_uint2(*reinterpret_cast<uint32_t*>(&l01),
                    *reinterpret_cast<uint32_t*>(&l23));
}

__device__ __forceinline__ void store_pair_h(
    __half* hi, __half* lo, size_t o, float v0, float v1)
{
    __half2 h = __floats2half2_rn(v0, v1);
    float2 f = __half22float2(h);
    __half2 l = __floats2half2_rn(v0 - f.x, v1 - f.y);
    *reinterpret_cast<__half2*>(hi + o) = h;
    *reinterpret_cast<__half2*>(lo + o) = l;
}

// ===========================================================================
// Pre-split kernels
// ===========================================================================
__global__ void __launch_bounds__(256) split_x_kernel(const float* __restrict__ x)
{
    const int i = blockIdx.x * 256 + threadIdx.x;
    float4 v = reinterpret_cast<const float4*>(x)[i];
    float4 v16;
    v16.x = v.x * 16.0f; v16.y = v.y * 16.0f;
    v16.z = v.z * 16.0f; v16.w = v.w * 16.0f;
    uint2 h, l;
    split4h(v16, h, l);
    reinterpret_cast<uint2*>(g_xfh)[i] = h;
    reinterpret_cast<uint2*>(g_xfl)[i] = l;
}

__global__ void __launch_bounds__(256) split_w_kernel(
    const float* __restrict__ w0, const float* __restrict__ w1,
    const float* __restrict__ w2, const float* __restrict__ w3)
{
    const int y = blockIdx.y;
    const float* src = (y == 0) ? w0 : (y == 1) ? w1 : (y == 2) ? w2 : w3;
    const int i = blockIdx.x * 256 + threadIdx.x;
    float4 v = reinterpret_cast<const float4*>(src)[i];
    __half2 h01 = __floats2half2_rn(v.x, v.y);
    __half2 h23 = __floats2half2_rn(v.z, v.w);
    uint2 h = make_uint2(*reinterpret_cast<uint32_t*>(&h01),
                         *reinterpret_cast<uint32_t*>(&h23));
    reinterpret_cast<uint2*>(g_wfh + (size_t)y * DD)[i] = h;
}

__global__ void __launch_bounds__(256) copy_bias_kernel(
    const float* __restrict__ b0, const float* __restrict__ b1,
    const float* __restrict__ b2)
{
    const int i = blockIdx.x * 256 + threadIdx.x;
    float v;
    if (i < DIM)            v = b0[i];
    else if (i < 2 * DIM)   v = b1[i - DIM];
    else                    v = b2[i - 2 * DIM];
    g_bias[i] = v;
}

// ===========================================================================
// GEMM mainloop: block 128x128, BK=64, 3-stage cp.async, 256 thr / 8 warps,
// warp tile 64x32.  fp16 2-term: acc = (Ahi + Alo) @ Wh^T.
// Stage = Ahi | Alo | Wh  (3 x 18432 = 55296 B); 3 stages = 165888 B.
// ===========================================================================
#define GROW   144
#define G_T    18432
#define STAGE  (3 * G_T)             // 55296
#define GEMM_SMEM (3 * STAGE)        // 165888
#define NCH 16

__device__ __forceinline__ void gemm_mainloop_2t(
    const __half* __restrict__ Ahi, const __half* __restrict__ Alo,
    const __half* __restrict__ Wh,
    int m0, int n0, uint32_t sb, float acc[4][4][4])
{
    const int tid  = threadIdx.x;
    const int lane = tid & 31;
    const int wid  = tid >> 5;
    const int warp_m = wid & 1;
    const int warp_n = wid >> 1;
    const int r    = lane & 7;
    const int quad = lane >> 3;
    const uint32_t a_off =
        (uint32_t)(warp_m * 64 + (quad & 1) * 8 + r) * GROW + (quad >> 1) * 16;
    const uint32_t b_off =
        (uint32_t)(warp_n * 32 + (quad >> 1) * 8 + r) * GROW + (quad & 1) * 16;

    auto ISSUE = [&](int c, int p) {
        const int k0 = c * 64;
        const uint32_t st = sb + p * STAGE;
        #pragma unroll
        for (int i = 0; i < 4; i++) {
            const int f   = i * 256 + tid;
            const int row = f >> 3, cc = f & 7;
            const size_t g = (size_t)(m0 + row) * DIM + k0 + cc * 8;
            const uint32_t d = st + (uint32_t)row * GROW + cc * 16;
            CP_A16(d,       Ahi + g);
            CP_A16(d + G_T, Alo + g);
        }
        #pragma unroll
        for (int i = 0; i < 4; i++) {
            const int f   = i * 256 + tid;
            const int row = f >> 3, cc = f & 7;
            const size_t g = (size_t)(n0 + row) * DIM + k0 + cc * 8;
            const uint32_t d = st + (uint32_t)row * GROW + cc * 16;
            CP_A16(d + 2 * G_T, Wh + g);
        }
        CP_COMMIT();
    };

    ISSUE(0, 0);
    ISSUE(1, 1);

    for (int c = 0; c < NCH; ++c) {
        const int p = c - (c / 3) * 3;
        if (c < NCH - 1) { CP_WAIT(1); } else { CP_WAIT(0); }
        __syncthreads();

        const uint32_t st = sb + p * STAGE;
        #pragma unroll
        for (int ks = 0; ks < 4; ++ks) {
            uint32_t ah[4][4], al[4][4];
            #pragma unroll
            for (int mi = 0; mi < 4; mi++) {
                const uint32_t addr = st + a_off + mi * (16 * GROW) + ks * 32;
                LDSM_X4(ah[mi], addr);
                LDSM_X4(al[mi], addr + G_T);
            }
            uint32_t bh[4][2];
            #pragma unroll
            for (int pr = 0; pr < 2; pr++) {
                const uint32_t addr = st + b_off + pr * (16 * GROW) + ks * 32;
                LDSM_X4(&bh[2 * pr][0], addr + 2 * G_T);
            }
            #pragma unroll
            for (int mi = 0; mi < 4; mi++)
                #pragma unroll
                for (int ni = 0; ni < 4; ni++) {
                    MMA_FP16(acc[mi][ni], ah[mi], bh[ni]);
                    MMA_FP16(acc[mi][ni], al[mi], bh[ni]);
                }
        }
        if (c + 2 < NCH) {
            const int p2 = (c + 2) - ((c + 2) / 3) * 3;
            ISSUE(c + 2, p2);
        }
    }
}

// Fused QKV projection: grid (24, 32). id = blockIdx.x>>3 selects Q/K/V.
// acc = (16*x) @ W^T  ->  val = acc/16 + bias.
__global__ void __launch_bounds__(256, 1) qkv_gemm_kernel(
    float* __restrict__ k_out, float* __restrict__ v_out)
{
    extern __shared__ char smem[];
    const uint32_t sb = smem_to_u32(smem);
    const int nb = blockIdx.x;
    const int id = nb >> 3;
    const int n0 = (nb & 7) * 128;
    const int m0 = blockIdx.y * 128;

    float acc[4][4][4];
    #pragma unroll
    for (int mi = 0; mi < 4; mi++)
        #pragma unroll
        for (int ni = 0; ni < 4; ni++)
            #pragma unroll
            for (int j = 0; j < 4; j++) acc[mi][ni][j] = 0.0f;

    gemm_mainloop_2t(g_xfh, g_xfl, g_wfh + (size_t)id * DD, m0, n0, sb, acc);

    const int lane = threadIdx.x & 31;
    const int wid  = threadIdx.x >> 5;
    const int warp_m = wid & 1;
    const int warp_n = wid >> 1;
    const int gid  = lane >> 2;
    const int tid4 = lane & 3;

    #pragma unroll
    for (int mi = 0; mi < 4; mi++) {
        #pragma unroll
        for (int ni = 0; ni < 4; ni++) {
            const int n = n0 + warp_n * 32 + ni * 8 + tid4 * 2;
            const float2 bb =
                *reinterpret_cast<const float2*>(&g_bias[id * DIM + n]);
            #pragma unroll
            for (int hrow = 0; hrow < 2; hrow++) {
                const int m = m0 + warp_m * 64 + mi * 16 + gid + hrow * 8;
                const float v0 = acc[mi][ni][hrow * 2 + 0] * 0.0625f + bb.x;
                const float v1 = acc[mi][ni][hrow * 2 + 1] * 0.0625f + bb.y;
                const int b  = m >> 11;
                const int t  = m & (T_ - 1);
                const int h  = n >> 6;
                const int hd = n & (HD - 1);
                const size_t o = ((((size_t)b * NH + h) * T_) + t) * HD + hd;
                if (id == 0) {                     // Q: store 4*q (2 planes)
                    store_pair_h(g_qh, g_ql, o, v0 * 4.0f, v1 * 4.0f);
                } else if (id == 1) {              // K: fp32 out + 16*k plane
                    float2 of; of.x = v0; of.y = v1;
                    *reinterpret_cast<float2*>(&k_out[o]) = of;
                    *reinterpret_cast<__half2*>(g_kh + o) =
                        __floats2half2_rn(v0 * 16.0f, v1 * 16.0f);
                } else {                           // V: fp32 out + fp16 plane
                    float2 of; of.x = v0; of.y = v1;
                    *reinterpret_cast<float2*>(&v_out[o]) = of;
                    *reinterpret_cast<__half2*>(g_vh16 + o) =
                        __floats2half2_rn(v0, v1);
                }
            }
        }
    }
}

// Output projection: (16*ctx fp16 planes) @ Woh^T / 16 + bo -> fp32 out
__global__ void __launch_bounds__(256, 1) oproj_gemm_kernel(
    const float* __restrict__ bo, float* __restrict__ out)
{
    extern __shared__ char smem[];
    const uint32_t sb = smem_to_u32(smem);
    const int n0 = blockIdx.x * 128;
    const int m0 = blockIdx.y * 128;

    float acc[4][4][4];
    #pragma unroll
    for (int mi = 0; mi < 4; mi++)
        #pragma unroll
        for (int ni = 0; ni < 4; ni++)
            #pragma unroll
            for (int j = 0; j < 4; j++) acc[mi][ni][j] = 0.0f;

    gemm_mainloop_2t(g_cfh, g_cfl, g_wfh + 3 * DD, m0, n0, sb, acc);

    const int lane = threadIdx.x & 31;
    const int wid  = threadIdx.x >> 5;
    const int warp_m = wid & 1;
    const int warp_n = wid >> 1;
    const int gid  = lane >> 2;
    const int tid4 = lane & 3;

    #pragma unroll
    for (int mi = 0; mi < 4; mi++) {
        #pragma unroll
        for (int ni = 0; ni < 4; ni++) {
            const int n = n0 + warp_n * 32 + ni * 8 + tid4 * 2;
            const float2 bb = *reinterpret_cast<const float2*>(&bo[n]);
            #pragma unroll
            for (int hrow = 0; hrow < 2; hrow++) {
                const int m = m0 + warp_m * 64 + mi * 16 + gid + hrow * 8;
                float2 o;
                o.x = acc[mi][ni][hrow * 2 + 0] * 0.0625f + bb.x;
                o.y = acc[mi][ni][hrow * 2 + 1] * 0.0625f + bb.y;
                *reinterpret_cast<float2*>(&out[(size_t)m * DIM + n]) = o;
            }
        }
    }
}

// ===========================================================================
// Tensor-core causal flash attention, all fp16 2-term.
// S:  acc = (4q_hi + 4q_lo) @ (16k)^T ;  s = acc / 512.
// PV: acc = (1024p hi+lo) @ v ;  ctx*16 = acc * 16 / (1024*l).
// Smem: KV 2 x (Kh|Vh) = 36864 | Q 2 planes 18432 | P 2 planes 18432 = 73728.
// ===========================================================================
#define KV_T   9216
#define KV_STG (2 * KV_T)              // 18432
#define OFF_Q  (2 * KV_STG)            // 36864
#define OFF_P  (OFF_Q + 2 * KV_T)      // 55296
#define ATTN_SMEM (OFF_P + 2 * KV_T)   // 73728

__global__ void __launch_bounds__(128, 2) attn_tc_kernel(
    float* __restrict__ dummy)
{
    extern __shared__ char smem[];
    const uint32_t sb = smem_to_u32(smem);
    const int tid  = threadIdx.x;
    const int lane = tid & 31;
    const int w    = tid >> 5;
    const int qt = gridDim.x - 1 - blockIdx.x;
    const int h  = blockIdx.y;
    const int b  = blockIdx.z;
    const int q0 = qt * 64;
    const int nkv = qt + 1;

    const size_t head = ((size_t)b * NH + h) * T_ * HD;

    const int r    = lane & 7;
    const int quad = lane >> 3;
    const int gid  = lane >> 2;
    const int tid4 = lane & 3;
    const uint32_t a_off =
        (uint32_t)((quad & 1) * 8 + r) * GROW + (quad >> 1) * 16;
    const uint32_t b_off =
        (uint32_t)((quad >> 1) * 8 + r) * GROW + (quad & 1) * 16;

    {   // Q prologue: 2 planes x 512 chunks
        #pragma unroll
        for (int i = 0; i < 4; i++) {
            const int f   = i * 128 + tid;
            const int row = f >> 3, cc = f & 7;
            const size_t g = head + (size_t)(q0 + row) * HD + cc * 8;
            const uint32_t d = sb + OFF_Q + (uint32_t)row * GROW + cc * 16;
            CP_A16(d,        g_qh + g);
            CP_A16(d + KV_T, g_ql + g);
        }
        CP_COMMIT();
    }
    auto ISSUE_KV = [&](int it, int p) {
        const int j0 = it * 64;
        const uint32_t st = sb + p * KV_STG;
        #pragma unroll
        for (int i = 0; i < 4; i++) {
            const int f   = i * 128 + tid;
            const int row = f >> 3, cc = f & 7;
            const size_t g = head + (size_t)(j0 + row) * HD + cc * 8;
            const uint32_t d = st + (uint32_t)row * GROW + cc * 16;
            CP_A16(d,        g_kh + g);
            CP_A16(d + KV_T, g_vh16 + g);
        }
        CP_COMMIT();
    };
    ISSUE_KV(0, 0);
    if (nkv > 1) ISSUE_KV(1, 1);

    uint32_t qh[4][4], ql[4][4];
    float c_acc[8][4];
    #pragma unroll
    for (int nt = 0; nt < 8; nt++)
        #pragma unroll
        for (int j = 0; j < 4; j++) c_acc[nt][j] = 0.0f;
    float m0r = -INFINITY, m1r = -INFINITY;
    float l0r = 0.0f, l1r = 0.0f;

    const int row0 = w * 16 + gid;
    const int row1 = row0 + 8;

    for (int it = 0; it < nkv; ++it) {
        const int p = it & 1;
        if (it < nkv - 1) { CP_WAIT(1); } else { CP_WAIT(0); }
        __syncthreads();

        if (it == 0) {
            #pragma unroll
            for (int ks = 0; ks < 4; ks++) {
                const uint32_t addr =
                    sb + OFF_Q + (uint32_t)(w * 16) * GROW + a_off + ks * 32;
                LDSM_X4(qh[ks], addr);
                LDSM_X4(ql[ks], addr + KV_T);
            }
        }

        const uint32_t kst = sb + p * KV_STG;

        // ---- S = Q @ K^T (fp16 2-term) ----
        float s[8][4];
        #pragma unroll
        for (int nt = 0; nt < 8; nt++)
            #pragma unroll
            for (int j = 0; j < 4; j++) s[nt][j] = 0.0f;

        #pragma unroll
        for (int ks = 0; ks < 4; ++ks) {
            uint32_t kb[4][4];
            #pragma unroll
            for (int p2 = 0; p2 < 4; p2++)
                LDSM_X4(kb[p2], kst + (uint32_t)(p2 * 16) * GROW + b_off + ks * 32);
            #pragma unroll
            for (int p2 = 0; p2 < 4; p2++) {
                MMA_FP16(s[2 * p2 + 0], qh[ks], &kb[p2][0]);
                MMA_FP16(s[2 * p2 + 1], qh[ks], &kb[p2][2]);
                MMA_FP16(s[2 * p2 + 0], ql[ks], &kb[p2][0]);
                MMA_FP16(s[2 * p2 + 1], ql[ks], &kb[p2][2]);
            }
        }

        // scale to natural scores: s = acc / 512
        #pragma unroll
        for (int nt = 0; nt < 8; nt++) {
            s[nt][0] *= 0.001953125f; s[nt][1] *= 0.001953125f;
            s[nt][2] *= 0.001953125f; s[nt][3] *= 0.001953125f;
        }

        if (it == qt) {
            #pragma unroll
            for (int nt = 0; nt < 8; nt++) {
                const int c0 = nt * 8 + tid4 * 2;
                if (c0     > row0) s[nt][0] = -INFINITY;
                if (c0 + 1 > row0) s[nt][1] = -INFINITY;
                if (c0     > row1) s[nt][2] = -INFINITY;
                if (c0 + 1 > row1) s[nt][3] = -INFINITY;
            }
        }

        float mt0 = -INFINITY, mt1 = -INFINITY;
        #pragma unroll
        for (int nt = 0; nt < 8; nt++) {
            mt0 = fmaxf(mt0, fmaxf(s[nt][0], s[nt][1]));
            mt1 = fmaxf(mt1, fmaxf(s[nt][2], s[nt][3]));
        }
        mt0 = fmaxf(mt0, __shfl_xor_sync(0xffffffffu, mt0, 1));
        mt0 = fmaxf(mt0, __shfl_xor_sync(0xffffffffu, mt0, 2));
        mt1 = fmaxf(mt1, __shfl_xor_sync(0xffffffffu, mt1, 1));
        mt1 = fmaxf(mt1, __shfl_xor_sync(0xffffffffu, mt1, 2));

        const float mn0 = fmaxf(m0r, mt0);
        const float mn1 = fmaxf(m1r, mt1);
        const float sc0 = __expf(m0r - mn0);
        const float sc1 = __expf(m1r - mn1);
        m0r = mn0; m1r = mn1;

        float ls0 = 0.0f, ls1 = 0.0f;
        #pragma unroll
        for (int nt = 0; nt < 8; nt++) {
            s[nt][0] = __expf(s[nt][0] - mn0);
            s[nt][1] = __expf(s[nt][1] - mn0);
            s[nt][2] = __expf(s[nt][2] - mn1);
            s[nt][3] = __expf(s[nt][3] - mn1);
            ls0 += s[nt][0] + s[nt][1];
            ls1 += s[nt][2] + s[nt][3];
        }
        ls0 += __shfl_xor_sync(0xffffffffu, ls0, 1);
        ls0 += __shfl_xor_sync(0xffffffffu, ls0, 2);
        ls1 += __shfl_xor_sync(0xffffffffu, ls1, 1);
        ls1 += __shfl_xor_sync(0xffffffffu, ls1, 2);
        l0r = l0r * sc0 + ls0;
        l1r = l1r * sc1 + ls1;

        #pragma unroll
        for (int nt = 0; nt < 8; nt++) {
            c_acc[nt][0] *= sc0; c_acc[nt][1] *= sc0;
            c_acc[nt][2] *= sc1; c_acc[nt][3] *= sc1;
        }

        // ---- write P*1024 (fp16 split) ----
        #pragma unroll
        for (int nt = 0; nt < 8; nt++) {
            const float p0 = s[nt][0] * 1024.0f, p1 = s[nt][1] * 1024.0f;
            const float p2f = s[nt][2] * 1024.0f, p3 = s[nt][3] * 1024.0f;
            __half2 h01 = __floats2half2_rn(p0, p1);
            float2 f01 = __half22float2(h01);
            __half2 l01 = __floats2half2_rn(p0 - f01.x, p1 - f01.y);
            __half2 h23 = __floats2half2_rn(p2f, p3);
            float2 f23 = __half22float2(h23);
            __half2 l23 = __floats2half2_rn(p2f - f23.x, p3 - f23.y);
            const uint32_t c0 = (uint32_t)(nt * 16 + tid4 * 4);
            char* pp0 = smem + OFF_P + (uint32_t)row0 * GROW + c0;
            char* pp1 = smem + OFF_P + (uint32_t)row1 * GROW + c0;
            *reinterpret_cast<uint32_t*>(pp0)        = *reinterpret_cast<uint32_t*>(&h01);
            *reinterpret_cast<uint32_t*>(pp0 + KV_T) = *reinterpret_cast<uint32_t*>(&l01);
            *reinterpret_cast<uint32_t*>(pp1)        = *reinterpret_cast<uint32_t*>(&h23);
            *reinterpret_cast<uint32_t*>(pp1 + KV_T) = *reinterpret_cast<uint32_t*>(&l23);
        }
        __syncwarp();

        // ---- ctx += P' @ Vh (fp16 2-term) ----
        #pragma unroll
        for (int kk = 0; kk < 4; ++kk) {
            uint32_t ph[4], pl[4];
            const uint32_t paddr =
                sb + OFF_P + (uint32_t)(w * 16) * GROW + a_off + kk * 32;
            LDSM_X4(ph, paddr);
            LDSM_X4(pl, paddr + KV_T);

            uint32_t vb[4][4];
            #pragma unroll
            for (int nt2 = 0; nt2 < 4; nt2++)
                LDSM_X4_T(vb[nt2], kst + KV_T
                          + (uint32_t)(kk * 16) * GROW + a_off + nt2 * 32);
            #pragma unroll
            for (int nt2 = 0; nt2 < 4; nt2++) {
                MMA_FP16(c_acc[2 * nt2 + 0], ph, &vb[nt2][0]);
                MMA_FP16(c_acc[2 * nt2 + 1], ph, &vb[nt2][2]);
                MMA_FP16(c_acc[2 * nt2 + 0], pl, &vb[nt2][0]);
                MMA_FP16(c_acc[2 * nt2 + 1], pl, &vb[nt2][2]);
            }
        }
        __syncthreads();
        if (it + 2 < nkv) ISSUE_KV(it + 2, p);
    }

    // ---- epilogue: ctx*16 -> fp16 hi/lo planes [B,T,DIM] ----
    const float inv0 = 0.015625f / l0r;   // 16/1024
    const float inv1 = 0.015625f / l1r;
    const int qr0 = q0 + row0;
    const int qr1 = q0 + row1;
    #pragma unroll
    for (int nt = 0; nt < 8; nt++) {
        const int hd = nt * 8 + tid4 * 2;
        const size_t o0 = ((size_t)b * T_ + qr0) * DIM + h * HD + hd;
        const size_t o1 = ((size_t)b * T_ + qr1) * DIM + h * HD + hd;
        store_pair_h(g_cfh, g_cfl, o0, c_acc[nt][0] * inv0, c_acc[nt][1] * inv0);
        store_pair_h(g_cfh, g_cfl, o1, c_acc[nt][2] * inv1, c_acc[nt][3] * inv1);
    }
    (void)dummy;
}

// ---------------------------------------------------------------------------
// kernel_launch
// ---------------------------------------------------------------------------
extern "C" void kernel_launch(void* const* d_in, const int* in_sizes, int n_in,
                              void* d_out, int out_size)
{
    const float* x  = (const float*)d_in[0];
    const float* Wq = (const float*)d_in[1];
    const float* bq = (const float*)d_in[2];
    const float* Wk = (const float*)d_in[3];
    const float* bk = (const float*)d_in[4];
    const float* Wv = (const float*)d_in[5];
    const float* bv = (const float*)d_in[6];
    const float* Wo = (const float*)d_in[7];
    const float* bo = (const float*)d_in[8];

    float* out   = (float*)d_out;
    float* k_out = out + (size_t)M_TOT * DIM;
    float* v_out = out + (size_t)2 * M_TOT * DIM;

    cudaFuncSetAttribute(qkv_gemm_kernel,
                         cudaFuncAttributeMaxDynamicSharedMemorySize, GEMM_SMEM);
    cudaFuncSetAttribute(oproj_gemm_kernel,
                         cudaFuncAttributeMaxDynamicSharedMemorySize, GEMM_SMEM);
    cudaFuncSetAttribute(attn_tc_kernel,
                         cudaFuncAttributeMaxDynamicSharedMemorySize, ATTN_SMEM);

    // Pre-split x, weights; gather biases
    split_x_kernel<<<M_TOT * DIM / 4 / 256, 256>>>(x);
    {
        dim3 wg(DD / 4 / 256, 4);
        split_w_kernel<<<wg, 256>>>(Wq, Wk, Wv, Wo);
    }
    copy_bias_kernel<<<3 * DIM / 256, 256>>>(bq, bk, bv);

    // Fused QKV projection
    dim3 qkvg(24, M_TOT / 128);           // (24, 32)
    qkv_gemm_kernel<<<qkvg, 256, GEMM_SMEM>>>(k_out, v_out);

    // Causal flash attention
    dim3 agrid(T_ / 64, NH, B_);          // (32, 16, 2)
    attn_tc_kernel<<<agrid, 128, ATTN_SMEM>>>(nullptr);

    // Output projection
    dim3 og(DIM / 128, M_TOT / 128);      // (8, 32)
    oproj_gemm_kernel<<<og, 256, GEMM_SMEM>>>(bo, out);
}

// round 10
// speedup vs baseline: 1.7379x; 1.1288x over previous
#include <cuda_runtime.h>
#include <cuda_bf16.h>
#include <cuda_fp16.h>
#include <cstdint>
#include <math.h>

// Problem constants
#define DIM 1024
#define NH  16
#define HD  64
#define B_  2
#define T_  2048
#define M_TOT (B_ * T_)          // 4096
#define DD   ((size_t)DIM * DIM)

// ---------------------------------------------------------------------------
// Device scratch (no allocation allowed).  All MMA operands are fp16 planes.
// ---------------------------------------------------------------------------
__device__ __half g_xfh[M_TOT * DIM];   // (16*x) fp16 hi
__device__ __half g_xfl[M_TOT * DIM];   // (16*x) fp16 lo
__device__ __half g_wfh[4 * DIM * DIM]; // Wq,Wk,Wv,Wo fp16 hi
__device__ __half g_qh[M_TOT * DIM];    // (4*q)  [B,H,T,Hd] single plane
__device__ __half g_kh[M_TOT * DIM];    // (16*k) single plane
__device__ __half g_vh16[M_TOT * DIM];  // V fp16 natural scale
__device__ __half g_cfh[M_TOT * DIM];   // (16*ctx) hi [B,T,DIM]
__device__ __half g_cfl[M_TOT * DIM];   // (16*ctx) lo
__device__ float  g_bias[3 * DIM];      // bq|bk|bv

// ===========================================================================
// Helpers
// ===========================================================================
__device__ __forceinline__ uint32_t smem_to_u32(const void* p) {
    uint32_t a;
    asm("{ .reg .u64 t; cvta.to.shared.u64 t, %1; cvt.u32.u64 %0, t; }"
        : "=r"(a) : "l"(p));
    return a;
}

#define LDSM_X4(r, addr) \
    asm volatile("ldmatrix.sync.aligned.m8n8.x4.shared.b16 {%0,%1,%2,%3}, [%4];" \
        : "=r"((r)[0]), "=r"((r)[1]), "=r"((r)[2]), "=r"((r)[3]) : "r"(addr))

#define LDSM_X4_T(r, addr) \
    asm volatile("ldmatrix.sync.aligned.m8n8.x4.trans.shared.b16 {%0,%1,%2,%3}, [%4];" \
        : "=r"((r)[0]), "=r"((r)[1]), "=r"((r)[2]), "=r"((r)[3]) : "r"(addr))

#define MMA_FP16(d, a, b) \
    asm volatile("mma.sync.aligned.m16n8k16.row.col.f32.f16.f16.f32 " \
        "{%0,%1,%2,%3}, {%4,%5,%6,%7}, {%8,%9}, {%0,%1,%2,%3};" \
        : "+f"((d)[0]), "+f"((d)[1]), "+f"((d)[2]), "+f"((d)[3]) \
        : "r"((a)[0]), "r"((a)[1]), "r"((a)[2]), "r"((a)[3]), \
          "r"((b)[0]), "r"((b)[1]))

#define CP_A16(dst, src) \
    asm volatile("cp.async.cg.shared.global [%0], [%1], 16;" \
        :: "r"(dst), "l"(src) : "memory")
#define CP_COMMIT() asm volatile("cp.async.commit_group;" ::: "memory")
#define CP_WAIT(N)  asm volatile("cp.async.wait_group %0;" :: "n"(N) : "memory")

__device__ __forceinline__ void split4h(float4 v, uint2& hi, uint2& lo) {
    __half2 h01 = __floats2half2_rn(v.x, v.y);
    __half2 h23 = __floats2half2_rn(v.z, v.w);
    float2 f01 = __half22float2(h01);
    float2 f23 = __half22float2(h23);
    __half2 l01 = __floats2half2_rn(v.x - f01.x, v.y - f01.y);
    __half2 l23 = __floats2half2_rn(v.z - f23.x, v.w - f23.y);
    hi = make_uint2(*reinterpret_cast<uint32_t*>(&h01),
                    *reinterpret_cast<uint32_t*>(&h23));
    lo = make_uint2(*reinterpret_cast<uint32_t*>(&l01),
                    *reinterpret_cast<uint32_t*>(&l23));
}

__device__ __forceinline__ void store_pair_h(
    __half* hi, __half* lo, size_t o, float v0, float v1)
{
    __half2 h = __floats2half2_rn(v0, v1);
    float2 f = __half22float2(h);
    __half2 l = __floats2half2_rn(v0 - f.x, v1 - f.y);
    *reinterpret_cast<__half2*>(hi + o) = h;
    *reinterpret_cast<__half2*>(lo + o) = l;
}

// ===========================================================================
// Pre-split kernels
// ===========================================================================
__global__ void __launch_bounds__(256) split_x_kernel(const float* __restrict__ x)
{
    const int i = blockIdx.x * 256 + threadIdx.x;
    float4 v = reinterpret_cast<const float4*>(x)[i];
    float4 v16;
    v16.x = v.x * 16.0f; v16.y = v.y * 16.0f;
    v16.z = v.z * 16.0f; v16.w = v.w * 16.0f;
    uint2 h, l;
    split4h(v16, h, l);
    reinterpret_cast<uint2*>(g_xfh)[i] = h;
    reinterpret_cast<uint2*>(g_xfl)[i] = l;
}

__global__ void __launch_bounds__(256) split_w_kernel(
    const float* __restrict__ w0, const float* __restrict__ w1,
    const float* __restrict__ w2, const float* __restrict__ w3)
{
    const int y = blockIdx.y;
    const float* src = (y == 0) ? w0 : (y == 1) ? w1 : (y == 2) ? w2 : w3;
    const int i = blockIdx.x * 256 + threadIdx.x;
    float4 v = reinterpret_cast<const float4*>(src)[i];
    __half2 h01 = __floats2half2_rn(v.x, v.y);
    __half2 h23 = __floats2half2_rn(v.z, v.w);
    uint2 h = make_uint2(*reinterpret_cast<uint32_t*>(&h01),
                         *reinterpret_cast<uint32_t*>(&h23));
    reinterpret_cast<uint2*>(g_wfh + (size_t)y * DD)[i] = h;
}

__global__ void __launch_bounds__(256) copy_bias_kernel(
    const float* __restrict__ b0, const float* __restrict__ b1,
    const float* __restrict__ b2)
{
    const int i = blockIdx.x * 256 + threadIdx.x;
    float v;
    if (i < DIM)            v = b0[i];
    else if (i < 2 * DIM)   v = b1[i - DIM];
    else                    v = b2[i - 2 * DIM];
    g_bias[i] = v;
}

// ===========================================================================
// GEMM mainloop: block 128x128, BK=64, 3-stage cp.async, 256 thr / 8 warps,
// warp tile 64x32.  fp16 2-term: acc = (Ahi + Alo) @ Wh^T.
// ===========================================================================
#define GROW   144
#define G_T    18432
#define STAGE  (3 * G_T)             // 55296
#define GEMM_SMEM (3 * STAGE)        // 165888
#define NCH 16

__device__ __forceinline__ void gemm_mainloop_2t(
    const __half* __restrict__ Ahi, const __half* __restrict__ Alo,
    const __half* __restrict__ Wh,
    int m0, int n0, uint32_t sb, float acc[4][4][4])
{
    const int tid  = threadIdx.x;
    const int lane = tid & 31;
    const int wid  = tid >> 5;
    const int warp_m = wid & 1;
    const int warp_n = wid >> 1;
    const int r    = lane & 7;
    const int quad = lane >> 3;
    const uint32_t a_off =
        (uint32_t)(warp_m * 64 + (quad & 1) * 8 + r) * GROW + (quad >> 1) * 16;
    const uint32_t b_off =
        (uint32_t)(warp_n * 32 + (quad >> 1) * 8 + r) * GROW + (quad & 1) * 16;

    auto ISSUE = [&](int c, int p) {
        const int k0 = c * 64;
        const uint32_t st = sb + p * STAGE;
        #pragma unroll
        for (int i = 0; i < 4; i++) {
            const int f   = i * 256 + tid;
            const int row = f >> 3, cc = f & 7;
            const size_t g = (size_t)(m0 + row) * DIM + k0 + cc * 8;
            const uint32_t d = st + (uint32_t)row * GROW + cc * 16;
            CP_A16(d,       Ahi + g);
            CP_A16(d + G_T, Alo + g);
        }
        #pragma unroll
        for (int i = 0; i < 4; i++) {
            const int f   = i * 256 + tid;
            const int row = f >> 3, cc = f & 7;
            const size_t g = (size_t)(n0 + row) * DIM + k0 + cc * 8;
            const uint32_t d = st + (uint32_t)row * GROW + cc * 16;
            CP_A16(d + 2 * G_T, Wh + g);
        }
        CP_COMMIT();
    };

    ISSUE(0, 0);
    ISSUE(1, 1);

    for (int c = 0; c < NCH; ++c) {
        const int p = c - (c / 3) * 3;
        if (c < NCH - 1) { CP_WAIT(1); } else { CP_WAIT(0); }
        __syncthreads();

        const uint32_t st = sb + p * STAGE;
        #pragma unroll
        for (int ks = 0; ks < 4; ++ks) {
            uint32_t ah[4][4], al[4][4];
            #pragma unroll
            for (int mi = 0; mi < 4; mi++) {
                const uint32_t addr = st + a_off + mi * (16 * GROW) + ks * 32;
                LDSM_X4(ah[mi], addr);
                LDSM_X4(al[mi], addr + G_T);
            }
            uint32_t bh[4][2];
            #pragma unroll
            for (int pr = 0; pr < 2; pr++) {
                const uint32_t addr = st + b_off + pr * (16 * GROW) + ks * 32;
                LDSM_X4(&bh[2 * pr][0], addr + 2 * G_T);
            }
            #pragma unroll
            for (int mi = 0; mi < 4; mi++)
                #pragma unroll
                for (int ni = 0; ni < 4; ni++) {
                    MMA_FP16(acc[mi][ni], ah[mi], bh[ni]);
                    MMA_FP16(acc[mi][ni], al[mi], bh[ni]);
                }
        }
        if (c + 2 < NCH) {
            const int p2 = (c + 2) - ((c + 2) / 3) * 3;
            ISSUE(c + 2, p2);
        }
    }
}

// Fused QKV projection: grid (24, 32). id = blockIdx.x>>3 selects Q/K/V.
__global__ void __launch_bounds__(256, 1) qkv_gemm_kernel(
    float* __restrict__ k_out, float* __restrict__ v_out)
{
    extern __shared__ char smem[];
    const uint32_t sb = smem_to_u32(smem);
    const int nb = blockIdx.x;
    const int id = nb >> 3;
    const int n0 = (nb & 7) * 128;
    const int m0 = blockIdx.y * 128;

    float acc[4][4][4];
    #pragma unroll
    for (int mi = 0; mi < 4; mi++)
        #pragma unroll
        for (int ni = 0; ni < 4; ni++)
            #pragma unroll
            for (int j = 0; j < 4; j++) acc[mi][ni][j] = 0.0f;

    gemm_mainloop_2t(g_xfh, g_xfl, g_wfh + (size_t)id * DD, m0, n0, sb, acc);

    const int lane = threadIdx.x & 31;
    const int wid  = threadIdx.x >> 5;
    const int warp_m = wid & 1;
    const int warp_n = wid >> 1;
    const int gid  = lane >> 2;
    const int tid4 = lane & 3;

    #pragma unroll
    for (int mi = 0; mi < 4; mi++) {
        #pragma unroll
        for (int ni = 0; ni < 4; ni++) {
            const int n = n0 + warp_n * 32 + ni * 8 + tid4 * 2;
            const float2 bb =
                *reinterpret_cast<const float2*>(&g_bias[id * DIM + n]);
            #pragma unroll
            for (int hrow = 0; hrow < 2; hrow++) {
                const int m = m0 + warp_m * 64 + mi * 16 + gid + hrow * 8;
                const float v0 = acc[mi][ni][hrow * 2 + 0] * 0.0625f + bb.x;
                const float v1 = acc[mi][ni][hrow * 2 + 1] * 0.0625f + bb.y;
                const int b  = m >> 11;
                const int t  = m & (T_ - 1);
                const int h  = n >> 6;
                const int hd = n & (HD - 1);
                const size_t o = ((((size_t)b * NH + h) * T_) + t) * HD + hd;
                if (id == 0) {                     // Q: single plane, 4*q
                    *reinterpret_cast<__half2*>(g_qh + o) =
                        __floats2half2_rn(v0 * 4.0f, v1 * 4.0f);
                } else if (id == 1) {              // K: fp32 out + 16*k plane
                    float2 of; of.x = v0; of.y = v1;
                    *reinterpret_cast<float2*>(&k_out[o]) = of;
                    *reinterpret_cast<__half2*>(g_kh + o) =
                        __floats2half2_rn(v0 * 16.0f, v1 * 16.0f);
                } else {                           // V: fp32 out + fp16 plane
                    float2 of; of.x = v0; of.y = v1;
                    *reinterpret_cast<float2*>(&v_out[o]) = of;
                    *reinterpret_cast<__half2*>(g_vh16 + o) =
                        __floats2half2_rn(v0, v1);
                }
            }
        }
    }
}

// Output projection: (16*ctx fp16 planes) @ Woh^T / 16 + bo -> fp32 out
__global__ void __launch_bounds__(256, 1) oproj_gemm_kernel(
    const float* __restrict__ bo, float* __restrict__ out)
{
    extern __shared__ char smem[];
    const uint32_t sb = smem_to_u32(smem);
    const int n0 = blockIdx.x * 128;
    const int m0 = blockIdx.y * 128;

    float acc[4][4][4];
    #pragma unroll
    for (int mi = 0; mi < 4; mi++)
        #pragma unroll
        for (int ni = 0; ni < 4; ni++)
            #pragma unroll
            for (int j = 0; j < 4; j++) acc[mi][ni][j] = 0.0f;

    gemm_mainloop_2t(g_cfh, g_cfl, g_wfh + 3 * DD, m0, n0, sb, acc);

    const int lane = threadIdx.x & 31;
    const int wid  = threadIdx.x >> 5;
    const int warp_m = wid & 1;
    const int warp_n = wid >> 1;
    const int gid  = lane >> 2;
    const int tid4 = lane & 3;

    #pragma unroll
    for (int mi = 0; mi < 4; mi++) {
        #pragma unroll
        for (int ni = 0; ni < 4; ni++) {
            const int n = n0 + warp_n * 32 + ni * 8 + tid4 * 2;
            const float2 bb = *reinterpret_cast<const float2*>(&bo[n]);
            #pragma unroll
            for (int hrow = 0; hrow < 2; hrow++) {
                const int m = m0 + warp_m * 64 + mi * 16 + gid + hrow * 8;
                float2 o;
                o.x = acc[mi][ni][hrow * 2 + 0] * 0.0625f + bb.x;
                o.y = acc[mi][ni][hrow * 2 + 1] * 0.0625f + bb.y;
                *reinterpret_cast<float2*>(&out[(size_t)m * DIM + n]) = o;
            }
        }
    }
}

// ===========================================================================
// Tensor-core causal flash attention, fp16 1-term S and PV.
// S:  acc = (4q) @ (16k)^T ;  s = acc / 512.
// PV: acc = (1024p) @ v ;  ctx*16 = acc / 64.
// Smem: KV 2 x (Kh|Vh) = 36864 | Q 9216 | P 9216 = 55296 -> up to 3 CTAs/SM.
// ===========================================================================
#define KV_T   9216
#define KV_STG (2 * KV_T)              // 18432
#define OFF_Q  (2 * KV_STG)            // 36864
#define OFF_P  (OFF_Q + KV_T)          // 46080
#define ATTN_SMEM (OFF_P + KV_T)       // 55296

__global__ void __launch_bounds__(128, 3) attn_tc_kernel(
    float* __restrict__ dummy)
{
    extern __shared__ char smem[];
    const uint32_t sb = smem_to_u32(smem);
    const int tid  = threadIdx.x;
    const int lane = tid & 31;
    const int w    = tid >> 5;
    const int qt = gridDim.x - 1 - blockIdx.x;
    const int h  = blockIdx.y;
    const int b  = blockIdx.z;
    const int q0 = qt * 64;
    const int nkv = qt + 1;

    const size_t head = ((size_t)b * NH + h) * T_ * HD;

    const int r    = lane & 7;
    const int quad = lane >> 3;
    const int gid  = lane >> 2;
    const int tid4 = lane & 3;
    const uint32_t a_off =
        (uint32_t)((quad & 1) * 8 + r) * GROW + (quad >> 1) * 16;
    const uint32_t b_off =
        (uint32_t)((quad >> 1) * 8 + r) * GROW + (quad & 1) * 16;

    {   // Q prologue: 1 plane x 512 chunks
        #pragma unroll
        for (int i = 0; i < 4; i++) {
            const int f   = i * 128 + tid;
            const int row = f >> 3, cc = f & 7;
            const size_t g = head + (size_t)(q0 + row) * HD + cc * 8;
            const uint32_t d = sb + OFF_Q + (uint32_t)row * GROW + cc * 16;
            if (i < 4) CP_A16(d, g_qh + g);
        }
        CP_COMMIT();
    }
    auto ISSUE_KV = [&](int it, int p) {
        const int j0 = it * 64;
        const uint32_t st = sb + p * KV_STG;
        #pragma unroll
        for (int i = 0; i < 4; i++) {
            const int f   = i * 128 + tid;
            const int row = f >> 3, cc = f & 7;
            const size_t g = head + (size_t)(j0 + row) * HD + cc * 8;
            const uint32_t d = st + (uint32_t)row * GROW + cc * 16;
            CP_A16(d,        g_kh + g);
            CP_A16(d + KV_T, g_vh16 + g);
        }
        CP_COMMIT();
    };
    ISSUE_KV(0, 0);
    if (nkv > 1) ISSUE_KV(1, 1);

    uint32_t qh[4][4];
    float c_acc[8][4];
    #pragma unroll
    for (int nt = 0; nt < 8; nt++)
        #pragma unroll
        for (int j = 0; j < 4; j++) c_acc[nt][j] = 0.0f;
    float m0r = -INFINITY, m1r = -INFINITY;
    float l0r = 0.0f, l1r = 0.0f;

    const int row0 = w * 16 + gid;
    const int row1 = row0 + 8;

    for (int it = 0; it < nkv; ++it) {
        const int p = it & 1;
        if (it < nkv - 1) { CP_WAIT(1); } else { CP_WAIT(0); }
        __syncthreads();

        if (it == 0) {
            #pragma unroll
            for (int ks = 0; ks < 4; ks++) {
                const uint32_t addr =
                    sb + OFF_Q + (uint32_t)(w * 16) * GROW + a_off + ks * 32;
                LDSM_X4(qh[ks], addr);
            }
        }

        const uint32_t kst = sb + p * KV_STG;

        // ---- S = Q @ K^T (fp16 1-term) ----
        float s[8][4];
        #pragma unroll
        for (int nt = 0; nt < 8; nt++)
            #pragma unroll
            for (int j = 0; j < 4; j++) s[nt][j] = 0.0f;

        #pragma unroll
        for (int ks = 0; ks < 4; ++ks) {
            uint32_t kb[4][4];
            #pragma unroll
            for (int p2 = 0; p2 < 4; p2++)
                LDSM_X4(kb[p2], kst + (uint32_t)(p2 * 16) * GROW + b_off + ks * 32);
            #pragma unroll
            for (int p2 = 0; p2 < 4; p2++) {
                MMA_FP16(s[2 * p2 + 0], qh[ks], &kb[p2][0]);
                MMA_FP16(s[2 * p2 + 1], qh[ks], &kb[p2][2]);
            }
        }

        // scale to natural scores: s = acc / 512
        #pragma unroll
        for (int nt = 0; nt < 8; nt++) {
            s[nt][0] *= 0.001953125f; s[nt][1] *= 0.001953125f;
            s[nt][2] *= 0.001953125f; s[nt][3] *= 0.001953125f;
        }

        if (it == qt) {
            #pragma unroll
            for (int nt = 0; nt < 8; nt++) {
                const int c0 = nt * 8 + tid4 * 2;
                if (c0     > row0) s[nt][0] = -INFINITY;
                if (c0 + 1 > row0) s[nt][1] = -INFINITY;
                if (c0     > row1) s[nt][2] = -INFINITY;
                if (c0 + 1 > row1) s[nt][3] = -INFINITY;
            }
        }

        float mt0 = -INFINITY, mt1 = -INFINITY;
        #pragma unroll
        for (int nt = 0; nt < 8; nt++) {
            mt0 = fmaxf(mt0, fmaxf(s[nt][0], s[nt][1]));
            mt1 = fmaxf(mt1, fmaxf(s[nt][2], s[nt][3]));
        }
        mt0 = fmaxf(mt0, __shfl_xor_sync(0xffffffffu, mt0, 1));
        mt0 = fmaxf(mt0, __shfl_xor_sync(0xffffffffu, mt0, 2));
        mt1 = fmaxf(mt1, __shfl_xor_sync(0xffffffffu, mt1, 1));
        mt1 = fmaxf(mt1, __shfl_xor_sync(0xffffffffu, mt1, 2));

        const float mn0 = fmaxf(m0r, mt0);
        const float mn1 = fmaxf(m1r, mt1);
        const float sc0 = __expf(m0r - mn0);
        const float sc1 = __expf(m1r - mn1);
        m0r = mn0; m1r = mn1;

        float ls0 = 0.0f, ls1 = 0.0f;
        #pragma unroll
        for (int nt = 0; nt < 8; nt++) {
            s[nt][0] = __expf(s[nt][0] - mn0);
            s[nt][1] = __expf(s[nt][1] - mn0);
            s[nt][2] = __expf(s[nt][2] - mn1);
            s[nt][3] = __expf(s[nt][3] - mn1);
            ls0 += s[nt][0] + s[nt][1];
            ls1 += s[nt][2] + s[nt][3];
        }
        ls0 += __shfl_xor_sync(0xffffffffu, ls0, 1);
        ls0 += __shfl_xor_sync(0xffffffffu, ls0, 2);
        ls1 += __shfl_xor_sync(0xffffffffu, ls1, 1);
        ls1 += __shfl_xor_sync(0xffffffffu, ls1, 2);
        l0r = l0r * sc0 + ls0;
        l1r = l1r * sc1 + ls1;

        #pragma unroll
        for (int nt = 0; nt < 8; nt++) {
            c_acc[nt][0] *= sc0; c_acc[nt][1] *= sc0;
            c_acc[nt][2] *= sc1; c_acc[nt][3] *= sc1;
        }

        // ---- write P*1024 (fp16 single plane) ----
        #pragma unroll
        for (int nt = 0; nt < 8; nt++) {
            __half2 h01 = __floats2half2_rn(s[nt][0] * 1024.0f,
                                            s[nt][1] * 1024.0f);
            __half2 h23 = __floats2half2_rn(s[nt][2] * 1024.0f,
                                            s[nt][3] * 1024.0f);
            const uint32_t c0 = (uint32_t)(nt * 16 + tid4 * 4);
            *reinterpret_cast<uint32_t*>(smem + OFF_P + (uint32_t)row0 * GROW + c0)
                = *reinterpret_cast<uint32_t*>(&h01);
            *reinterpret_cast<uint32_t*>(smem + OFF_P + (uint32_t)row1 * GROW + c0)
                = *reinterpret_cast<uint32_t*>(&h23);
        }
        __syncwarp();

        // ---- ctx += P' @ Vh (fp16 1-term) ----
        #pragma unroll
        for (int kk = 0; kk < 4; ++kk) {
            uint32_t ph[4];
            LDSM_X4(ph, sb + OFF_P + (uint32_t)(w * 16) * GROW + a_off + kk * 32);

            uint32_t vb[4][4];
            #pragma unroll
            for (int nt2 = 0; nt2 < 4; nt2++)
                LDSM_X4_T(vb[nt2], kst + KV_T
                          + (uint32_t)(kk * 16) * GROW + a_off + nt2 * 32);
            #pragma unroll
            for (int nt2 = 0; nt2 < 4; nt2++) {
                MMA_FP16(c_acc[2 * nt2 + 0], ph, &vb[nt2][0]);
                MMA_FP16(c_acc[2 * nt2 + 1], ph, &vb[nt2][2]);
            }
        }
        __syncthreads();
        if (it + 2 < nkv) ISSUE_KV(it + 2, p);
    }

    // ---- epilogue: ctx*16 -> fp16 hi/lo planes [B,T,DIM] ----
    const float inv0 = 0.015625f / l0r;   // 16/1024
    const float inv1 = 0.015625f / l1r;
    const int qr0 = q0 + row0;
    const int qr1 = q0 + row1;
    #pragma unroll
    for (int nt = 0; nt < 8; nt++) {
        const int hd = nt * 8 + tid4 * 2;
        const size_t o0 = ((size_t)b * T_ + qr0) * DIM + h * HD + hd;
        const size_t o1 = ((size_t)b * T_ + qr1) * DIM + h * HD + hd;
        store_pair_h(g_cfh, g_cfl, o0, c_acc[nt][0] * inv0, c_acc[nt][1] * inv0);
        store_pair_h(g_cfh, g_cfl, o1, c_acc[nt][2] * inv1, c_acc[nt][3] * inv1);
    }
    (void)dummy;
}

// ---------------------------------------------------------------------------
// kernel_launch
// ---------------------------------------------------------------------------
extern "C" void kernel_launch(void* const* d_in, const int* in_sizes, int n_in,
                              void* d_out, int out_size)
{
    const float* x  = (const float*)d_in[0];
    const float* Wq = (const float*)d_in[1];
    const float* bq = (const float*)d_in[2];
    const float* Wk = (const float*)d_in[3];
    const float* bk = (const float*)d_in[4];
    const float* Wv = (const float*)d_in[5];
    const float* bv = (const float*)d_in[6];
    const float* Wo = (const float*)d_in[7];
    const float* bo = (const float*)d_in[8];

    float* out   = (float*)d_out;
    float* k_out = out + (size_t)M_TOT * DIM;
    float* v_out = out + (size_t)2 * M_TOT * DIM;

    cudaFuncSetAttribute(qkv_gemm_kernel,
                         cudaFuncAttributeMaxDynamicSharedMemorySize, GEMM_SMEM);
    cudaFuncSetAttribute(oproj_gemm_kernel,
                         cudaFuncAttributeMaxDynamicSharedMemorySize, GEMM_SMEM);
    cudaFuncSetAttribute(attn_tc_kernel,
                         cudaFuncAttributeMaxDynamicSharedMemorySize, ATTN_SMEM);

    // Pre-split x, weights; gather biases
    split_x_kernel<<<M_TOT * DIM / 4 / 256, 256>>>(x);
    {
        dim3 wg(DD / 4 / 256, 4);
        split_w_kernel<<<wg, 256>>>(Wq, Wk, Wv, Wo);
    }
    copy_bias_kernel<<<3 * DIM / 256, 256>>>(bq, bk, bv);

    // Fused QKV projection
    dim3 qkvg(24, M_TOT / 128);           // (24, 32)
    qkv_gemm_kernel<<<qkvg, 256, GEMM_SMEM>>>(k_out, v_out);

    // Causal flash attention
    dim3 agrid(T_ / 64, NH, B_);          // (32, 16, 2)
    attn_tc_kernel<<<agrid, 128, ATTN_SMEM>>>(nullptr);

    // Output projection
    dim3 og(DIM / 128, M_TOT / 128);      // (8, 32)
    oproj_gemm_kernel<<<og, 256, GEMM_SMEM>>>(bo, out);
}

// round 11
// speedup vs baseline: 2.3073x; 1.3277x over previous
#include <cuda_runtime.h>
#include <cuda_bf16.h>
#include <cuda_fp16.h>
#include <cstdint>
#include <math.h>

// Problem constants
#define DIM 1024
#define NH  16
#define HD  64
#define B_  2
#define T_  2048
#define M_TOT (B_ * T_)          // 4096
#define DD   ((size_t)DIM * DIM)

// ---------------------------------------------------------------------------
// Device scratch (no allocation allowed).  All MMA operands: single fp16 plane.
// ---------------------------------------------------------------------------
__device__ __half g_xfh[M_TOT * DIM];   // (16*x) fp16
__device__ __half g_wfh[4 * DIM * DIM]; // Wq,Wk,Wv,Wo fp16
__device__ __half g_qh[M_TOT * DIM];    // (4*q)  [B,H,T,Hd]
__device__ __half g_kh[M_TOT * DIM];    // (16*k)
__device__ __half g_vh16[M_TOT * DIM];  // V fp16 natural scale
__device__ __half g_cfh[M_TOT * DIM];   // (16*ctx) [B,T,DIM]
__device__ float  g_bias[3 * DIM];      // bq|bk|bv

// ===========================================================================
// Helpers
// ===========================================================================
__device__ __forceinline__ uint32_t smem_to_u32(const void* p) {
    uint32_t a;
    asm("{ .reg .u64 t; cvta.to.shared.u64 t, %1; cvt.u32.u64 %0, t; }"
        : "=r"(a) : "l"(p));
    return a;
}

#define LDSM_X4(r, addr) \
    asm volatile("ldmatrix.sync.aligned.m8n8.x4.shared.b16 {%0,%1,%2,%3}, [%4];" \
        : "=r"((r)[0]), "=r"((r)[1]), "=r"((r)[2]), "=r"((r)[3]) : "r"(addr))

#define LDSM_X4_T(r, addr) \
    asm volatile("ldmatrix.sync.aligned.m8n8.x4.trans.shared.b16 {%0,%1,%2,%3}, [%4];" \
        : "=r"((r)[0]), "=r"((r)[1]), "=r"((r)[2]), "=r"((r)[3]) : "r"(addr))

#define MMA_FP16(d, a, b) \
    asm volatile("mma.sync.aligned.m16n8k16.row.col.f32.f16.f16.f32 " \
        "{%0,%1,%2,%3}, {%4,%5,%6,%7}, {%8,%9}, {%0,%1,%2,%3};" \
        : "+f"((d)[0]), "+f"((d)[1]), "+f"((d)[2]), "+f"((d)[3]) \
        : "r"((a)[0]), "r"((a)[1]), "r"((a)[2]), "r"((a)[3]), \
          "r"((b)[0]), "r"((b)[1]))

#define CP_A16(dst, src) \
    asm volatile("cp.async.cg.shared.global [%0], [%1], 16;" \
        :: "r"(dst), "l"(src) : "memory")
#define CP_COMMIT() asm volatile("cp.async.commit_group;" ::: "memory")
#define CP_WAIT(N)  asm volatile("cp.async.wait_group %0;" :: "n"(N) : "memory")

// ===========================================================================
// Pre-split kernels
// ===========================================================================
__global__ void __launch_bounds__(256) split_x_kernel(const float* __restrict__ x)
{
    const int i = blockIdx.x * 256 + threadIdx.x;
    float4 v = reinterpret_cast<const float4*>(x)[i];
    __half2 h01 = __floats2half2_rn(v.x * 16.0f, v.y * 16.0f);
    __half2 h23 = __floats2half2_rn(v.z * 16.0f, v.w * 16.0f);
    uint2 h = make_uint2(*reinterpret_cast<uint32_t*>(&h01),
                         *reinterpret_cast<uint32_t*>(&h23));
    reinterpret_cast<uint2*>(g_xfh)[i] = h;
}

__global__ void __launch_bounds__(256) split_w_kernel(
    const float* __restrict__ w0, const float* __restrict__ w1,
    const float* __restrict__ w2, const float* __restrict__ w3)
{
    const int y = blockIdx.y;
    const float* src = (y == 0) ? w0 : (y == 1) ? w1 : (y == 2) ? w2 : w3;
    const int i = blockIdx.x * 256 + threadIdx.x;
    float4 v = reinterpret_cast<const float4*>(src)[i];
    __half2 h01 = __floats2half2_rn(v.x, v.y);
    __half2 h23 = __floats2half2_rn(v.z, v.w);
    uint2 h = make_uint2(*reinterpret_cast<uint32_t*>(&h01),
                         *reinterpret_cast<uint32_t*>(&h23));
    reinterpret_cast<uint2*>(g_wfh + (size_t)y * DD)[i] = h;
}

__global__ void __launch_bounds__(256) copy_bias_kernel(
    const float* __restrict__ b0, const float* __restrict__ b1,
    const float* __restrict__ b2)
{
    const int i = blockIdx.x * 256 + threadIdx.x;
    float v;
    if (i < DIM)            v = b0[i];
    else if (i < 2 * DIM)   v = b1[i - DIM];
    else                    v = b2[i - 2 * DIM];
    g_bias[i] = v;
}

// ===========================================================================
// GEMM mainloop: block 128x128, BK=64, 3-stage cp.async, 256 thr / 8 warps,
// warp tile 64x32.  fp16 1-term: acc = Ah @ Wh^T.
// Stage = Ah | Wh  (2 x 18432 = 36864 B); 3 stages = 110592 B.
// ===========================================================================
#define GROW   144
#define G_T    18432
#define STAGE  (2 * G_T)             // 36864
#define GEMM_SMEM (3 * STAGE)        // 110592
#define NCH 16

__device__ __forceinline__ void gemm_mainloop_1t(
    const __half* __restrict__ Ah, const __half* __restrict__ Wh,
    int m0, int n0, uint32_t sb, float acc[4][4][4])
{
    const int tid  = threadIdx.x;
    const int lane = tid & 31;
    const int wid  = tid >> 5;
    const int warp_m = wid & 1;
    const int warp_n = wid >> 1;
    const int r    = lane & 7;
    const int quad = lane >> 3;
    const uint32_t a_off =
        (uint32_t)(warp_m * 64 + (quad & 1) * 8 + r) * GROW + (quad >> 1) * 16;
    const uint32_t b_off =
        (uint32_t)(warp_n * 32 + (quad >> 1) * 8 + r) * GROW + (quad & 1) * 16;

    auto ISSUE = [&](int c, int p) {
        const int k0 = c * 64;
        const uint32_t st = sb + p * STAGE;
        #pragma unroll
        for (int i = 0; i < 4; i++) {
            const int f   = i * 256 + tid;
            const int row = f >> 3, cc = f & 7;
            const size_t ga = (size_t)(m0 + row) * DIM + k0 + cc * 8;
            const size_t gw = (size_t)(n0 + row) * DIM + k0 + cc * 8;
            const uint32_t d = st + (uint32_t)row * GROW + cc * 16;
            CP_A16(d,       Ah + ga);
            CP_A16(d + G_T, Wh + gw);
        }
        CP_COMMIT();
    };

    ISSUE(0, 0);
    ISSUE(1, 1);

    for (int c = 0; c < NCH; ++c) {
        const int p = c - (c / 3) * 3;
        if (c < NCH - 1) { CP_WAIT(1); } else { CP_WAIT(0); }
        __syncthreads();

        const uint32_t st = sb + p * STAGE;
        #pragma unroll
        for (int ks = 0; ks < 4; ++ks) {
            uint32_t ah[4][4];
            #pragma unroll
            for (int mi = 0; mi < 4; mi++)
                LDSM_X4(ah[mi], st + a_off + mi * (16 * GROW) + ks * 32);
            uint32_t bh[4][2];
            #pragma unroll
            for (int pr = 0; pr < 2; pr++)
                LDSM_X4(&bh[2 * pr][0],
                        st + G_T + b_off + pr * (16 * GROW) + ks * 32);
            #pragma unroll
            for (int mi = 0; mi < 4; mi++)
                #pragma unroll
                for (int ni = 0; ni < 4; ni++)
                    MMA_FP16(acc[mi][ni], ah[mi], bh[ni]);
        }
        if (c + 2 < NCH) {
            const int p2 = (c + 2) - ((c + 2) / 3) * 3;
            ISSUE(c + 2, p2);
        }
    }
}

// Fused QKV projection: grid (24, 32). id = blockIdx.x>>3 selects Q/K/V.
// acc = (16*x) @ W^T  ->  val = acc/16 + bias.
__global__ void __launch_bounds__(256, 1) qkv_gemm_kernel(
    float* __restrict__ k_out, float* __restrict__ v_out)
{
    extern __shared__ char smem[];
    const uint32_t sb = smem_to_u32(smem);
    const int nb = blockIdx.x;
    const int id = nb >> 3;
    const int n0 = (nb & 7) * 128;
    const int m0 = blockIdx.y * 128;

    float acc[4][4][4];
    #pragma unroll
    for (int mi = 0; mi < 4; mi++)
        #pragma unroll
        for (int ni = 0; ni < 4; ni++)
            #pragma unroll
            for (int j = 0; j < 4; j++) acc[mi][ni][j] = 0.0f;

    gemm_mainloop_1t(g_xfh, g_wfh + (size_t)id * DD, m0, n0, sb, acc);

    const int lane = threadIdx.x & 31;
    const int wid  = threadIdx.x >> 5;
    const int warp_m = wid & 1;
    const int warp_n = wid >> 1;
    const int gid  = lane >> 2;
    const int tid4 = lane & 3;

    #pragma unroll
    for (int mi = 0; mi < 4; mi++) {
        #pragma unroll
        for (int ni = 0; ni < 4; ni++) {
            const int n = n0 + warp_n * 32 + ni * 8 + tid4 * 2;
            const float2 bb =
                *reinterpret_cast<const float2*>(&g_bias[id * DIM + n]);
            #pragma unroll
            for (int hrow = 0; hrow < 2; hrow++) {
                const int m = m0 + warp_m * 64 + mi * 16 + gid + hrow * 8;
                const float v0 = acc[mi][ni][hrow * 2 + 0] * 0.0625f + bb.x;
                const float v1 = acc[mi][ni][hrow * 2 + 1] * 0.0625f + bb.y;
                const int b  = m >> 11;
                const int t  = m & (T_ - 1);
                const int h  = n >> 6;
                const int hd = n & (HD - 1);
                const size_t o = ((((size_t)b * NH + h) * T_) + t) * HD + hd;
                if (id == 0) {                     // Q: 4*q plane
                    *reinterpret_cast<__half2*>(g_qh + o) =
                        __floats2half2_rn(v0 * 4.0f, v1 * 4.0f);
                } else if (id == 1) {              // K: fp32 out + 16*k plane
                    float2 of; of.x = v0; of.y = v1;
                    *reinterpret_cast<float2*>(&k_out[o]) = of;
                    *reinterpret_cast<__half2*>(g_kh + o) =
                        __floats2half2_rn(v0 * 16.0f, v1 * 16.0f);
                } else {                           // V: fp32 out + fp16 plane
                    float2 of; of.x = v0; of.y = v1;
                    *reinterpret_cast<float2*>(&v_out[o]) = of;
                    *reinterpret_cast<__half2*>(g_vh16 + o) =
                        __floats2half2_rn(v0, v1);
                }
            }
        }
    }
}

// Output projection: (16*ctx) @ Woh^T / 16 + bo -> fp32 out
__global__ void __launch_bounds__(256, 1) oproj_gemm_kernel(
    const float* __restrict__ bo, float* __restrict__ out)
{
    extern __shared__ char smem[];
    const uint32_t sb = smem_to_u32(smem);
    const int n0 = blockIdx.x * 128;
    const int m0 = blockIdx.y * 128;

    float acc[4][4][4];
    #pragma unroll
    for (int mi = 0; mi < 4; mi++)
        #pragma unroll
        for (int ni = 0; ni < 4; ni++)
            #pragma unroll
            for (int j = 0; j < 4; j++) acc[mi][ni][j] = 0.0f;

    gemm_mainloop_1t(g_cfh, g_wfh + 3 * DD, m0, n0, sb, acc);

    const int lane = threadIdx.x & 31;
    const int wid  = threadIdx.x >> 5;
    const int warp_m = wid & 1;
    const int warp_n = wid >> 1;
    const int gid  = lane >> 2;
    const int tid4 = lane & 3;

    #pragma unroll
    for (int mi = 0; mi < 4; mi++) {
        #pragma unroll
        for (int ni = 0; ni < 4; ni++) {
            const int n = n0 + warp_n * 32 + ni * 8 + tid4 * 2;
            const float2 bb = *reinterpret_cast<const float2*>(&bo[n]);
            #pragma unroll
            for (int hrow = 0; hrow < 2; hrow++) {
                const int m = m0 + warp_m * 64 + mi * 16 + gid + hrow * 8;
                float2 o;
                o.x = acc[mi][ni][hrow * 2 + 0] * 0.0625f + bb.x;
                o.y = acc[mi][ni][hrow * 2 + 1] * 0.0625f + bb.y;
                *reinterpret_cast<float2*>(&out[(size_t)m * DIM + n]) = o;
            }
        }
    }
}

// ===========================================================================
// Tensor-core causal flash attention, fp16 1-term S and PV (unchanged R10).
// S:  acc = (4q) @ (16k)^T ;  s = acc / 512.
// PV: acc = (1024p) @ v ;  ctx*16 = acc / 64.
// ===========================================================================
#define KV_T   9216
#define KV_STG (2 * KV_T)              // 18432
#define OFF_Q  (2 * KV_STG)            // 36864
#define OFF_P  (OFF_Q + KV_T)          // 46080
#define ATTN_SMEM (OFF_P + KV_T)       // 55296

__global__ void __launch_bounds__(128, 3) attn_tc_kernel(
    float* __restrict__ dummy)
{
    extern __shared__ char smem[];
    const uint32_t sb = smem_to_u32(smem);
    const int tid  = threadIdx.x;
    const int lane = tid & 31;
    const int w    = tid >> 5;
    const int qt = gridDim.x - 1 - blockIdx.x;
    const int h  = blockIdx.y;
    const int b  = blockIdx.z;
    const int q0 = qt * 64;
    const int nkv = qt + 1;

    const size_t head = ((size_t)b * NH + h) * T_ * HD;

    const int r    = lane & 7;
    const int quad = lane >> 3;
    const int gid  = lane >> 2;
    const int tid4 = lane & 3;
    const uint32_t a_off =
        (uint32_t)((quad & 1) * 8 + r) * GROW + (quad >> 1) * 16;
    const uint32_t b_off =
        (uint32_t)((quad >> 1) * 8 + r) * GROW + (quad & 1) * 16;

    {   // Q prologue
        #pragma unroll
        for (int i = 0; i < 4; i++) {
            const int f   = i * 128 + tid;
            const int row = f >> 3, cc = f & 7;
            const size_t g = head + (size_t)(q0 + row) * HD + cc * 8;
            const uint32_t d = sb + OFF_Q + (uint32_t)row * GROW + cc * 16;
            CP_A16(d, g_qh + g);
        }
        CP_COMMIT();
    }
    auto ISSUE_KV = [&](int it, int p) {
        const int j0 = it * 64;
        const uint32_t st = sb + p * KV_STG;
        #pragma unroll
        for (int i = 0; i < 4; i++) {
            const int f   = i * 128 + tid;
            const int row = f >> 3, cc = f & 7;
            const size_t g = head + (size_t)(j0 + row) * HD + cc * 8;
            const uint32_t d = st + (uint32_t)row * GROW + cc * 16;
            CP_A16(d,        g_kh + g);
            CP_A16(d + KV_T, g_vh16 + g);
        }
        CP_COMMIT();
    };
    ISSUE_KV(0, 0);
    if (nkv > 1) ISSUE_KV(1, 1);

    uint32_t qh[4][4];
    float c_acc[8][4];
    #pragma unroll
    for (int nt = 0; nt < 8; nt++)
        #pragma unroll
        for (int j = 0; j < 4; j++) c_acc[nt][j] = 0.0f;
    float m0r = -INFINITY, m1r = -INFINITY;
    float l0r = 0.0f, l1r = 0.0f;

    const int row0 = w * 16 + gid;
    const int row1 = row0 + 8;

    for (int it = 0; it < nkv; ++it) {
        const int p = it & 1;
        if (it < nkv - 1) { CP_WAIT(1); } else { CP_WAIT(0); }
        __syncthreads();

        if (it == 0) {
            #pragma unroll
            for (int ks = 0; ks < 4; ks++)
                LDSM_X4(qh[ks], sb + OFF_Q + (uint32_t)(w * 16) * GROW
                                + a_off + ks * 32);
        }

        const uint32_t kst = sb + p * KV_STG;

        // ---- S = Q @ K^T ----
        float s[8][4];
        #pragma unroll
        for (int nt = 0; nt < 8; nt++)
            #pragma unroll
            for (int j = 0; j < 4; j++) s[nt][j] = 0.0f;

        #pragma unroll
        for (int ks = 0; ks < 4; ++ks) {
            uint32_t kb[4][4];
            #pragma unroll
            for (int p2 = 0; p2 < 4; p2++)
                LDSM_X4(kb[p2], kst + (uint32_t)(p2 * 16) * GROW + b_off + ks * 32);
            #pragma unroll
            for (int p2 = 0; p2 < 4; p2++) {
                MMA_FP16(s[2 * p2 + 0], qh[ks], &kb[p2][0]);
                MMA_FP16(s[2 * p2 + 1], qh[ks], &kb[p2][2]);
            }
        }

        #pragma unroll
        for (int nt = 0; nt < 8; nt++) {
            s[nt][0] *= 0.001953125f; s[nt][1] *= 0.001953125f;
            s[nt][2] *= 0.001953125f; s[nt][3] *= 0.001953125f;
        }

        if (it == qt) {
            #pragma unroll
            for (int nt = 0; nt < 8; nt++) {
                const int c0 = nt * 8 + tid4 * 2;
                if (c0     > row0) s[nt][0] = -INFINITY;
                if (c0 + 1 > row0) s[nt][1] = -INFINITY;
                if (c0     > row1) s[nt][2] = -INFINITY;
                if (c0 + 1 > row1) s[nt][3] = -INFINITY;
            }
        }

        float mt0 = -INFINITY, mt1 = -INFINITY;
        #pragma unroll
        for (int nt = 0; nt < 8; nt++) {
            mt0 = fmaxf(mt0, fmaxf(s[nt][0], s[nt][1]));
            mt1 = fmaxf(mt1, fmaxf(s[nt][2], s[nt][3]));
        }
        mt0 = fmaxf(mt0, __shfl_xor_sync(0xffffffffu, mt0, 1));
        mt0 = fmaxf(mt0, __shfl_xor_sync(0xffffffffu, mt0, 2));
        mt1 = fmaxf(mt1, __shfl_xor_sync(0xffffffffu, mt1, 1));
        mt1 = fmaxf(mt1, __shfl_xor_sync(0xffffffffu, mt1, 2));

        const float mn0 = fmaxf(m0r, mt0);
        const float mn1 = fmaxf(m1r, mt1);
        const float sc0 = __expf(m0r - mn0);
        const float sc1 = __expf(m1r - mn1);
        m0r = mn0; m1r = mn1;

        float ls0 = 0.0f, ls1 = 0.0f;
        #pragma unroll
        for (int nt = 0; nt < 8; nt++) {
            s[nt][0] = __expf(s[nt][0] - mn0);
            s[nt][1] = __expf(s[nt][1] - mn0);
            s[nt][2] = __expf(s[nt][2] - mn1);
            s[nt][3] = __expf(s[nt][3] - mn1);
            ls0 += s[nt][0] + s[nt][1];
            ls1 += s[nt][2] + s[nt][3];
        }
        ls0 += __shfl_xor_sync(0xffffffffu, ls0, 1);
        ls0 += __shfl_xor_sync(0xffffffffu, ls0, 2);
        ls1 += __shfl_xor_sync(0xffffffffu, ls1, 1);
        ls1 += __shfl_xor_sync(0xffffffffu, ls1, 2);
        l0r = l0r * sc0 + ls0;
        l1r = l1r * sc1 + ls1;

        #pragma unroll
        for (int nt = 0; nt < 8; nt++) {
            c_acc[nt][0] *= sc0; c_acc[nt][1] *= sc0;
            c_acc[nt][2] *= sc1; c_acc[nt][3] *= sc1;
        }

        // ---- write P*1024 ----
        #pragma unroll
        for (int nt = 0; nt < 8; nt++) {
            __half2 h01 = __floats2half2_rn(s[nt][0] * 1024.0f,
                                            s[nt][1] * 1024.0f);
            __half2 h23 = __floats2half2_rn(s[nt][2] * 1024.0f,
                                            s[nt][3] * 1024.0f);
            const uint32_t c0 = (uint32_t)(nt * 16 + tid4 * 4);
            *reinterpret_cast<uint32_t*>(smem + OFF_P + (uint32_t)row0 * GROW + c0)
                = *reinterpret_cast<uint32_t*>(&h01);
            *reinterpret_cast<uint32_t*>(smem + OFF_P + (uint32_t)row1 * GROW + c0)
                = *reinterpret_cast<uint32_t*>(&h23);
        }
        __syncwarp();

        // ---- ctx += P' @ Vh ----
        #pragma unroll
        for (int kk = 0; kk < 4; ++kk) {
            uint32_t ph[4];
            LDSM_X4(ph, sb + OFF_P + (uint32_t)(w * 16) * GROW + a_off + kk * 32);

            uint32_t vb[4][4];
            #pragma unroll
            for (int nt2 = 0; nt2 < 4; nt2++)
                LDSM_X4_T(vb[nt2], kst + KV_T
                          + (uint32_t)(kk * 16) * GROW + a_off + nt2 * 32);
            #pragma unroll
            for (int nt2 = 0; nt2 < 4; nt2++) {
                MMA_FP16(c_acc[2 * nt2 + 0], ph, &vb[nt2][0]);
                MMA_FP16(c_acc[2 * nt2 + 1], ph, &vb[nt2][2]);
            }
        }
        __syncthreads();
        if (it + 2 < nkv) ISSUE_KV(it + 2, p);
    }

    // ---- epilogue: ctx*16 single fp16 plane [B,T,DIM] ----
    const float inv0 = 0.015625f / l0r;   // 16/1024
    const float inv1 = 0.015625f / l1r;
    const int qr0 = q0 + row0;
    const int qr1 = q0 + row1;
    #pragma unroll
    for (int nt = 0; nt < 8; nt++) {
        const int hd = nt * 8 + tid4 * 2;
        const size_t o0 = ((size_t)b * T_ + qr0) * DIM + h * HD + hd;
        const size_t o1 = ((size_t)b * T_ + qr1) * DIM + h * HD + hd;
        *reinterpret_cast<__half2*>(g_cfh + o0) =
            __floats2half2_rn(c_acc[nt][0] * inv0, c_acc[nt][1] * inv0);
        *reinterpret_cast<__half2*>(g_cfh + o1) =
            __floats2half2_rn(c_acc[nt][2] * inv1, c_acc[nt][3] * inv1);
    }
    (void)dummy;
}

// ---------------------------------------------------------------------------
// kernel_launch
// ---------------------------------------------------------------------------
extern "C" void kernel_launch(void* const* d_in, const int* in_sizes, int n_in,
                              void* d_out, int out_size)
{
    const float* x  = (const float*)d_in[0];
    const float* Wq = (const float*)d_in[1];
    const float* bq = (const float*)d_in[2];
    const float* Wk = (const float*)d_in[3];
    const float* bk = (const float*)d_in[4];
    const float* Wv = (const float*)d_in[5];
    const float* bv = (const float*)d_in[6];
    const float* Wo = (const float*)d_in[7];
    const float* bo = (const float*)d_in[8];

    float* out   = (float*)d_out;
    float* k_out = out + (size_t)M_TOT * DIM;
    float* v_out = out + (size_t)2 * M_TOT * DIM;

    cudaFuncSetAttribute(qkv_gemm_kernel,
                         cudaFuncAttributeMaxDynamicSharedMemorySize, GEMM_SMEM);
    cudaFuncSetAttribute(oproj_gemm_kernel,
                         cudaFuncAttributeMaxDynamicSharedMemorySize, GEMM_SMEM);
    cudaFuncSetAttribute(attn_tc_kernel,
                         cudaFuncAttributeMaxDynamicSharedMemorySize, ATTN_SMEM);

    // Pre-split x, weights; gather biases
    split_x_kernel<<<M_TOT * DIM / 4 / 256, 256>>>(x);
    {
        dim3 wg(DD / 4 / 256, 4);
        split_w_kernel<<<wg, 256>>>(Wq, Wk, Wv, Wo);
    }
    copy_bias_kernel<<<3 * DIM / 256, 256>>>(bq, bk, bv);

    // Fused QKV projection
    dim3 qkvg(24, M_TOT / 128);           // (24, 32)
    qkv_gemm_kernel<<<qkvg, 256, GEMM_SMEM>>>(k_out, v_out);

    // Causal flash attention
    dim3 agrid(T_ / 64, NH, B_);          // (32, 16, 2)
    attn_tc_kernel<<<agrid, 128, ATTN_SMEM>>>(nullptr);

    // Output projection
    dim3 og(DIM / 128, M_TOT / 128);      // (8, 32)
    oproj_gemm_kernel<<<og, 256, GEMM_SMEM>>>(bo, out);
}

// round 12
// speedup vs baseline: 2.5114x; 1.0884x over previous
#include <cuda_runtime.h>
#include <cuda_bf16.h>
#include <cuda_fp16.h>
#include <cstdint>
#include <math.h>

// Problem constants
#define DIM 1024
#define NH  16
#define HD  64
#define B_  2
#define T_  2048
#define M_TOT (B_ * T_)          // 4096
#define DD   ((size_t)DIM * DIM)

// ---------------------------------------------------------------------------
// Device scratch (no allocation allowed).  All MMA operands: single fp16 plane.
// ---------------------------------------------------------------------------
__device__ __half g_xfh[M_TOT * DIM];   // (16*x) fp16
__device__ __half g_wfh[4 * DIM * DIM]; // Wq,Wk,Wv,Wo fp16
__device__ __half g_qh[M_TOT * DIM];    // (4*q)  [B,H,T,Hd]
__device__ __half g_kh[M_TOT * DIM];    // (16*k)
__device__ __half g_vh16[M_TOT * DIM];  // V fp16 natural scale
__device__ __half g_cfh[M_TOT * DIM];   // (16*ctx) [B,T,DIM]
__device__ float  g_bias[3 * DIM];      // bq|bk|bv

// ===========================================================================
// Helpers
// ===========================================================================
__device__ __forceinline__ uint32_t smem_to_u32(const void* p) {
    uint32_t a;
    asm("{ .reg .u64 t; cvta.to.shared.u64 t, %1; cvt.u32.u64 %0, t; }"
        : "=r"(a) : "l"(p));
    return a;
}

#define LDSM_X4(r, addr) \
    asm volatile("ldmatrix.sync.aligned.m8n8.x4.shared.b16 {%0,%1,%2,%3}, [%4];" \
        : "=r"((r)[0]), "=r"((r)[1]), "=r"((r)[2]), "=r"((r)[3]) : "r"(addr))

#define LDSM_X4_T(r, addr) \
    asm volatile("ldmatrix.sync.aligned.m8n8.x4.trans.shared.b16 {%0,%1,%2,%3}, [%4];" \
        : "=r"((r)[0]), "=r"((r)[1]), "=r"((r)[2]), "=r"((r)[3]) : "r"(addr))

#define MMA_FP16(d, a, b) \
    asm volatile("mma.sync.aligned.m16n8k16.row.col.f32.f16.f16.f32 " \
        "{%0,%1,%2,%3}, {%4,%5,%6,%7}, {%8,%9}, {%0,%1,%2,%3};" \
        : "+f"((d)[0]), "+f"((d)[1]), "+f"((d)[2]), "+f"((d)[3]) \
        : "r"((a)[0]), "r"((a)[1]), "r"((a)[2]), "r"((a)[3]), \
          "r"((b)[0]), "r"((b)[1]))

#define CP_A16(dst, src) \
    asm volatile("cp.async.cg.shared.global [%0], [%1], 16;" \
        :: "r"(dst), "l"(src) : "memory")
#define CP_COMMIT() asm volatile("cp.async.commit_group;" ::: "memory")
#define CP_WAIT(N)  asm volatile("cp.async.wait_group %0;" :: "n"(N) : "memory")

// ===========================================================================
// Prep kernels
// ===========================================================================
// x -> (16*x) fp16 plane; last 3 blocks also copy biases.
__global__ void __launch_bounds__(256) prep_x_bias_kernel(
    const float* __restrict__ x,
    const float* __restrict__ b0, const float* __restrict__ b1,
    const float* __restrict__ b2)
{
    const int i = blockIdx.x * 256 + threadIdx.x;
    if (i < M_TOT * DIM / 4) {
        float4 v = reinterpret_cast<const float4*>(x)[i];
        __half2 h01 = __floats2half2_rn(v.x * 16.0f, v.y * 16.0f);
        __half2 h23 = __floats2half2_rn(v.z * 16.0f, v.w * 16.0f);
        uint2 h = make_uint2(*reinterpret_cast<uint32_t*>(&h01),
                             *reinterpret_cast<uint32_t*>(&h23));
        reinterpret_cast<uint2*>(g_xfh)[i] = h;
    }
    const int j = i - M_TOT * DIM / 4;
    if (j >= 0 && j < 3 * DIM) {
        float v;
        if (j < DIM)            v = b0[j];
        else if (j < 2 * DIM)   v = b1[j - DIM];
        else                    v = b2[j - 2 * DIM];
        g_bias[j] = v;
    }
}

__global__ void __launch_bounds__(256) split_w_kernel(
    const float* __restrict__ w0, const float* __restrict__ w1,
    const float* __restrict__ w2, const float* __restrict__ w3)
{
    const int y = blockIdx.y;
    const float* src = (y == 0) ? w0 : (y == 1) ? w1 : (y == 2) ? w2 : w3;
    const int i = blockIdx.x * 256 + threadIdx.x;
    float4 v = reinterpret_cast<const float4*>(src)[i];
    __half2 h01 = __floats2half2_rn(v.x, v.y);
    __half2 h23 = __floats2half2_rn(v.z, v.w);
    uint2 h = make_uint2(*reinterpret_cast<uint32_t*>(&h01),
                         *reinterpret_cast<uint32_t*>(&h23));
    reinterpret_cast<uint2*>(g_wfh + (size_t)y * DD)[i] = h;
}

// ===========================================================================
// GEMM mainloop: block 128x128, BK=64, 3-stage cp.async, 256 thr / 8 warps,
// warp tile 64x32.  fp16 1-term: acc = Ah @ Wh^T.
// Stage = Ah | Wh  (2 x 18432 = 36864 B); 3 stages = 110592 B -> 2 CTAs/SM.
// ===========================================================================
#define GROW   144
#define G_T    18432
#define STAGE  (2 * G_T)             // 36864
#define GEMM_SMEM (3 * STAGE)        // 110592
#define NCH 16

__device__ __forceinline__ void gemm_mainloop_1t(
    const __half* __restrict__ Ah, const __half* __restrict__ Wh,
    int m0, int n0, uint32_t sb, float acc[4][4][4])
{
    const int tid  = threadIdx.x;
    const int lane = tid & 31;
    const int wid  = tid >> 5;
    const int warp_m = wid & 1;
    const int warp_n = wid >> 1;
    const int r    = lane & 7;
    const int quad = lane >> 3;
    const uint32_t a_off =
        (uint32_t)(warp_m * 64 + (quad & 1) * 8 + r) * GROW + (quad >> 1) * 16;
    const uint32_t b_off =
        (uint32_t)(warp_n * 32 + (quad >> 1) * 8 + r) * GROW + (quad & 1) * 16;

    auto ISSUE = [&](int c, int p) {
        const int k0 = c * 64;
        const uint32_t st = sb + p * STAGE;
        #pragma unroll
        for (int i = 0; i < 4; i++) {
            const int f   = i * 256 + tid;
            const int row = f >> 3, cc = f & 7;
            const size_t ga = (size_t)(m0 + row) * DIM + k0 + cc * 8;
            const size_t gw = (size_t)(n0 + row) * DIM + k0 + cc * 8;
            const uint32_t d = st + (uint32_t)row * GROW + cc * 16;
            CP_A16(d,       Ah + ga);
            CP_A16(d + G_T, Wh + gw);
        }
        CP_COMMIT();
    };

    ISSUE(0, 0);
    ISSUE(1, 1);

    for (int c = 0; c < NCH; ++c) {
        const int p = c - (c / 3) * 3;
        if (c < NCH - 1) { CP_WAIT(1); } else { CP_WAIT(0); }
        __syncthreads();

        const uint32_t st = sb + p * STAGE;
        #pragma unroll
        for (int ks = 0; ks < 4; ++ks) {
            uint32_t ah[4][4];
            #pragma unroll
            for (int mi = 0; mi < 4; mi++)
                LDSM_X4(ah[mi], st + a_off + mi * (16 * GROW) + ks * 32);
            uint32_t bh[4][2];
            #pragma unroll
            for (int pr = 0; pr < 2; pr++)
                LDSM_X4(&bh[2 * pr][0],
                        st + G_T + b_off + pr * (16 * GROW) + ks * 32);
            #pragma unroll
            for (int mi = 0; mi < 4; mi++)
                #pragma unroll
                for (int ni = 0; ni < 4; ni++)
                    MMA_FP16(acc[mi][ni], ah[mi], bh[ni]);
        }
        if (c + 2 < NCH) {
            const int p2 = (c + 2) - ((c + 2) / 3) * 3;
            ISSUE(c + 2, p2);
        }
    }
}

// Fused QKV projection: grid (24, 32). id = blockIdx.x>>3 selects Q/K/V.
__global__ void __launch_bounds__(256, 2) qkv_gemm_kernel(
    float* __restrict__ k_out, float* __restrict__ v_out)
{
    extern __shared__ char smem[];
    const uint32_t sb = smem_to_u32(smem);
    const int nb = blockIdx.x;
    const int id = nb >> 3;
    const int n0 = (nb & 7) * 128;
    const int m0 = blockIdx.y * 128;

    float acc[4][4][4];
    #pragma unroll
    for (int mi = 0; mi < 4; mi++)
        #pragma unroll
        for (int ni = 0; ni < 4; ni++)
            #pragma unroll
            for (int j = 0; j < 4; j++) acc[mi][ni][j] = 0.0f;

    gemm_mainloop_1t(g_xfh, g_wfh + (size_t)id * DD, m0, n0, sb, acc);

    const int lane = threadIdx.x & 31;
    const int wid  = threadIdx.x >> 5;
    const int warp_m = wid & 1;
    const int warp_n = wid >> 1;
    const int gid  = lane >> 2;
    const int tid4 = lane & 3;

    #pragma unroll
    for (int mi = 0; mi < 4; mi++) {
        #pragma unroll
        for (int ni = 0; ni < 4; ni++) {
            const int n = n0 + warp_n * 32 + ni * 8 + tid4 * 2;
            const float2 bb =
                *reinterpret_cast<const float2*>(&g_bias[id * DIM + n]);
            #pragma unroll
            for (int hrow = 0; hrow < 2; hrow++) {
                const int m = m0 + warp_m * 64 + mi * 16 + gid + hrow * 8;
                const float v0 = acc[mi][ni][hrow * 2 + 0] * 0.0625f + bb.x;
                const float v1 = acc[mi][ni][hrow * 2 + 1] * 0.0625f + bb.y;
                const int b  = m >> 11;
                const int t  = m & (T_ - 1);
                const int h  = n >> 6;
                const int hd = n & (HD - 1);
                const size_t o = ((((size_t)b * NH + h) * T_) + t) * HD + hd;
                if (id == 0) {                     // Q: 4*q plane
                    *reinterpret_cast<__half2*>(g_qh + o) =
                        __floats2half2_rn(v0 * 4.0f, v1 * 4.0f);
                } else if (id == 1) {              // K: fp32 out + 16*k plane
                    float2 of; of.x = v0; of.y = v1;
                    *reinterpret_cast<float2*>(&k_out[o]) = of;
                    *reinterpret_cast<__half2*>(g_kh + o) =
                        __floats2half2_rn(v0 * 16.0f, v1 * 16.0f);
                } else {                           // V: fp32 out + fp16 plane
                    float2 of; of.x = v0; of.y = v1;
                    *reinterpret_cast<float2*>(&v_out[o]) = of;
                    *reinterpret_cast<__half2*>(g_vh16 + o) =
                        __floats2half2_rn(v0, v1);
                }
            }
        }
    }
}

// Output projection: (16*ctx) @ Woh^T / 16 + bo -> fp32 out
__global__ void __launch_bounds__(256, 2) oproj_gemm_kernel(
    const float* __restrict__ bo, float* __restrict__ out)
{
    extern __shared__ char smem[];
    const uint32_t sb = smem_to_u32(smem);
    const int n0 = blockIdx.x * 128;
    const int m0 = blockIdx.y * 128;

    float acc[4][4][4];
    #pragma unroll
    for (int mi = 0; mi < 4; mi++)
        #pragma unroll
        for (int ni = 0; ni < 4; ni++)
            #pragma unroll
            for (int j = 0; j < 4; j++) acc[mi][ni][j] = 0.0f;

    gemm_mainloop_1t(g_cfh, g_wfh + 3 * DD, m0, n0, sb, acc);

    const int lane = threadIdx.x & 31;
    const int wid  = threadIdx.x >> 5;
    const int warp_m = wid & 1;
    const int warp_n = wid >> 1;
    const int gid  = lane >> 2;
    const int tid4 = lane & 3;

    #pragma unroll
    for (int mi = 0; mi < 4; mi++) {
        #pragma unroll
        for (int ni = 0; ni < 4; ni++) {
            const int n = n0 + warp_n * 32 + ni * 8 + tid4 * 2;
            const float2 bb = *reinterpret_cast<const float2*>(&bo[n]);
            #pragma unroll
            for (int hrow = 0; hrow < 2; hrow++) {
                const int m = m0 + warp_m * 64 + mi * 16 + gid + hrow * 8;
                float2 o;
                o.x = acc[mi][ni][hrow * 2 + 0] * 0.0625f + bb.x;
                o.y = acc[mi][ni][hrow * 2 + 1] * 0.0625f + bb.y;
                *reinterpret_cast<float2*>(&out[(size_t)m * DIM + n]) = o;
            }
        }
    }
}

// ===========================================================================
// Tensor-core causal flash attention, fp16 1-term S and PV (unchanged).
// S:  acc = (4q) @ (16k)^T ;  s = acc / 512.
// PV: acc = (1024p) @ v ;  ctx*16 = acc / 64.
// ===========================================================================
#define KV_T   9216
#define KV_STG (2 * KV_T)              // 18432
#define OFF_Q  (2 * KV_STG)            // 36864
#define OFF_P  (OFF_Q + KV_T)          // 46080
#define ATTN_SMEM (OFF_P + KV_T)       // 55296

__global__ void __launch_bounds__(128, 3) attn_tc_kernel(
    float* __restrict__ dummy)
{
    extern __shared__ char smem[];
    const uint32_t sb = smem_to_u32(smem);
    const int tid  = threadIdx.x;
    const int lane = tid & 31;
    const int w    = tid >> 5;
    const int qt = gridDim.x - 1 - blockIdx.x;
    const int h  = blockIdx.y;
    const int b  = blockIdx.z;
    const int q0 = qt * 64;
    const int nkv = qt + 1;

    const size_t head = ((size_t)b * NH + h) * T_ * HD;

    const int r    = lane & 7;
    const int quad = lane >> 3;
    const int gid  = lane >> 2;
    const int tid4 = lane & 3;
    const uint32_t a_off =
        (uint32_t)((quad & 1) * 8 + r) * GROW + (quad >> 1) * 16;
    const uint32_t b_off =
        (uint32_t)((quad >> 1) * 8 + r) * GROW + (quad & 1) * 16;

    {   // Q prologue
        #pragma unroll
        for (int i = 0; i < 4; i++) {
            const int f   = i * 128 + tid;
            const int row = f >> 3, cc = f & 7;
            const size_t g = head + (size_t)(q0 + row) * HD + cc * 8;
            const uint32_t d = sb + OFF_Q + (uint32_t)row * GROW + cc * 16;
            CP_A16(d, g_qh + g);
        }
        CP_COMMIT();
    }
    auto ISSUE_KV = [&](int it, int p) {
        const int j0 = it * 64;
        const uint32_t st = sb + p * KV_STG;
        #pragma unroll
        for (int i = 0; i < 4; i++) {
            const int f   = i * 128 + tid;
            const int row = f >> 3, cc = f & 7;
            const size_t g = head + (size_t)(j0 + row) * HD + cc * 8;
            const uint32_t d = st + (uint32_t)row * GROW + cc * 16;
            CP_A16(d,        g_kh + g);
            CP_A16(d + KV_T, g_vh16 + g);
        }
        CP_COMMIT();
    };
    ISSUE_KV(0, 0);
    if (nkv > 1) ISSUE_KV(1, 1);

    uint32_t qh[4][4];
    float c_acc[8][4];
    #pragma unroll
    for (int nt = 0; nt < 8; nt++)
        #pragma unroll
        for (int j = 0; j < 4; j++) c_acc[nt][j] = 0.0f;
    float m0r = -INFINITY, m1r = -INFINITY;
    float l0r = 0.0f, l1r = 0.0f;

    const int row0 = w * 16 + gid;
    const int row1 = row0 + 8;

    for (int it = 0; it < nkv; ++it) {
        const int p = it & 1;
        if (it < nkv - 1) { CP_WAIT(1); } else { CP_WAIT(0); }
        __syncthreads();

        if (it == 0) {
            #pragma unroll
            for (int ks = 0; ks < 4; ks++)
                LDSM_X4(qh[ks], sb + OFF_Q + (uint32_t)(w * 16) * GROW
                                + a_off + ks * 32);
        }

        const uint32_t kst = sb + p * KV_STG;

        // ---- S = Q @ K^T ----
        float s[8][4];
        #pragma unroll
        for (int nt = 0; nt < 8; nt++)
            #pragma unroll
            for (int j = 0; j < 4; j++) s[nt][j] = 0.0f;

        #pragma unroll
        for (int ks = 0; ks < 4; ++ks) {
            uint32_t kb[4][4];
            #pragma unroll
            for (int p2 = 0; p2 < 4; p2++)
                LDSM_X4(kb[p2], kst + (uint32_t)(p2 * 16) * GROW + b_off + ks * 32);
            #pragma unroll
            for (int p2 = 0; p2 < 4; p2++) {
                MMA_FP16(s[2 * p2 + 0], qh[ks], &kb[p2][0]);
                MMA_FP16(s[2 * p2 + 1], qh[ks], &kb[p2][2]);
            }
        }

        #pragma unroll
        for (int nt = 0; nt < 8; nt++) {
            s[nt][0] *= 0.001953125f; s[nt][1] *= 0.001953125f;
            s[nt][2] *= 0.001953125f; s[nt][3] *= 0.001953125f;
        }

        if (it == qt) {
            #pragma unroll
            for (int nt = 0; nt < 8; nt++) {
                const int c0 = nt * 8 + tid4 * 2;
                if (c0     > row0) s[nt][0] = -INFINITY;
                if (c0 + 1 > row0) s[nt][1] = -INFINITY;
                if (c0     > row1) s[nt][2] = -INFINITY;
                if (c0 + 1 > row1) s[nt][3] = -INFINITY;
            }
        }

        float mt0 = -INFINITY, mt1 = -INFINITY;
        #pragma unroll
        for (int nt = 0; nt < 8; nt++) {
            mt0 = fmaxf(mt0, fmaxf(s[nt][0], s[nt][1]));
            mt1 = fmaxf(mt1, fmaxf(s[nt][2], s[nt][3]));
        }
        mt0 = fmaxf(mt0, __shfl_xor_sync(0xffffffffu, mt0, 1));
        mt0 = fmaxf(mt0, __shfl_xor_sync(0xffffffffu, mt0, 2));
        mt1 = fmaxf(mt1, __shfl_xor_sync(0xffffffffu, mt1, 1));
        mt1 = fmaxf(mt1, __shfl_xor_sync(0xffffffffu, mt1, 2));

        const float mn0 = fmaxf(m0r, mt0);
        const float mn1 = fmaxf(m1r, mt1);
        const float sc0 = __expf(m0r - mn0);
        const float sc1 = __expf(m1r - mn1);
        m0r = mn0; m1r = mn1;

        float ls0 = 0.0f, ls1 = 0.0f;
        #pragma unroll
        for (int nt = 0; nt < 8; nt++) {
            s[nt][0] = __expf(s[nt][0] - mn0);
            s[nt][1] = __expf(s[nt][1] - mn0);
            s[nt][2] = __expf(s[nt][2] - mn1);
            s[nt][3] = __expf(s[nt][3] - mn1);
            ls0 += s[nt][0] + s[nt][1];
            ls1 += s[nt][2] + s[nt][3];
        }
        ls0 += __shfl_xor_sync(0xffffffffu, ls0, 1);
        ls0 += __shfl_xor_sync(0xffffffffu, ls0, 2);
        ls1 += __shfl_xor_sync(0xffffffffu, ls1, 1);
        ls1 += __shfl_xor_sync(0xffffffffu, ls1, 2);
        l0r = l0r * sc0 + ls0;
        l1r = l1r * sc1 + ls1;

        #pragma unroll
        for (int nt = 0; nt < 8; nt++) {
            c_acc[nt][0] *= sc0; c_acc[nt][1] *= sc0;
            c_acc[nt][2] *= sc1; c_acc[nt][3] *= sc1;
        }

        // ---- write P*1024 ----
        #pragma unroll
        for (int nt = 0; nt < 8; nt++) {
            __half2 h01 = __floats2half2_rn(s[nt][0] * 1024.0f,
                                            s[nt][1] * 1024.0f);
            __half2 h23 = __floats2half2_rn(s[nt][2] * 1024.0f,
                                            s[nt][3] * 1024.0f);
            const uint32_t c0 = (uint32_t)(nt * 16 + tid4 * 4);
            *reinterpret_cast<uint32_t*>(smem + OFF_P + (uint32_t)row0 * GROW + c0)
                = *reinterpret_cast<uint32_t*>(&h01);
            *reinterpret_cast<uint32_t*>(smem + OFF_P + (uint32_t)row1 * GROW + c0)
                = *reinterpret_cast<uint32_t*>(&h23);
        }
        __syncwarp();

        // ---- ctx += P' @ Vh ----
        #pragma unroll
        for (int kk = 0; kk < 4; ++kk) {
            uint32_t ph[4];
            LDSM_X4(ph, sb + OFF_P + (uint32_t)(w * 16) * GROW + a_off + kk * 32);

            uint32_t vb[4][4];
            #pragma unroll
            for (int nt2 = 0; nt2 < 4; nt2++)
                LDSM_X4_T(vb[nt2], kst + KV_T
                          + (uint32_t)(kk * 16) * GROW + a_off + nt2 * 32);
            #pragma unroll
            for (int nt2 = 0; nt2 < 4; nt2++) {
                MMA_FP16(c_acc[2 * nt2 + 0], ph, &vb[nt2][0]);
                MMA_FP16(c_acc[2 * nt2 + 1], ph, &vb[nt2][2]);
            }
        }
        __syncthreads();
        if (it + 2 < nkv) ISSUE_KV(it + 2, p);
    }

    // ---- epilogue: ctx*16 single fp16 plane [B,T,DIM] ----
    const float inv0 = 0.015625f / l0r;   // 16/1024
    const float inv1 = 0.015625f / l1r;
    const int qr0 = q0 + row0;
    const int qr1 = q0 + row1;
    #pragma unroll
    for (int nt = 0; nt < 8; nt++) {
        const int hd = nt * 8 + tid4 * 2;
        const size_t o0 = ((size_t)b * T_ + qr0) * DIM + h * HD + hd;
        const size_t o1 = ((size_t)b * T_ + qr1) * DIM + h * HD + hd;
        *reinterpret_cast<__half2*>(g_cfh + o0) =
            __floats2half2_rn(c_acc[nt][0] * inv0, c_acc[nt][1] * inv0);
        *reinterpret_cast<__half2*>(g_cfh + o1) =
            __floats2half2_rn(c_acc[nt][2] * inv1, c_acc[nt][3] * inv1);
    }
    (void)dummy;
}

// ---------------------------------------------------------------------------
// kernel_launch
// ---------------------------------------------------------------------------
extern "C" void kernel_launch(void* const* d_in, const int* in_sizes, int n_in,
                              void* d_out, int out_size)
{
    const float* x  = (const float*)d_in[0];
    const float* Wq = (const float*)d_in[1];
    const float* bq = (const float*)d_in[2];
    const float* Wk = (const float*)d_in[3];
    const float* bk = (const float*)d_in[4];
    const float* Wv = (const float*)d_in[5];
    const float* bv = (const float*)d_in[6];
    const float* Wo = (const float*)d_in[7];
    const float* bo = (const float*)d_in[8];

    float* out   = (float*)d_out;
    float* k_out = out + (size_t)M_TOT * DIM;
    float* v_out = out + (size_t)2 * M_TOT * DIM;

    cudaFuncSetAttribute(qkv_gemm_kernel,
                         cudaFuncAttributeMaxDynamicSharedMemorySize, GEMM_SMEM);
    cudaFuncSetAttribute(oproj_gemm_kernel,
                         cudaFuncAttributeMaxDynamicSharedMemorySize, GEMM_SMEM);
    cudaFuncSetAttribute(attn_tc_kernel,
                         cudaFuncAttributeMaxDynamicSharedMemorySize, ATTN_SMEM);

    // Prep: x-plane + biases in one launch, weights in one launch
    {
        const int nx = M_TOT * DIM / 4;
        prep_x_bias_kernel<<<(nx + 3 * DIM + 255) / 256, 256>>>(x, bq, bk, bv);
        dim3 wg(DD / 4 / 256, 4);
        split_w_kernel<<<wg, 256>>>(Wq, Wk, Wv, Wo);
    }

    // Fused QKV projection
    dim3 qkvg(24, M_TOT / 128);           // (24, 32)
    qkv_gemm_kernel<<<qkvg, 256, GEMM_SMEM>>>(k_out, v_out);

    // Causal flash attention
    dim3 agrid(T_ / 64, NH, B_);          // (32, 16, 2)
    attn_tc_kernel<<<agrid, 128, ATTN_SMEM>>>(nullptr);

    // Output projection
    dim3 og(DIM / 128, M_TOT / 128);      // (8, 32)
    oproj_gemm_kernel<<<og, 256, GEMM_SMEM>>>(bo, out);
}